// round 4
// baseline (speedup 1.0000x reference)
#include <cuda_runtime.h>
#include <math.h>
#include <stdint.h>

#define BB 16
#define CC 32
#define NN 512
#define T1 192
#define T2 96
#define L1 97
#define L2 49
#define EE 64

typedef unsigned long long ull;

static constexpr size_t SZ1 = (size_t)BB*CC*NN*T1;
static constexpr size_t SZ2 = (size_t)BB*CC*NN*T2;

// ---------------- scratch ----------------
__device__ float g_bufA[SZ1];
__device__ float g_bufB[SZ1];
__device__ float g_bufC[SZ1];
__device__ float g_bufD[SZ2];
__device__ float g_bufE[SZ2];
__device__ float g_bufF[SZ2];
__device__ float g_Mc[CC*T1*T1];
__device__ float g_Mt[CC*T1*T1];
__device__ float g_D1[CC*T1*T2];
__device__ float g_C2[CC*T2*T2];
__device__ float g_cos1[L1*T1];
__device__ float g_sin1[L1*T1];
__device__ float g_cos2[L2*T2];
__device__ float g_sin2[L2*T2];
__device__ float g_K1[CC*T1];
__device__ float g_K2[CC*T2];
__device__ float g_featP[BB*CC*8*T1];
__device__ float g_gate[BB*T1];

// ---------------- f32x2 helpers ----------------
__device__ __forceinline__ ull pk2(float lo, float hi) {
    ull r; asm("mov.b64 %0, {%1,%2};" : "=l"(r) : "f"(lo), "f"(hi)); return r;
}
__device__ __forceinline__ void fma2(ull& d, ull a, ull b) {
    asm("fma.rn.f32x2 %0, %1, %2, %0;" : "+l"(d) : "l"(a), "l"(b));
}
__device__ __forceinline__ float2 upk2(ull v) {
    float2 f; asm("mov.b64 {%0,%1}, %2;" : "=f"(f.x), "=f"(f.y) : "l"(v)); return f;
}

__device__ __forceinline__ float gelu_t(float x) {
    float x3 = x*x*x;
    return 0.5f*x*(1.0f + tanhf(0.7978845608028654f*(x + 0.044715f*x3)));
}

// ---------------- precompute ----------------
__global__ void k_tables() {
    int i = blockIdx.x*blockDim.x + threadIdx.x;
    if (i < L1*T1) {
        int h = i / T1, t = i % T1;
        int m = (h*t) % T1;
        float a = (float)m * (1.0f/96.0f);
        g_cos1[i] = cospif(a);
        g_sin1[i] = sinpif(a);
    }
    int j = i - L1*T1;
    if (j >= 0 && j < L2*T2) {
        int h = j / T2, t = j % T2;
        int m = (h*t) % T2;
        float a = (float)m * (1.0f/48.0f);
        g_cos2[j] = cospif(a);
        g_sin2[j] = sinpif(a);
    }
}

__global__ void k_buildM(const float* __restrict__ Lc, const float* __restrict__ Lt) {
    int t = blockIdx.x, l = blockIdx.y, tp = threadIdx.x;
    float ac = 0.f, as = 0.f;
    for (int h = 0; h < L1; h++) {
        float w = (h == 0 || h == L1-1) ? (1.0f/T1) : (2.0f/T1);
        float lc = Lc[l*L1+h]*w, lt = Lt[l*L1+h]*w;
        ac = fmaf(lc * g_cos1[h*T1+t], g_cos1[h*T1+tp], ac);
        as = fmaf(lt * g_sin1[h*T1+t], g_sin1[h*T1+tp], as);
    }
    size_t o = ((size_t)l*T1 + t)*T1 + tp;
    g_Mc[o] = ac;
    g_Mt[o] = as;
}

__global__ void k_buildK1(const float* __restrict__ Wr, const float* __restrict__ Wi) {
    int i = blockIdx.x*blockDim.x + threadIdx.x;
    if (i >= CC*T1) return;
    int c = i / T1, d = i % T1;
    float acc = 0.f;
    for (int h = 0; h < L1; h++) {
        float w = (h == 0 || h == L1-1) ? (1.0f/T1) : (2.0f/T1);
        acc += w * (Wr[c*L1+h]*g_cos1[h*T1+d] - Wi[c*L1+h]*g_sin1[h*T1+d]);
    }
    g_K1[i] = acc;
}

// D1[c][t][s2] = sum_s K1[c][(s-t) mod T1] * Wfc[s][s2]
__global__ void k_buildD1(const float* __restrict__ Wfc) {
    __shared__ float kr[T1];
    int t = blockIdx.x, c = blockIdx.y, s2 = threadIdx.x;   // block 96 threads
    for (int s = s2; s < T1; s += T2) kr[s] = g_K1[c*T1 + s];
    __syncthreads();
    float acc = 0.f;
    int ii = (T1 - t) % T1;
    for (int s = 0; s < T1; s++) {
        acc = fmaf(kr[ii], Wfc[s*T2 + s2], acc);
        ii++; if (ii == T1) ii = 0;
    }
    g_D1[((size_t)c*T1 + t)*T2 + s2] = acc;
}

__global__ void k_buildK2(const float* __restrict__ Wr, const float* __restrict__ Wi) {
    int i = blockIdx.x*blockDim.x + threadIdx.x;
    if (i >= CC*T2) return;
    int c = i / T2, d = i % T2;
    float acc = 0.f;
    for (int h = 0; h < L2; h++) {
        float w = (h == 0 || h == L2-1) ? (1.0f/T2) : (2.0f/T2);
        acc += w * (Wr[c*L2+h]*g_cos2[h*T2+d] - Wi[c*L2+h]*g_sin2[h*T2+d]);
    }
    g_K2[i] = acc;
}
__global__ void k_expand2() {
    size_t i = (size_t)blockIdx.x*blockDim.x + threadIdx.x;
    if (i >= (size_t)CC*T2*T2) return;
    int s = (int)(i % T2);
    int t = (int)((i / T2) % T2);
    int c = (int)(i / ((size_t)T2*T2));
    g_C2[i] = g_K2[c*T2 + ((s - t + T2) % T2)];
}

// ---------------- channel mix (f32x2: pack (u,v)) ----------------
__global__ void __launch_bounds__(256) k_chmix(const float* __restrict__ x,
                                               const float* __restrict__ Gc,
                                               const float* __restrict__ Gt) {
    __shared__ __align__(16) float2 sG[CC*CC];
    int tid = threadIdx.x;
    for (int i = tid; i < CC*CC; i += 256) sG[i] = make_float2(Gc[i], Gt[i]);
    __syncthreads();
    int b = blockIdx.y;
    size_t m = (size_t)blockIdx.x*256 + tid;   // < NN*T1
    ull a[CC];
#pragma unroll
    for (int l = 0; l < CC; l++) a[l] = 0ull;
    for (int c = 0; c < CC; c++) {
        float xv = x[((size_t)(b*CC + c)*NN)*T1 + m];
        ull xp = pk2(xv, xv);
#pragma unroll
        for (int l = 0; l < CC; l++) fma2(a[l], xp, *(const ull*)&sG[c*CC + l]);
    }
#pragma unroll
    for (int l = 0; l < CC; l++) {
        float2 p = upk2(a[l]);
        g_bufA[((size_t)(b*CC + l)*NN)*T1 + m] = p.x;
        g_bufB[((size_t)(b*CC + l)*NN)*T1 + m] = p.y;
    }
}

// ---------------- xc = resid + u@Mc[c] + v@Mt[c]  (TM=64, f32x2) ----------------
__global__ void __launch_bounds__(256, 1) k_mm2(const float* __restrict__ X1,
                                                const float* __restrict__ X2,
                                                const float* __restrict__ Wa,
                                                const float* __restrict__ Wb,
                                                const float* __restrict__ resid,
                                                float* __restrict__ Y) {
    constexpr int TD = T1, SD = T1, TM = 64, RI = 4, NP = SD/32, TMP = TM + 8;
    __shared__ __align__(16) float xs1[16][TMP];
    __shared__ __align__(16) float xs2[16][TMP];
    __shared__ __align__(16) float wsa[16][SD];
    __shared__ __align__(16) float wsb[16][SD];
    int tid = threadIdx.x, tx = tid & 15, ty = tid >> 4;
    int c = blockIdx.y, b = blockIdx.z;
    size_t row0 = (size_t)(b*CC + c)*NN + (size_t)blockIdx.x*TM;
    const float* WaB = Wa + (size_t)c*TD*SD;
    const float* WbB = Wb + (size_t)c*TD*SD;
    ull acc[RI][NP];
#pragma unroll
    for (int i = 0; i < RI; i++)
#pragma unroll
        for (int j = 0; j < NP; j++) acc[i][j] = 0ull;

    for (int kt = 0; kt < TD/16; kt++) {
        {
            int r = tid >> 2, q = tid & 3;
            size_t gi = (row0 + r)*TD + kt*16 + q*4;
            float4 v1 = *(const float4*)&X1[gi];
            float4 v2 = *(const float4*)&X2[gi];
            xs1[q*4+0][r] = v1.x; xs1[q*4+1][r] = v1.y; xs1[q*4+2][r] = v1.z; xs1[q*4+3][r] = v1.w;
            xs2[q*4+0][r] = v2.x; xs2[q*4+1][r] = v2.y; xs2[q*4+2][r] = v2.z; xs2[q*4+3][r] = v2.w;
        }
        for (int idx = tid; idx < 16*SD/4; idx += 256) {
            int kk = idx / (SD/4), sq = idx % (SD/4);
            *(float4*)&wsa[kk][sq*4] = *(const float4*)&WaB[(size_t)(kt*16+kk)*SD + sq*4];
            *(float4*)&wsb[kk][sq*4] = *(const float4*)&WbB[(size_t)(kt*16+kk)*SD + sq*4];
        }
        __syncthreads();
#pragma unroll
        for (int k = 0; k < 16; k++) {
            float4 xa = *(const float4*)&xs1[k][ty*RI];
            float4 xb = *(const float4*)&xs2[k][ty*RI];
            ull xp1[RI] = { pk2(xa.x,xa.x), pk2(xa.y,xa.y), pk2(xa.z,xa.z), pk2(xa.w,xa.w) };
            ull xp2[RI] = { pk2(xb.x,xb.x), pk2(xb.y,xb.y), pk2(xb.z,xb.z), pk2(xb.w,xb.w) };
            ull wpa[NP], wpb[NP];
#pragma unroll
            for (int j = 0; j < NP; j++) {
                wpa[j] = *(const ull*)&wsa[k][32*j + 2*tx];
                wpb[j] = *(const ull*)&wsb[k][32*j + 2*tx];
            }
#pragma unroll
            for (int i = 0; i < RI; i++)
#pragma unroll
                for (int j = 0; j < NP; j++) {
                    fma2(acc[i][j], xp1[i], wpa[j]);
                    fma2(acc[i][j], xp2[i], wpb[j]);
                }
        }
        __syncthreads();
    }
#pragma unroll
    for (int i = 0; i < RI; i++)
#pragma unroll
        for (int j = 0; j < NP; j++) {
            int col = 32*j + 2*tx;
            size_t gi = (row0 + ty*RI + i)*SD + col;
            float2 o = upk2(acc[i][j]);
            float2 r = *(const float2*)&resid[gi];
            o.x += r.x; o.y += r.y;
            *(float2*)&Y[gi] = o;
        }
}

// ---------------- generic GEMM: Y = (X1 [+ X2*g][*g]) @ W[c] [+ bias] (TM=128) ----------------
template<int TD, int SD, bool PERCH, bool ADD2, bool G1, bool G2, bool BIAS>
__global__ void __launch_bounds__(256, 1) k_gemm(const float* __restrict__ X1,
                                                 const float* __restrict__ X2,
                                                 const float* __restrict__ W,
                                                 const float* __restrict__ bias,
                                                 const float* __restrict__ gate,
                                                 float* __restrict__ Y) {
    constexpr int TM = 128, RI = 8, NP = SD/32, TMP = TM + 8;
    __shared__ __align__(16) float xs[16][TMP];
    __shared__ __align__(16) float ws[16][SD];
    __shared__ float sg[TD];
    int tid = threadIdx.x, tx = tid & 15, ty = tid >> 4;
    int c = blockIdx.y, b = blockIdx.z;
    size_t row0 = (size_t)(b*CC + c)*NN + (size_t)blockIdx.x*TM;
    const float* Wb = PERCH ? (W + (size_t)c*TD*SD) : W;
    if (G1 || G2) {
        for (int t = tid; t < TD; t += 256) sg[t] = 1.0f + gate[b*TD + t];
        __syncthreads();   // sg must be fully visible before staging reads it
    }
    ull acc[RI][NP];
#pragma unroll
    for (int i = 0; i < RI; i++)
#pragma unroll
        for (int j = 0; j < NP; j++) acc[i][j] = 0ull;

    for (int kt = 0; kt < TD/16; kt++) {
#pragma unroll
        for (int l = 0; l < 2; l++) {
            int idx = tid + 256*l;
            int r = idx >> 2, q = idx & 3;
            int k0 = kt*16 + q*4;
            size_t gi = (row0 + r)*TD + k0;
            float4 v = *(const float4*)&X1[gi];
            if (ADD2) {
                float4 u = *(const float4*)&X2[gi];
                if (G2) {
                    v.x = fmaf(u.x, sg[k0+0], v.x);
                    v.y = fmaf(u.y, sg[k0+1], v.y);
                    v.z = fmaf(u.z, sg[k0+2], v.z);
                    v.w = fmaf(u.w, sg[k0+3], v.w);
                } else { v.x += u.x; v.y += u.y; v.z += u.z; v.w += u.w; }
            } else if (G1) {
                v.x *= sg[k0+0]; v.y *= sg[k0+1]; v.z *= sg[k0+2]; v.w *= sg[k0+3];
            }
            xs[q*4+0][r] = v.x; xs[q*4+1][r] = v.y; xs[q*4+2][r] = v.z; xs[q*4+3][r] = v.w;
        }
        for (int idx = tid; idx < 16*SD/4; idx += 256) {
            int kk = idx / (SD/4), sq = idx % (SD/4);
            *(float4*)&ws[kk][sq*4] = *(const float4*)&Wb[(size_t)(kt*16+kk)*SD + sq*4];
        }
        __syncthreads();
#pragma unroll
        for (int k = 0; k < 16; k++) {
            float4 xa = *(const float4*)&xs[k][ty*RI];
            float4 xb = *(const float4*)&xs[k][ty*RI + 4];
            ull xp[RI] = { pk2(xa.x,xa.x), pk2(xa.y,xa.y), pk2(xa.z,xa.z), pk2(xa.w,xa.w),
                           pk2(xb.x,xb.x), pk2(xb.y,xb.y), pk2(xb.z,xb.z), pk2(xb.w,xb.w) };
            ull wp[NP];
#pragma unroll
            for (int j = 0; j < NP; j++) wp[j] = *(const ull*)&ws[k][32*j + 2*tx];
#pragma unroll
            for (int i = 0; i < RI; i++)
#pragma unroll
                for (int j = 0; j < NP; j++) fma2(acc[i][j], xp[i], wp[j]);
        }
        __syncthreads();
    }
#pragma unroll
    for (int i = 0; i < RI; i++)
#pragma unroll
        for (int j = 0; j < NP; j++) {
            int col = 32*j + 2*tx;
            float2 o = upk2(acc[i][j]);
            if (BIAS) { o.x += bias[col]; o.y += bias[col+1]; }
            *(float2*)&Y[(row0 + ty*RI + i)*SD + col] = o;
        }
}

// ---------------- gmlp: Y = (X@W1)*gelu(X@W2), fused gate-in + feat partials ----------------
template<int TD, bool G1>
__global__ void __launch_bounds__(256, 1) k_gmlp(const float* __restrict__ X,
                                                 const float* __restrict__ W1,
                                                 const float* __restrict__ W2,
                                                 const float* __restrict__ gate,
                                                 float* __restrict__ Y) {
    constexpr int SD = TD, TM = 64, RI = 4, NP = SD/32, TMP = TM + 8;
    __shared__ __align__(16) float xs[16][TMP];
    __shared__ __align__(16) float ws1[16][SD];
    __shared__ __align__(16) float ws2[16][SD];
    __shared__ float sg[TD];
    int tid = threadIdx.x, tx = tid & 15, ty = tid >> 4;
    int c = blockIdx.y, b = blockIdx.z;
    size_t row0 = (size_t)(b*CC + c)*NN + (size_t)blockIdx.x*TM;
    if (G1) {
        for (int t = tid; t < TD; t += 256) sg[t] = 1.0f + gate[b*TD + t];
        __syncthreads();   // sg must be fully visible before staging reads it
    }
    ull a1[RI][NP], a2[RI][NP];
#pragma unroll
    for (int i = 0; i < RI; i++)
#pragma unroll
        for (int j = 0; j < NP; j++) { a1[i][j] = 0ull; a2[i][j] = 0ull; }

    for (int kt = 0; kt < TD/16; kt++) {
        {
            int r = tid >> 2, q = tid & 3;
            int k0 = kt*16 + q*4;
            float4 v = *(const float4*)&X[(row0 + r)*TD + k0];
            if (G1) { v.x *= sg[k0+0]; v.y *= sg[k0+1]; v.z *= sg[k0+2]; v.w *= sg[k0+3]; }
            xs[q*4+0][r] = v.x; xs[q*4+1][r] = v.y; xs[q*4+2][r] = v.z; xs[q*4+3][r] = v.w;
        }
        for (int idx = tid; idx < 16*SD/4; idx += 256) {
            int kk = idx / (SD/4), sq = idx % (SD/4);
            *(float4*)&ws1[kk][sq*4] = *(const float4*)&W1[(size_t)(kt*16+kk)*SD + sq*4];
            *(float4*)&ws2[kk][sq*4] = *(const float4*)&W2[(size_t)(kt*16+kk)*SD + sq*4];
        }
        __syncthreads();
#pragma unroll
        for (int k = 0; k < 16; k++) {
            float4 xa = *(const float4*)&xs[k][ty*RI];
            ull xp[RI] = { pk2(xa.x,xa.x), pk2(xa.y,xa.y), pk2(xa.z,xa.z), pk2(xa.w,xa.w) };
            ull wp1[NP], wp2[NP];
#pragma unroll
            for (int j = 0; j < NP; j++) {
                wp1[j] = *(const ull*)&ws1[k][32*j + 2*tx];
                wp2[j] = *(const ull*)&ws2[k][32*j + 2*tx];
            }
#pragma unroll
            for (int i = 0; i < RI; i++)
#pragma unroll
                for (int j = 0; j < NP; j++) {
                    fma2(a1[i][j], xp[i], wp1[j]);
                    fma2(a2[i][j], xp[i], wp2[j]);
                }
        }
        __syncthreads();
    }
    float colx[NP], coly[NP];
#pragma unroll
    for (int j = 0; j < NP; j++) { colx[j] = 0.f; coly[j] = 0.f; }
#pragma unroll
    for (int i = 0; i < RI; i++)
#pragma unroll
        for (int j = 0; j < NP; j++) {
            int col = 32*j + 2*tx;
            float2 p1 = upk2(a1[i][j]);
            float2 p2 = upk2(a2[i][j]);
            float2 o = make_float2(p1.x*gelu_t(p2.x), p1.y*gelu_t(p2.y));
            *(float2*)&Y[(row0 + ty*RI + i)*SD + col] = o;
            colx[j] += o.x; coly[j] += o.y;
        }
    // per-block column partial sums (n-mean fusion), deterministic
#pragma unroll
    for (int j = 0; j < NP; j++) {
        ws1[ty][32*j + 2*tx]     = colx[j];
        ws1[ty][32*j + 2*tx + 1] = coly[j];
    }
    __syncthreads();
    if (tid < SD) {
        float tot = 0.f;
#pragma unroll
        for (int r = 0; r < 16; r++) tot += ws1[r][tid];
        g_featP[((size_t)(b*CC + c)*8 + blockIdx.x)*TD + tid] = tot;
    }
}

// ---------------- attn gate: g[b,t] = gelu(diag softmax(qk^T/8)) ----------------
template<int T>
__global__ void __launch_bounds__(T) k_gate(const float* __restrict__ Wq,
                                            const float* __restrict__ Wk) {
    __shared__ float ks[T][EE];
    int b = blockIdx.x, t = threadIdx.x;
    float q[EE], kk[EE];
#pragma unroll
    for (int e = 0; e < EE; e++) { q[e] = 0.f; kk[e] = 0.f; }
    for (int c = 0; c < CC; c++) {
        float f = 0.f;
#pragma unroll
        for (int p = 0; p < 8; p++) f += g_featP[((size_t)(b*CC + c)*8 + p)*T + t];
        f *= (1.0f/NN);
#pragma unroll
        for (int e = 0; e < EE; e++) {
            q[e]  = fmaf(f, Wq[c*EE + e], q[e]);
            kk[e] = fmaf(f, Wk[c*EE + e], kk[e]);
        }
    }
#pragma unroll
    for (int e = 0; e < EE; e++) ks[t][e] = kk[e];
    __syncthreads();
    float smax = -1e30f, stt = 0.f;
    for (int j = 0; j < T; j++) {
        float d = 0.f;
#pragma unroll
        for (int e = 0; e < EE; e++) d = fmaf(q[e], ks[j][e], d);
        d *= 0.125f;
        if (j == t) stt = d;
        smax = fmaxf(smax, d);
    }
    float ssum = 0.f;
    for (int j = 0; j < T; j++) {
        float d = 0.f;
#pragma unroll
        for (int e = 0; e < EE; e++) d = fmaf(q[e], ks[j][e], d);
        ssum += expf(d*0.125f - smax);
    }
    float p = expf(stt - smax) / ssum;
    g_gate[b*T + t] = gelu_t(p);
}

// ---------------- driver ----------------
extern "C" void kernel_launch(void* const* d_in, const int* in_sizes, int n_in,
                              void* d_out, int out_size) {
    const float* x   = (const float*)d_in[0];
    const float* Gc  = (const float*)d_in[3];
    const float* Lc  = (const float*)d_in[4];
    const float* Gt  = (const float*)d_in[5];
    const float* Lt  = (const float*)d_in[6];
    const float* f1r = (const float*)d_in[7];
    const float* f1i = (const float*)d_in[8];
    const float* f2r = (const float*)d_in[9];
    const float* f2i = (const float*)d_in[10];
    const float* Wfc = (const float*)d_in[11];
    const float* bfc = (const float*)d_in[12];
    const float* mi1 = (const float*)d_in[13];
    const float* mi2 = (const float*)d_in[14];
    const float* mo1 = (const float*)d_in[15];
    const float* mo2 = (const float*)d_in[16];
    const float* aiq = (const float*)d_in[17];
    const float* aik = (const float*)d_in[18];
    const float* aoq = (const float*)d_in[19];
    const float* aok = (const float*)d_in[20];
    float* out = (float*)d_out;

    float *bufA, *bufB, *bufC, *bufD, *bufE, *bufF, *Mc, *Mt, *D1, *C2, *gate;
    cudaGetSymbolAddress((void**)&bufA, g_bufA);
    cudaGetSymbolAddress((void**)&bufB, g_bufB);
    cudaGetSymbolAddress((void**)&bufC, g_bufC);
    cudaGetSymbolAddress((void**)&bufD, g_bufD);
    cudaGetSymbolAddress((void**)&bufE, g_bufE);
    cudaGetSymbolAddress((void**)&bufF, g_bufF);
    cudaGetSymbolAddress((void**)&Mc,   g_Mc);
    cudaGetSymbolAddress((void**)&Mt,   g_Mt);
    cudaGetSymbolAddress((void**)&D1,   g_D1);
    cudaGetSymbolAddress((void**)&C2,   g_C2);
    cudaGetSymbolAddress((void**)&gate, g_gate);

    // precompute operator matrices
    k_tables<<<(L1*T1 + L2*T2 + 255)/256, 256>>>();
    k_buildM<<<dim3(T1, CC), T1>>>(Lc, Lt);
    k_buildK1<<<(CC*T1 + 255)/256, 256>>>(f1r, f1i);
    k_buildD1<<<dim3(T1, CC), T2>>>(Wfc);
    k_buildK2<<<(CC*T2 + 255)/256, 256>>>(f2r, f2i);
    k_expand2<<<(int)(((size_t)CC*T2*T2 + 255)/256), 256>>>();

    // freq_attn_in: u = Gc^T x, v = Gt^T x ; xc = x + u@Mc[c] + v@Mt[c]
    k_chmix<<<dim3(NN*T1/256, BB), 256>>>(x, Gc, Gt);
    k_mm2<<<dim3(NN/64, CC, BB), 256>>>(bufA, bufB, Mc, Mt, x, bufC);

    // input-side layers (gate fused into next consumer's loads)
    k_gmlp<T1, false><<<dim3(NN/64, CC, BB), 256>>>(bufC, mi1, mi2, nullptr, bufA);
    k_gate<T1><<<BB, T1>>>(aiq, aik);
    k_gmlp<T1, true ><<<dim3(NN/64, CC, BB), 256>>>(bufA, mi1 + (size_t)T1*T1, mi2 + (size_t)T1*T1, gate, bufC);
    k_gate<T1><<<BB, T1>>>(aiq + CC*EE, aik + CC*EE);

    // h_y = (x + xc*(1+g)) @ D1[c] + bfc     (fconv1 + fc_idp fused)
    k_gemm<T1, T2, true, true, false, true, true><<<dim3(NN/128, CC, BB), 256>>>(x, bufC, D1, bfc, gate, bufD);

    // output-side layers
    k_gmlp<T2, false><<<dim3(NN/64, CC, BB), 256>>>(bufD, mo1, mo2, nullptr, bufE);
    k_gate<T2><<<BB, T2>>>(aoq, aok);
    k_gmlp<T2, true ><<<dim3(NN/64, CC, BB), 256>>>(bufE, mo1 + (size_t)T2*T2, mo2 + (size_t)T2*T2, gate, bufF);
    k_gate<T2><<<BB, T2>>>(aoq + CC*EE, aok + CC*EE);

    // out = (h_y + y_c*(1+g)) @ C2[c]
    k_gemm<T2, T2, true, true, false, true, false><<<dim3(NN/128, CC, BB), 256>>>(bufD, bufF, C2, nullptr, gate, out);
}

// round 5
// speedup vs baseline: 1.5060x; 1.5060x over previous
#include <cuda_runtime.h>
#include <math.h>
#include <stdint.h>

#define BB 16
#define CC 32
#define NN 512
#define T1 192
#define T2 96
#define L1 97
#define L2 49
#define EE 64

typedef unsigned long long ull;

static constexpr size_t SZ1 = (size_t)BB*CC*NN*T1;
static constexpr size_t SZ2 = (size_t)BB*CC*NN*T2;

// ---------------- scratch ----------------
__device__ float g_bufA[SZ1];
__device__ float g_bufB[SZ1];
__device__ float g_bufC[SZ1];
__device__ float g_bufD[SZ2];
__device__ float g_bufE[SZ2];
__device__ float g_bufF[SZ2];
__device__ float g_Mc[CC*T1*T1];
__device__ float g_Mt[CC*T1*T1];
__device__ float g_D1[CC*T1*T2];
__device__ float g_C2[CC*T2*T2];
__device__ float g_cos1[L1*T1];
__device__ float g_sin1[L1*T1];
__device__ float g_cos2[L2*T2];
__device__ float g_sin2[L2*T2];
__device__ float g_K1[CC*T1];
__device__ float g_K2[CC*T2];
__device__ float g_featP[BB*CC*8*T1];
__device__ float g_gate[BB*T1];

// ---------------- f32x2 helpers ----------------
__device__ __forceinline__ ull pk2(float lo, float hi) {
    ull r; asm("mov.b64 %0, {%1,%2};" : "=l"(r) : "f"(lo), "f"(hi)); return r;
}
__device__ __forceinline__ void fma2(ull& d, ull a, ull b) {
    asm("fma.rn.f32x2 %0, %1, %2, %0;" : "+l"(d) : "l"(a), "l"(b));
}
__device__ __forceinline__ float2 upk2(ull v) {
    float2 f; asm("mov.b64 {%0,%1}, %2;" : "=f"(f.x), "=f"(f.y) : "l"(v)); return f;
}

__device__ __forceinline__ float gelu_t(float x) {
    float x3 = x*x*x;
    return 0.5f*x*(1.0f + tanhf(0.7978845608028654f*(x + 0.044715f*x3)));
}

// ---------------- precompute ----------------
__global__ void k_tables() {
    int i = blockIdx.x*blockDim.x + threadIdx.x;
    if (i < L1*T1) {
        int h = i / T1, t = i % T1;
        int m = (h*t) % T1;
        float a = (float)m * (1.0f/96.0f);
        g_cos1[i] = cospif(a);
        g_sin1[i] = sinpif(a);
    }
    int j = i - L1*T1;
    if (j >= 0 && j < L2*T2) {
        int h = j / T2, t = j % T2;
        int m = (h*t) % T2;
        float a = (float)m * (1.0f/48.0f);
        g_cos2[j] = cospif(a);
        g_sin2[j] = sinpif(a);
    }
}

__global__ void k_buildM(const float* __restrict__ Lc, const float* __restrict__ Lt) {
    int t = blockIdx.x, l = blockIdx.y, tp = threadIdx.x;
    float ac = 0.f, as = 0.f;
    for (int h = 0; h < L1; h++) {
        float w = (h == 0 || h == L1-1) ? (1.0f/T1) : (2.0f/T1);
        float lc = Lc[l*L1+h]*w, lt = Lt[l*L1+h]*w;
        ac = fmaf(lc * g_cos1[h*T1+t], g_cos1[h*T1+tp], ac);
        as = fmaf(lt * g_sin1[h*T1+t], g_sin1[h*T1+tp], as);
    }
    size_t o = ((size_t)l*T1 + t)*T1 + tp;
    g_Mc[o] = ac;
    g_Mt[o] = as;
}

__global__ void k_buildK1(const float* __restrict__ Wr, const float* __restrict__ Wi) {
    int i = blockIdx.x*blockDim.x + threadIdx.x;
    if (i >= CC*T1) return;
    int c = i / T1, d = i % T1;
    float acc = 0.f;
    for (int h = 0; h < L1; h++) {
        float w = (h == 0 || h == L1-1) ? (1.0f/T1) : (2.0f/T1);
        acc += w * (Wr[c*L1+h]*g_cos1[h*T1+d] - Wi[c*L1+h]*g_sin1[h*T1+d]);
    }
    g_K1[i] = acc;
}

// D1[c][t][s2] = sum_s K1[c][(s-t) mod T1] * Wfc[s][s2]
__global__ void k_buildD1(const float* __restrict__ Wfc) {
    __shared__ float kr[T1];
    int t = blockIdx.x, c = blockIdx.y, s2 = threadIdx.x;   // block 96 threads
    for (int s = s2; s < T1; s += T2) kr[s] = g_K1[c*T1 + s];
    __syncthreads();
    float acc = 0.f;
    int ii = (T1 - t) % T1;
    for (int s = 0; s < T1; s++) {
        acc = fmaf(kr[ii], Wfc[s*T2 + s2], acc);
        ii++; if (ii == T1) ii = 0;
    }
    g_D1[((size_t)c*T1 + t)*T2 + s2] = acc;
}

__global__ void k_buildK2(const float* __restrict__ Wr, const float* __restrict__ Wi) {
    int i = blockIdx.x*blockDim.x + threadIdx.x;
    if (i >= CC*T2) return;
    int c = i / T2, d = i % T2;
    float acc = 0.f;
    for (int h = 0; h < L2; h++) {
        float w = (h == 0 || h == L2-1) ? (1.0f/T2) : (2.0f/T2);
        acc += w * (Wr[c*L2+h]*g_cos2[h*T2+d] - Wi[c*L2+h]*g_sin2[h*T2+d]);
    }
    g_K2[i] = acc;
}
__global__ void k_expand2() {
    size_t i = (size_t)blockIdx.x*blockDim.x + threadIdx.x;
    if (i >= (size_t)CC*T2*T2) return;
    int s = (int)(i % T2);
    int t = (int)((i / T2) % T2);
    int c = (int)(i / ((size_t)T2*T2));
    g_C2[i] = g_K2[c*T2 + ((s - t + T2) % T2)];
}

// ---------------- channel mix (f32x2: pack (u,v)) ----------------
__global__ void __launch_bounds__(256) k_chmix(const float* __restrict__ x,
                                               const float* __restrict__ Gc,
                                               const float* __restrict__ Gt) {
    __shared__ __align__(16) float2 sG[CC*CC];
    int tid = threadIdx.x;
    for (int i = tid; i < CC*CC; i += 256) sG[i] = make_float2(Gc[i], Gt[i]);
    __syncthreads();
    int b = blockIdx.y;
    size_t m = (size_t)blockIdx.x*256 + tid;   // < NN*T1
    ull a[CC];
#pragma unroll
    for (int l = 0; l < CC; l++) a[l] = 0ull;
    for (int c = 0; c < CC; c++) {
        float xv = x[((size_t)(b*CC + c)*NN)*T1 + m];
        ull xp = pk2(xv, xv);
#pragma unroll
        for (int l = 0; l < CC; l++) fma2(a[l], xp, *(const ull*)&sG[c*CC + l]);
    }
#pragma unroll
    for (int l = 0; l < CC; l++) {
        float2 p = upk2(a[l]);
        g_bufA[((size_t)(b*CC + l)*NN)*T1 + m] = p.x;
        g_bufB[((size_t)(b*CC + l)*NN)*T1 + m] = p.y;
    }
}

// ---------------- xc = resid + u@Mc[c] + v@Mt[c]  (TM=64, f32x2) ----------------
__global__ void __launch_bounds__(256, 1) k_mm2(const float* __restrict__ X1,
                                                const float* __restrict__ X2,
                                                const float* __restrict__ Wa,
                                                const float* __restrict__ Wb,
                                                const float* __restrict__ resid,
                                                float* __restrict__ Y) {
    constexpr int TD = T1, SD = T1, TM = 64, RI = 4, NP = SD/32, TMP = TM + 8;
    __shared__ __align__(16) float xs1[16][TMP];
    __shared__ __align__(16) float xs2[16][TMP];
    __shared__ __align__(16) float wsa[16][SD];
    __shared__ __align__(16) float wsb[16][SD];
    int tid = threadIdx.x, tx = tid & 15, ty = tid >> 4;
    int c = blockIdx.y, b = blockIdx.z;
    size_t row0 = (size_t)(b*CC + c)*NN + (size_t)blockIdx.x*TM;
    const float* WaB = Wa + (size_t)c*TD*SD;
    const float* WbB = Wb + (size_t)c*TD*SD;
    ull acc[RI][NP];
#pragma unroll
    for (int i = 0; i < RI; i++)
#pragma unroll
        for (int j = 0; j < NP; j++) acc[i][j] = 0ull;

    for (int kt = 0; kt < TD/16; kt++) {
        {
            int r = tid >> 2, q = tid & 3;
            size_t gi = (row0 + r)*TD + kt*16 + q*4;
            float4 v1 = *(const float4*)&X1[gi];
            float4 v2 = *(const float4*)&X2[gi];
            xs1[q*4+0][r] = v1.x; xs1[q*4+1][r] = v1.y; xs1[q*4+2][r] = v1.z; xs1[q*4+3][r] = v1.w;
            xs2[q*4+0][r] = v2.x; xs2[q*4+1][r] = v2.y; xs2[q*4+2][r] = v2.z; xs2[q*4+3][r] = v2.w;
        }
        for (int idx = tid; idx < 16*SD/4; idx += 256) {
            int kk = idx / (SD/4), sq = idx % (SD/4);
            *(float4*)&wsa[kk][sq*4] = *(const float4*)&WaB[(size_t)(kt*16+kk)*SD + sq*4];
            *(float4*)&wsb[kk][sq*4] = *(const float4*)&WbB[(size_t)(kt*16+kk)*SD + sq*4];
        }
        __syncthreads();
#pragma unroll
        for (int k = 0; k < 16; k++) {
            float4 xa = *(const float4*)&xs1[k][ty*RI];
            float4 xb = *(const float4*)&xs2[k][ty*RI];
            ull xp1[RI] = { pk2(xa.x,xa.x), pk2(xa.y,xa.y), pk2(xa.z,xa.z), pk2(xa.w,xa.w) };
            ull xp2[RI] = { pk2(xb.x,xb.x), pk2(xb.y,xb.y), pk2(xb.z,xb.z), pk2(xb.w,xb.w) };
            ull wpa[NP], wpb[NP];
#pragma unroll
            for (int j = 0; j < NP; j++) {
                wpa[j] = *(const ull*)&wsa[k][32*j + 2*tx];
                wpb[j] = *(const ull*)&wsb[k][32*j + 2*tx];
            }
#pragma unroll
            for (int i = 0; i < RI; i++)
#pragma unroll
                for (int j = 0; j < NP; j++) {
                    fma2(acc[i][j], xp1[i], wpa[j]);
                    fma2(acc[i][j], xp2[i], wpb[j]);
                }
        }
        __syncthreads();
    }
#pragma unroll
    for (int i = 0; i < RI; i++)
#pragma unroll
        for (int j = 0; j < NP; j++) {
            int col = 32*j + 2*tx;
            size_t gi = (row0 + ty*RI + i)*SD + col;
            float2 o = upk2(acc[i][j]);
            float2 r = *(const float2*)&resid[gi];
            o.x += r.x; o.y += r.y;
            *(float2*)&Y[gi] = o;
        }
}

// ---------------- generic GEMM: Y = (X1 [+ X2*g][*g]) @ W[c] [+ bias] (TM=128) ----------------
template<int TD, int SD, bool PERCH, bool ADD2, bool G1, bool G2, bool BIAS>
__global__ void __launch_bounds__(256, 1) k_gemm(const float* __restrict__ X1,
                                                 const float* __restrict__ X2,
                                                 const float* __restrict__ W,
                                                 const float* __restrict__ bias,
                                                 const float* __restrict__ gate,
                                                 float* __restrict__ Y) {
    constexpr int TM = 128, RI = 8, NP = SD/32, TMP = TM + 8;
    __shared__ __align__(16) float xs[16][TMP];
    __shared__ __align__(16) float ws[16][SD];
    __shared__ float sg[TD];
    int tid = threadIdx.x, tx = tid & 15, ty = tid >> 4;
    int c = blockIdx.y, b = blockIdx.z;
    size_t row0 = (size_t)(b*CC + c)*NN + (size_t)blockIdx.x*TM;
    const float* Wb = PERCH ? (W + (size_t)c*TD*SD) : W;
    if (G1 || G2) {
        for (int t = tid; t < TD; t += 256) sg[t] = 1.0f + gate[b*TD + t];
        __syncthreads();   // sg must be fully visible before staging reads it
    }
    ull acc[RI][NP];
#pragma unroll
    for (int i = 0; i < RI; i++)
#pragma unroll
        for (int j = 0; j < NP; j++) acc[i][j] = 0ull;

    for (int kt = 0; kt < TD/16; kt++) {
#pragma unroll
        for (int l = 0; l < 2; l++) {
            int idx = tid + 256*l;
            int r = idx >> 2, q = idx & 3;
            int k0 = kt*16 + q*4;
            size_t gi = (row0 + r)*TD + k0;
            float4 v = *(const float4*)&X1[gi];
            if (ADD2) {
                float4 u = *(const float4*)&X2[gi];
                if (G2) {
                    v.x = fmaf(u.x, sg[k0+0], v.x);
                    v.y = fmaf(u.y, sg[k0+1], v.y);
                    v.z = fmaf(u.z, sg[k0+2], v.z);
                    v.w = fmaf(u.w, sg[k0+3], v.w);
                } else { v.x += u.x; v.y += u.y; v.z += u.z; v.w += u.w; }
            } else if (G1) {
                v.x *= sg[k0+0]; v.y *= sg[k0+1]; v.z *= sg[k0+2]; v.w *= sg[k0+3];
            }
            xs[q*4+0][r] = v.x; xs[q*4+1][r] = v.y; xs[q*4+2][r] = v.z; xs[q*4+3][r] = v.w;
        }
        for (int idx = tid; idx < 16*SD/4; idx += 256) {
            int kk = idx / (SD/4), sq = idx % (SD/4);
            *(float4*)&ws[kk][sq*4] = *(const float4*)&Wb[(size_t)(kt*16+kk)*SD + sq*4];
        }
        __syncthreads();
#pragma unroll
        for (int k = 0; k < 16; k++) {
            float4 xa = *(const float4*)&xs[k][ty*RI];
            float4 xb = *(const float4*)&xs[k][ty*RI + 4];
            ull xp[RI] = { pk2(xa.x,xa.x), pk2(xa.y,xa.y), pk2(xa.z,xa.z), pk2(xa.w,xa.w),
                           pk2(xb.x,xb.x), pk2(xb.y,xb.y), pk2(xb.z,xb.z), pk2(xb.w,xb.w) };
            ull wp[NP];
#pragma unroll
            for (int j = 0; j < NP; j++) wp[j] = *(const ull*)&ws[k][32*j + 2*tx];
#pragma unroll
            for (int i = 0; i < RI; i++)
#pragma unroll
                for (int j = 0; j < NP; j++) fma2(acc[i][j], xp[i], wp[j]);
        }
        __syncthreads();
    }
#pragma unroll
    for (int i = 0; i < RI; i++)
#pragma unroll
        for (int j = 0; j < NP; j++) {
            int col = 32*j + 2*tx;
            float2 o = upk2(acc[i][j]);
            if (BIAS) { o.x += bias[col]; o.y += bias[col+1]; }
            *(float2*)&Y[(row0 + ty*RI + i)*SD + col] = o;
        }
}

// ---------------- gmlp: Y = (X@W1)*gelu(X@W2), fused gate-in + feat partials ----------------
template<int TD, bool G1>
__global__ void __launch_bounds__(256, 1) k_gmlp(const float* __restrict__ X,
                                                 const float* __restrict__ W1,
                                                 const float* __restrict__ W2,
                                                 const float* __restrict__ gate,
                                                 float* __restrict__ Y) {
    constexpr int SD = TD, TM = 64, RI = 4, NP = SD/32, TMP = TM + 8;
    __shared__ __align__(16) float xs[16][TMP];
    __shared__ __align__(16) float ws1[16][SD];
    __shared__ __align__(16) float ws2[16][SD];
    __shared__ float sg[TD];
    int tid = threadIdx.x, tx = tid & 15, ty = tid >> 4;
    int c = blockIdx.y, b = blockIdx.z;
    size_t row0 = (size_t)(b*CC + c)*NN + (size_t)blockIdx.x*TM;
    if (G1) {
        for (int t = tid; t < TD; t += 256) sg[t] = 1.0f + gate[b*TD + t];
        __syncthreads();   // sg must be fully visible before staging reads it
    }
    ull a1[RI][NP], a2[RI][NP];
#pragma unroll
    for (int i = 0; i < RI; i++)
#pragma unroll
        for (int j = 0; j < NP; j++) { a1[i][j] = 0ull; a2[i][j] = 0ull; }

    for (int kt = 0; kt < TD/16; kt++) {
        {
            int r = tid >> 2, q = tid & 3;
            int k0 = kt*16 + q*4;
            float4 v = *(const float4*)&X[(row0 + r)*TD + k0];
            if (G1) { v.x *= sg[k0+0]; v.y *= sg[k0+1]; v.z *= sg[k0+2]; v.w *= sg[k0+3]; }
            xs[q*4+0][r] = v.x; xs[q*4+1][r] = v.y; xs[q*4+2][r] = v.z; xs[q*4+3][r] = v.w;
        }
        for (int idx = tid; idx < 16*SD/4; idx += 256) {
            int kk = idx / (SD/4), sq = idx % (SD/4);
            *(float4*)&ws1[kk][sq*4] = *(const float4*)&W1[(size_t)(kt*16+kk)*SD + sq*4];
            *(float4*)&ws2[kk][sq*4] = *(const float4*)&W2[(size_t)(kt*16+kk)*SD + sq*4];
        }
        __syncthreads();
#pragma unroll
        for (int k = 0; k < 16; k++) {
            float4 xa = *(const float4*)&xs[k][ty*RI];
            ull xp[RI] = { pk2(xa.x,xa.x), pk2(xa.y,xa.y), pk2(xa.z,xa.z), pk2(xa.w,xa.w) };
            ull wp1[NP], wp2[NP];
#pragma unroll
            for (int j = 0; j < NP; j++) {
                wp1[j] = *(const ull*)&ws1[k][32*j + 2*tx];
                wp2[j] = *(const ull*)&ws2[k][32*j + 2*tx];
            }
#pragma unroll
            for (int i = 0; i < RI; i++)
#pragma unroll
                for (int j = 0; j < NP; j++) {
                    fma2(a1[i][j], xp[i], wp1[j]);
                    fma2(a2[i][j], xp[i], wp2[j]);
                }
        }
        __syncthreads();
    }
    float colx[NP], coly[NP];
#pragma unroll
    for (int j = 0; j < NP; j++) { colx[j] = 0.f; coly[j] = 0.f; }
#pragma unroll
    for (int i = 0; i < RI; i++)
#pragma unroll
        for (int j = 0; j < NP; j++) {
            int col = 32*j + 2*tx;
            float2 p1 = upk2(a1[i][j]);
            float2 p2 = upk2(a2[i][j]);
            float2 o = make_float2(p1.x*gelu_t(p2.x), p1.y*gelu_t(p2.y));
            *(float2*)&Y[(row0 + ty*RI + i)*SD + col] = o;
            colx[j] += o.x; coly[j] += o.y;
        }
    // per-block column partial sums (n-mean fusion), deterministic
#pragma unroll
    for (int j = 0; j < NP; j++) {
        ws1[ty][32*j + 2*tx]     = colx[j];
        ws1[ty][32*j + 2*tx + 1] = coly[j];
    }
    __syncthreads();
    if (tid < SD) {
        float tot = 0.f;
#pragma unroll
        for (int r = 0; r < 16; r++) tot += ws1[r][tid];
        g_featP[((size_t)(b*CC + c)*8 + blockIdx.x)*TD + tid] = tot;
    }
}

// ---------------- attn gate: g[b,t] = gelu(diag softmax(qk^T/8)) ----------------
template<int T>
__global__ void __launch_bounds__(T) k_gate(const float* __restrict__ Wq,
                                            const float* __restrict__ Wk) {
    __shared__ float ks[T][EE];
    int b = blockIdx.x, t = threadIdx.x;
    float q[EE], kk[EE];
#pragma unroll
    for (int e = 0; e < EE; e++) { q[e] = 0.f; kk[e] = 0.f; }
    for (int c = 0; c < CC; c++) {
        float f = 0.f;
#pragma unroll
        for (int p = 0; p < 8; p++) f += g_featP[((size_t)(b*CC + c)*8 + p)*T + t];
        f *= (1.0f/NN);
#pragma unroll
        for (int e = 0; e < EE; e++) {
            q[e]  = fmaf(f, Wq[c*EE + e], q[e]);
            kk[e] = fmaf(f, Wk[c*EE + e], kk[e]);
        }
    }
#pragma unroll
    for (int e = 0; e < EE; e++) ks[t][e] = kk[e];
    __syncthreads();
    float smax = -1e30f, stt = 0.f;
    for (int j = 0; j < T; j++) {
        float d = 0.f;
#pragma unroll
        for (int e = 0; e < EE; e++) d = fmaf(q[e], ks[j][e], d);
        d *= 0.125f;
        if (j == t) stt = d;
        smax = fmaxf(smax, d);
    }
    float ssum = 0.f;
    for (int j = 0; j < T; j++) {
        float d = 0.f;
#pragma unroll
        for (int e = 0; e < EE; e++) d = fmaf(q[e], ks[j][e], d);
        ssum += expf(d*0.125f - smax);
    }
    float p = expf(stt - smax) / ssum;
    g_gate[b*T + t] = gelu_t(p);
}

// ---------------- driver ----------------
extern "C" void kernel_launch(void* const* d_in, const int* in_sizes, int n_in,
                              void* d_out, int out_size) {
    const float* x   = (const float*)d_in[0];
    const float* Gc  = (const float*)d_in[3];
    const float* Lc  = (const float*)d_in[4];
    const float* Gt  = (const float*)d_in[5];
    const float* Lt  = (const float*)d_in[6];
    const float* f1r = (const float*)d_in[7];
    const float* f1i = (const float*)d_in[8];
    const float* f2r = (const float*)d_in[9];
    const float* f2i = (const float*)d_in[10];
    const float* Wfc = (const float*)d_in[11];
    const float* bfc = (const float*)d_in[12];
    const float* mi1 = (const float*)d_in[13];
    const float* mi2 = (const float*)d_in[14];
    const float* mo1 = (const float*)d_in[15];
    const float* mo2 = (const float*)d_in[16];
    const float* aiq = (const float*)d_in[17];
    const float* aik = (const float*)d_in[18];
    const float* aoq = (const float*)d_in[19];
    const float* aok = (const float*)d_in[20];
    float* out = (float*)d_out;

    float *bufA, *bufB, *bufC, *bufD, *bufE, *bufF, *Mc, *Mt, *D1, *C2, *gate;
    cudaGetSymbolAddress((void**)&bufA, g_bufA);
    cudaGetSymbolAddress((void**)&bufB, g_bufB);
    cudaGetSymbolAddress((void**)&bufC, g_bufC);
    cudaGetSymbolAddress((void**)&bufD, g_bufD);
    cudaGetSymbolAddress((void**)&bufE, g_bufE);
    cudaGetSymbolAddress((void**)&bufF, g_bufF);
    cudaGetSymbolAddress((void**)&Mc,   g_Mc);
    cudaGetSymbolAddress((void**)&Mt,   g_Mt);
    cudaGetSymbolAddress((void**)&D1,   g_D1);
    cudaGetSymbolAddress((void**)&C2,   g_C2);
    cudaGetSymbolAddress((void**)&gate, g_gate);

    // precompute operator matrices
    k_tables<<<(L1*T1 + L2*T2 + 255)/256, 256>>>();
    k_buildM<<<dim3(T1, CC), T1>>>(Lc, Lt);
    k_buildK1<<<(CC*T1 + 255)/256, 256>>>(f1r, f1i);
    k_buildD1<<<dim3(T1, CC), T2>>>(Wfc);
    k_buildK2<<<(CC*T2 + 255)/256, 256>>>(f2r, f2i);
    k_expand2<<<(int)(((size_t)CC*T2*T2 + 255)/256), 256>>>();

    // freq_attn_in: u = Gc^T x, v = Gt^T x ; xc = x + u@Mc[c] + v@Mt[c]
    k_chmix<<<dim3(NN*T1/256, BB), 256>>>(x, Gc, Gt);
    k_mm2<<<dim3(NN/64, CC, BB), 256>>>(bufA, bufB, Mc, Mt, x, bufC);

    // input-side layers (gate fused into next consumer's loads)
    k_gmlp<T1, false><<<dim3(NN/64, CC, BB), 256>>>(bufC, mi1, mi2, nullptr, bufA);
    k_gate<T1><<<BB, T1>>>(aiq, aik);
    k_gmlp<T1, true ><<<dim3(NN/64, CC, BB), 256>>>(bufA, mi1 + (size_t)T1*T1, mi2 + (size_t)T1*T1, gate, bufC);
    k_gate<T1><<<BB, T1>>>(aiq + CC*EE, aik + CC*EE);

    // h_y = (x + xc*(1+g)) @ D1[c] + bfc     (fconv1 + fc_idp fused)
    k_gemm<T1, T2, true, true, false, true, true><<<dim3(NN/128, CC, BB), 256>>>(x, bufC, D1, bfc, gate, bufD);

    // output-side layers
    k_gmlp<T2, false><<<dim3(NN/64, CC, BB), 256>>>(bufD, mo1, mo2, nullptr, bufE);
    k_gate<T2><<<BB, T2>>>(aoq, aok);
    k_gmlp<T2, true ><<<dim3(NN/64, CC, BB), 256>>>(bufE, mo1 + (size_t)T2*T2, mo2 + (size_t)T2*T2, gate, bufF);
    k_gate<T2><<<BB, T2>>>(aoq + CC*EE, aok + CC*EE);

    // out = (h_y + y_c*(1+g)) @ C2[c]
    k_gemm<T2, T2, true, true, false, true, false><<<dim3(NN/128, CC, BB), 256>>>(bufD, bufF, C2, nullptr, gate, out);
}

// round 6
// speedup vs baseline: 1.5086x; 1.0017x over previous
#include <cuda_runtime.h>
#include <math.h>
#include <stdint.h>

#define BB 16
#define CC 32
#define NN 512
#define T1 192
#define T2 96
#define L1 97
#define L2 49
#define EE 64

typedef unsigned long long ull;

static constexpr size_t SZ1 = (size_t)BB*CC*NN*T1;
static constexpr size_t SZ2 = (size_t)BB*CC*NN*T2;

// ---------------- scratch ----------------
__device__ float g_bufA[SZ1];
__device__ float g_bufB[SZ1];
__device__ float g_bufC[SZ1];
__device__ float g_bufD[SZ2];
__device__ float g_bufE[SZ2];
__device__ float g_bufF[SZ2];
__device__ float g_Mc[CC*T1*T1];
__device__ float g_Mt[CC*T1*T1];
__device__ float g_D1[CC*T1*T2];
__device__ float g_C2[CC*T2*T2];
__device__ float g_cos1[L1*T1];
__device__ float g_sin1[L1*T1];
__device__ float g_cos2[L2*T2];
__device__ float g_sin2[L2*T2];
__device__ float g_K1[CC*T1];
__device__ float g_K2[CC*T2];
__device__ float g_featP[BB*CC*4*T1];
__device__ float g_gate[BB*T1];

// ---------------- f32x2 helpers ----------------
__device__ __forceinline__ ull pk2(float lo, float hi) {
    ull r; asm("mov.b64 %0, {%1,%2};" : "=l"(r) : "f"(lo), "f"(hi)); return r;
}
__device__ __forceinline__ void fma2(ull& d, ull a, ull b) {
    asm("fma.rn.f32x2 %0, %1, %2, %0;" : "+l"(d) : "l"(a), "l"(b));
}
__device__ __forceinline__ float2 upk2(ull v) {
    float2 f; asm("mov.b64 {%0,%1}, %2;" : "=f"(f.x), "=f"(f.y) : "l"(v)); return f;
}

__device__ __forceinline__ float gelu_t(float x) {
    float x3 = x*x*x;
    return 0.5f*x*(1.0f + tanhf(0.7978845608028654f*(x + 0.044715f*x3)));
}

// ---------------- precompute ----------------
__global__ void k_tables() {
    int i = blockIdx.x*blockDim.x + threadIdx.x;
    if (i < L1*T1) {
        int h = i / T1, t = i % T1;
        int m = (h*t) % T1;
        float a = (float)m * (1.0f/96.0f);
        g_cos1[i] = cospif(a);
        g_sin1[i] = sinpif(a);
    }
    int j = i - L1*T1;
    if (j >= 0 && j < L2*T2) {
        int h = j / T2, t = j % T2;
        int m = (h*t) % T2;
        float a = (float)m * (1.0f/48.0f);
        g_cos2[j] = cospif(a);
        g_sin2[j] = sinpif(a);
    }
}

__global__ void k_buildM(const float* __restrict__ Lc, const float* __restrict__ Lt) {
    int t = blockIdx.x, l = blockIdx.y, tp = threadIdx.x;
    float ac = 0.f, as = 0.f;
    for (int h = 0; h < L1; h++) {
        float w = (h == 0 || h == L1-1) ? (1.0f/T1) : (2.0f/T1);
        float lc = Lc[l*L1+h]*w, lt = Lt[l*L1+h]*w;
        ac = fmaf(lc * g_cos1[h*T1+t], g_cos1[h*T1+tp], ac);
        as = fmaf(lt * g_sin1[h*T1+t], g_sin1[h*T1+tp], as);
    }
    size_t o = ((size_t)l*T1 + t)*T1 + tp;
    g_Mc[o] = ac;
    g_Mt[o] = as;
}

__global__ void k_buildK1(const float* __restrict__ Wr, const float* __restrict__ Wi) {
    int i = blockIdx.x*blockDim.x + threadIdx.x;
    if (i >= CC*T1) return;
    int c = i / T1, d = i % T1;
    float acc = 0.f;
    for (int h = 0; h < L1; h++) {
        float w = (h == 0 || h == L1-1) ? (1.0f/T1) : (2.0f/T1);
        acc += w * (Wr[c*L1+h]*g_cos1[h*T1+d] - Wi[c*L1+h]*g_sin1[h*T1+d]);
    }
    g_K1[i] = acc;
}

// D1[c][t][s2] = sum_s K1[c][(s-t) mod T1] * Wfc[s][s2]
__global__ void k_buildD1(const float* __restrict__ Wfc) {
    __shared__ float kr[T1];
    int t = blockIdx.x, c = blockIdx.y, s2 = threadIdx.x;
    for (int s = s2; s < T1; s += T2) kr[s] = g_K1[c*T1 + s];
    __syncthreads();
    float acc = 0.f;
    int ii = (T1 - t) % T1;
    for (int s = 0; s < T1; s++) {
        acc = fmaf(kr[ii], Wfc[s*T2 + s2], acc);
        ii++; if (ii == T1) ii = 0;
    }
    g_D1[((size_t)c*T1 + t)*T2 + s2] = acc;
}

__global__ void k_buildK2(const float* __restrict__ Wr, const float* __restrict__ Wi) {
    int i = blockIdx.x*blockDim.x + threadIdx.x;
    if (i >= CC*T2) return;
    int c = i / T2, d = i % T2;
    float acc = 0.f;
    for (int h = 0; h < L2; h++) {
        float w = (h == 0 || h == L2-1) ? (1.0f/T2) : (2.0f/T2);
        acc += w * (Wr[c*L2+h]*g_cos2[h*T2+d] - Wi[c*L2+h]*g_sin2[h*T2+d]);
    }
    g_K2[i] = acc;
}
__global__ void k_expand2() {
    size_t i = (size_t)blockIdx.x*blockDim.x + threadIdx.x;
    if (i >= (size_t)CC*T2*T2) return;
    int s = (int)(i % T2);
    int t = (int)((i / T2) % T2);
    int c = (int)(i / ((size_t)T2*T2));
    g_C2[i] = g_K2[c*T2 + ((s - t + T2) % T2)];
}

// ---------------- channel mix (f32x2: pack (u,v)) ----------------
__global__ void __launch_bounds__(256) k_chmix(const float* __restrict__ x,
                                               const float* __restrict__ Gc,
                                               const float* __restrict__ Gt) {
    __shared__ __align__(16) float2 sG[CC*CC];
    int tid = threadIdx.x;
    for (int i = tid; i < CC*CC; i += 256) sG[i] = make_float2(Gc[i], Gt[i]);
    __syncthreads();
    int b = blockIdx.y;
    size_t m = (size_t)blockIdx.x*256 + tid;
    ull a[CC];
#pragma unroll
    for (int l = 0; l < CC; l++) a[l] = 0ull;
    for (int c = 0; c < CC; c++) {
        float xv = x[((size_t)(b*CC + c)*NN)*T1 + m];
        ull xp = pk2(xv, xv);
#pragma unroll
        for (int l = 0; l < CC; l++) fma2(a[l], xp, *(const ull*)&sG[c*CC + l]);
    }
#pragma unroll
    for (int l = 0; l < CC; l++) {
        float2 p = upk2(a[l]);
        g_bufA[((size_t)(b*CC + l)*NN)*T1 + m] = p.x;
        g_bufB[((size_t)(b*CC + l)*NN)*T1 + m] = p.y;
    }
}

// ---------------- mm2: Y = resid + [u|v] @ [Mc[c];Mt[c]]  (K=384 concat, col-half split) ----------------
__global__ void __launch_bounds__(256, 2) k_mm2n(const float* __restrict__ U,
                                                 const float* __restrict__ V,
                                                 const float* __restrict__ resid,
                                                 float* __restrict__ Y) {
    constexpr int TM = 128, RI = 8, SN = 96, NP = 3, KT = 24;
    __shared__ __align__(16) ull xs[16][TM];
    __shared__ __align__(16) float ws[16][SN];
    int tid = threadIdx.x, tx = tid & 15, ty = tid >> 4;
    int c = blockIdx.y, b = blockIdx.z;
    int xt = blockIdx.x >> 1, half = blockIdx.x & 1;
    size_t row0 = (size_t)(b*CC + c)*NN + (size_t)xt*TM;
    int colbase = half*SN;
    const float* WaB = g_Mc + (size_t)c*T1*T1;
    const float* WbB = g_Mt + (size_t)c*T1*T1;

    int xr = tid & 127, xkq = tid >> 7;
    int wk0 = tid / 24, wc0 = (tid % 24)*4;
    int wk1 = (tid + 256) / 24, wc1 = ((tid + 256) % 24)*4;
    bool won = (tid < 128);

    ull acc[RI][NP];
#pragma unroll
    for (int i = 0; i < RI; i++)
#pragma unroll
        for (int j = 0; j < NP; j++) acc[i][j] = 0ull;

    float4 nx0, nx1, nw0, nw1;
    {   // tile 0 (kt=0 -> U / Mc)
        const float* xrow = U + (row0 + xr)*T1;
        nx0 = *(const float4*)&xrow[xkq*4];
        nx1 = *(const float4*)&xrow[(xkq+2)*4];
        nw0 = *(const float4*)&WaB[(size_t)wk0*T1 + colbase + wc0];
        if (won) nw1 = *(const float4*)&WaB[(size_t)wk1*T1 + colbase + wc1];
    }
    for (int kt = 0; kt < KT; kt++) {
        // store staged tile
        xs[xkq*4+0][xr] = pk2(nx0.x, nx0.x);
        xs[xkq*4+1][xr] = pk2(nx0.y, nx0.y);
        xs[xkq*4+2][xr] = pk2(nx0.z, nx0.z);
        xs[xkq*4+3][xr] = pk2(nx0.w, nx0.w);
        xs[(xkq+2)*4+0][xr] = pk2(nx1.x, nx1.x);
        xs[(xkq+2)*4+1][xr] = pk2(nx1.y, nx1.y);
        xs[(xkq+2)*4+2][xr] = pk2(nx1.z, nx1.z);
        xs[(xkq+2)*4+3][xr] = pk2(nx1.w, nx1.w);
        *(float4*)&ws[wk0][wc0] = nw0;
        if (won) *(float4*)&ws[wk1][wc1] = nw1;
        __syncthreads();
        // prefetch next tile
        if (kt + 1 < KT) {
            int ktn = kt + 1;
            const float* Xs = (ktn < 12) ? U : V;
            const float* Ws = (ktn < 12) ? WaB : WbB;
            int ktl = (ktn < 12) ? ktn : ktn - 12;
            const float* xrow = Xs + (row0 + xr)*T1 + ktl*16;
            nx0 = *(const float4*)&xrow[xkq*4];
            nx1 = *(const float4*)&xrow[(xkq+2)*4];
            nw0 = *(const float4*)&Ws[(size_t)(ktl*16 + wk0)*T1 + colbase + wc0];
            if (won) nw1 = *(const float4*)&Ws[(size_t)(ktl*16 + wk1)*T1 + colbase + wc1];
        }
        // compute
#pragma unroll
        for (int k = 0; k < 16; k++) {
            ulonglong2 xA = *(const ulonglong2*)&xs[k][ty*8];
            ulonglong2 xB = *(const ulonglong2*)&xs[k][ty*8+2];
            ulonglong2 xC = *(const ulonglong2*)&xs[k][ty*8+4];
            ulonglong2 xD = *(const ulonglong2*)&xs[k][ty*8+6];
            ull xp[RI] = { xA.x, xA.y, xB.x, xB.y, xC.x, xC.y, xD.x, xD.y };
            ull wp[NP];
#pragma unroll
            for (int j = 0; j < NP; j++) wp[j] = *(const ull*)&ws[k][32*j + 2*tx];
#pragma unroll
            for (int i = 0; i < RI; i++)
#pragma unroll
                for (int j = 0; j < NP; j++) fma2(acc[i][j], xp[i], wp[j]);
        }
        __syncthreads();
    }
#pragma unroll
    for (int i = 0; i < RI; i++)
#pragma unroll
        for (int j = 0; j < NP; j++) {
            size_t gi = (row0 + ty*8 + i)*T1 + colbase + 32*j + 2*tx;
            float2 o = upk2(acc[i][j]);
            float2 r = *(const float2*)&resid[gi];
            o.x += r.x; o.y += r.y;
            *(float2*)&Y[gi] = o;
        }
}

// ---------------- gmlp: Y = (X@W1)*gelu(X@W2), gate-in fused, featP partials ----------------
template<int TD, int NSPLIT, bool G1>
__global__ void __launch_bounds__(256, 1) k_gmlp(const float* __restrict__ X,
                                                 const float* __restrict__ W1,
                                                 const float* __restrict__ W2,
                                                 const float* __restrict__ gate,
                                                 float* __restrict__ Y) {
    constexpr int TM = 128, RI = 8, SN = 96, NP = 3, KT = TD/16;
    __shared__ __align__(16) ull xs[16][TM];
    __shared__ __align__(16) float ws1[16][SN];
    __shared__ __align__(16) float ws2[16][SN];
    __shared__ float sg[TD];
    int tid = threadIdx.x, tx = tid & 15, ty = tid >> 4;
    int c = blockIdx.y, b = blockIdx.z;
    int xt = blockIdx.x / NSPLIT, half = blockIdx.x % NSPLIT;
    size_t row0 = (size_t)(b*CC + c)*NN + (size_t)xt*TM;
    int colbase = half*SN;
    if (G1) {
        for (int t = tid; t < TD; t += 256) sg[t] = 1.0f + gate[b*TD + t];
        __syncthreads();
    }
    int xr = tid & 127, xkq = tid >> 7;
    const float* xrow = X + (row0 + xr)*TD;
    int wk0 = tid / 24, wc0 = (tid % 24)*4;
    int wk1 = (tid + 256) / 24, wc1 = ((tid + 256) % 24)*4;
    bool won = (tid < 128);

    ull a1[RI][NP], a2[RI][NP];
#pragma unroll
    for (int i = 0; i < RI; i++)
#pragma unroll
        for (int j = 0; j < NP; j++) { a1[i][j] = 0ull; a2[i][j] = 0ull; }

    float4 nx0, nx1, nw10, nw11, nw20, nw21;
    {
        nx0 = *(const float4*)&xrow[xkq*4];
        nx1 = *(const float4*)&xrow[(xkq+2)*4];
        nw10 = *(const float4*)&W1[(size_t)wk0*TD + colbase + wc0];
        nw20 = *(const float4*)&W2[(size_t)wk0*TD + colbase + wc0];
        if (won) {
            nw11 = *(const float4*)&W1[(size_t)wk1*TD + colbase + wc1];
            nw21 = *(const float4*)&W2[(size_t)wk1*TD + colbase + wc1];
        }
    }
    for (int kt = 0; kt < KT; kt++) {
        {
            int k0 = kt*16 + xkq*4;
            float4 v = nx0;
            if (G1) { v.x *= sg[k0]; v.y *= sg[k0+1]; v.z *= sg[k0+2]; v.w *= sg[k0+3]; }
            xs[xkq*4+0][xr] = pk2(v.x, v.x);
            xs[xkq*4+1][xr] = pk2(v.y, v.y);
            xs[xkq*4+2][xr] = pk2(v.z, v.z);
            xs[xkq*4+3][xr] = pk2(v.w, v.w);
            int k2 = k0 + 8;
            v = nx1;
            if (G1) { v.x *= sg[k2]; v.y *= sg[k2+1]; v.z *= sg[k2+2]; v.w *= sg[k2+3]; }
            xs[(xkq+2)*4+0][xr] = pk2(v.x, v.x);
            xs[(xkq+2)*4+1][xr] = pk2(v.y, v.y);
            xs[(xkq+2)*4+2][xr] = pk2(v.z, v.z);
            xs[(xkq+2)*4+3][xr] = pk2(v.w, v.w);
            *(float4*)&ws1[wk0][wc0] = nw10;
            *(float4*)&ws2[wk0][wc0] = nw20;
            if (won) { *(float4*)&ws1[wk1][wc1] = nw11; *(float4*)&ws2[wk1][wc1] = nw21; }
        }
        __syncthreads();
        if (kt + 1 < KT) {
            int kn = (kt + 1)*16;
            nx0 = *(const float4*)&xrow[kn + xkq*4];
            nx1 = *(const float4*)&xrow[kn + (xkq+2)*4];
            nw10 = *(const float4*)&W1[(size_t)(kn + wk0)*TD + colbase + wc0];
            nw20 = *(const float4*)&W2[(size_t)(kn + wk0)*TD + colbase + wc0];
            if (won) {
                nw11 = *(const float4*)&W1[(size_t)(kn + wk1)*TD + colbase + wc1];
                nw21 = *(const float4*)&W2[(size_t)(kn + wk1)*TD + colbase + wc1];
            }
        }
#pragma unroll
        for (int k = 0; k < 16; k++) {
            ulonglong2 xA = *(const ulonglong2*)&xs[k][ty*8];
            ulonglong2 xB = *(const ulonglong2*)&xs[k][ty*8+2];
            ulonglong2 xC = *(const ulonglong2*)&xs[k][ty*8+4];
            ulonglong2 xD = *(const ulonglong2*)&xs[k][ty*8+6];
            ull xp[RI] = { xA.x, xA.y, xB.x, xB.y, xC.x, xC.y, xD.x, xD.y };
            ull wp1[NP], wp2[NP];
#pragma unroll
            for (int j = 0; j < NP; j++) {
                wp1[j] = *(const ull*)&ws1[k][32*j + 2*tx];
                wp2[j] = *(const ull*)&ws2[k][32*j + 2*tx];
            }
#pragma unroll
            for (int i = 0; i < RI; i++)
#pragma unroll
                for (int j = 0; j < NP; j++) {
                    fma2(a1[i][j], xp[i], wp1[j]);
                    fma2(a2[i][j], xp[i], wp2[j]);
                }
        }
        __syncthreads();
    }
    float colx[NP], coly[NP];
#pragma unroll
    for (int j = 0; j < NP; j++) { colx[j] = 0.f; coly[j] = 0.f; }
#pragma unroll
    for (int i = 0; i < RI; i++)
#pragma unroll
        for (int j = 0; j < NP; j++) {
            int col = colbase + 32*j + 2*tx;
            float2 p1 = upk2(a1[i][j]);
            float2 p2 = upk2(a2[i][j]);
            float2 o = make_float2(p1.x*gelu_t(p2.x), p1.y*gelu_t(p2.y));
            *(float2*)&Y[(row0 + ty*8 + i)*TD + col] = o;
            colx[j] += o.x; coly[j] += o.y;
        }
    // per-block column partial sums (n-mean fusion), deterministic
#pragma unroll
    for (int j = 0; j < NP; j++) {
        ws1[ty][32*j + 2*tx]     = colx[j];
        ws1[ty][32*j + 2*tx + 1] = coly[j];
    }
    __syncthreads();
    if (tid < SN) {
        float tot = 0.f;
#pragma unroll
        for (int r = 0; r < 16; r++) tot += ws1[r][tid];
        g_featP[((size_t)(b*CC + c)*4 + xt)*TD + colbase + tid] = tot;
    }
}

// ---------------- gemm1: Y = (X1 + sg*X2) @ W[c] [+ bias], SD=96 ----------------
template<int TD, bool BIAS>
__global__ void __launch_bounds__(256, 2) k_gemm1(const float* __restrict__ X1,
                                                  const float* __restrict__ X2,
                                                  const float* __restrict__ W,
                                                  const float* __restrict__ bias,
                                                  const float* __restrict__ gate,
                                                  float* __restrict__ Y) {
    constexpr int TM = 128, RI = 8, SN = 96, NP = 3, KT = TD/16;
    __shared__ __align__(16) ull xs[16][TM];
    __shared__ __align__(16) float ws[16][SN];
    __shared__ float sg[TD];
    int tid = threadIdx.x, tx = tid & 15, ty = tid >> 4;
    int c = blockIdx.y, b = blockIdx.z;
    size_t row0 = (size_t)(b*CC + c)*NN + (size_t)blockIdx.x*TM;
    const float* Wb = W + (size_t)c*TD*SN;
    for (int t = tid; t < TD; t += 256) sg[t] = 1.0f + gate[b*TD + t];
    __syncthreads();

    int xr = tid & 127, xkq = tid >> 7;
    const float* x1row = X1 + (row0 + xr)*TD;
    const float* x2row = X2 + (row0 + xr)*TD;
    int wk0 = tid / 24, wc0 = (tid % 24)*4;
    int wk1 = (tid + 256) / 24, wc1 = ((tid + 256) % 24)*4;
    bool won = (tid < 128);

    ull acc[RI][NP];
#pragma unroll
    for (int i = 0; i < RI; i++)
#pragma unroll
        for (int j = 0; j < NP; j++) acc[i][j] = 0ull;

    float4 na0, na1, nb0, nb1, nw0, nw1;
    {
        na0 = *(const float4*)&x1row[xkq*4];
        na1 = *(const float4*)&x1row[(xkq+2)*4];
        nb0 = *(const float4*)&x2row[xkq*4];
        nb1 = *(const float4*)&x2row[(xkq+2)*4];
        nw0 = *(const float4*)&Wb[(size_t)wk0*SN + wc0];
        if (won) nw1 = *(const float4*)&Wb[(size_t)wk1*SN + wc1];
    }
    for (int kt = 0; kt < KT; kt++) {
        {
            int k0 = kt*16 + xkq*4;
            float4 v = na0, u = nb0;
            v.x = fmaf(u.x, sg[k0],   v.x);
            v.y = fmaf(u.y, sg[k0+1], v.y);
            v.z = fmaf(u.z, sg[k0+2], v.z);
            v.w = fmaf(u.w, sg[k0+3], v.w);
            xs[xkq*4+0][xr] = pk2(v.x, v.x);
            xs[xkq*4+1][xr] = pk2(v.y, v.y);
            xs[xkq*4+2][xr] = pk2(v.z, v.z);
            xs[xkq*4+3][xr] = pk2(v.w, v.w);
            int k2 = k0 + 8;
            v = na1; u = nb1;
            v.x = fmaf(u.x, sg[k2],   v.x);
            v.y = fmaf(u.y, sg[k2+1], v.y);
            v.z = fmaf(u.z, sg[k2+2], v.z);
            v.w = fmaf(u.w, sg[k2+3], v.w);
            xs[(xkq+2)*4+0][xr] = pk2(v.x, v.x);
            xs[(xkq+2)*4+1][xr] = pk2(v.y, v.y);
            xs[(xkq+2)*4+2][xr] = pk2(v.z, v.z);
            xs[(xkq+2)*4+3][xr] = pk2(v.w, v.w);
            *(float4*)&ws[wk0][wc0] = nw0;
            if (won) *(float4*)&ws[wk1][wc1] = nw1;
        }
        __syncthreads();
        if (kt + 1 < KT) {
            int kn = (kt + 1)*16;
            na0 = *(const float4*)&x1row[kn + xkq*4];
            na1 = *(const float4*)&x1row[kn + (xkq+2)*4];
            nb0 = *(const float4*)&x2row[kn + xkq*4];
            nb1 = *(const float4*)&x2row[kn + (xkq+2)*4];
            nw0 = *(const float4*)&Wb[(size_t)(kn + wk0)*SN + wc0];
            if (won) nw1 = *(const float4*)&Wb[(size_t)(kn + wk1)*SN + wc1];
        }
#pragma unroll
        for (int k = 0; k < 16; k++) {
            ulonglong2 xA = *(const ulonglong2*)&xs[k][ty*8];
            ulonglong2 xB = *(const ulonglong2*)&xs[k][ty*8+2];
            ulonglong2 xC = *(const ulonglong2*)&xs[k][ty*8+4];
            ulonglong2 xD = *(const ulonglong2*)&xs[k][ty*8+6];
            ull xp[RI] = { xA.x, xA.y, xB.x, xB.y, xC.x, xC.y, xD.x, xD.y };
            ull wp[NP];
#pragma unroll
            for (int j = 0; j < NP; j++) wp[j] = *(const ull*)&ws[k][32*j + 2*tx];
#pragma unroll
            for (int i = 0; i < RI; i++)
#pragma unroll
                for (int j = 0; j < NP; j++) fma2(acc[i][j], xp[i], wp[j]);
        }
        __syncthreads();
    }
#pragma unroll
    for (int i = 0; i < RI; i++)
#pragma unroll
        for (int j = 0; j < NP; j++) {
            int col = 32*j + 2*tx;
            float2 o = upk2(acc[i][j]);
            if (BIAS) { o.x += bias[col]; o.y += bias[col+1]; }
            *(float2*)&Y[(row0 + ty*8 + i)*SN + col] = o;
        }
}

// ---------------- attn gate ----------------
template<int T>
__global__ void __launch_bounds__(T) k_gate(const float* __restrict__ Wq,
                                            const float* __restrict__ Wk) {
    __shared__ float ks[T][EE];
    int b = blockIdx.x, t = threadIdx.x;
    float q[EE], kk[EE];
#pragma unroll
    for (int e = 0; e < EE; e++) { q[e] = 0.f; kk[e] = 0.f; }
    for (int c = 0; c < CC; c++) {
        float f = 0.f;
#pragma unroll
        for (int p = 0; p < 4; p++) f += g_featP[((size_t)(b*CC + c)*4 + p)*T + t];
        f *= (1.0f/NN);
#pragma unroll
        for (int e = 0; e < EE; e++) {
            q[e]  = fmaf(f, Wq[c*EE + e], q[e]);
            kk[e] = fmaf(f, Wk[c*EE + e], kk[e]);
        }
    }
#pragma unroll
    for (int e = 0; e < EE; e++) ks[t][e] = kk[e];
    __syncthreads();
    float smax = -1e30f, stt = 0.f;
    for (int j = 0; j < T; j++) {
        float d = 0.f;
#pragma unroll
        for (int e = 0; e < EE; e++) d = fmaf(q[e], ks[j][e], d);
        d *= 0.125f;
        if (j == t) stt = d;
        smax = fmaxf(smax, d);
    }
    float ssum = 0.f;
    for (int j = 0; j < T; j++) {
        float d = 0.f;
#pragma unroll
        for (int e = 0; e < EE; e++) d = fmaf(q[e], ks[j][e], d);
        ssum += expf(d*0.125f - smax);
    }
    float p = expf(stt - smax) / ssum;
    g_gate[b*T + t] = gelu_t(p);
}

// ---------------- driver ----------------
extern "C" void kernel_launch(void* const* d_in, const int* in_sizes, int n_in,
                              void* d_out, int out_size) {
    const float* x   = (const float*)d_in[0];
    const float* Gc  = (const float*)d_in[3];
    const float* Lc  = (const float*)d_in[4];
    const float* Gt  = (const float*)d_in[5];
    const float* Lt  = (const float*)d_in[6];
    const float* f1r = (const float*)d_in[7];
    const float* f1i = (const float*)d_in[8];
    const float* f2r = (const float*)d_in[9];
    const float* f2i = (const float*)d_in[10];
    const float* Wfc = (const float*)d_in[11];
    const float* bfc = (const float*)d_in[12];
    const float* mi1 = (const float*)d_in[13];
    const float* mi2 = (const float*)d_in[14];
    const float* mo1 = (const float*)d_in[15];
    const float* mo2 = (const float*)d_in[16];
    const float* aiq = (const float*)d_in[17];
    const float* aik = (const float*)d_in[18];
    const float* aoq = (const float*)d_in[19];
    const float* aok = (const float*)d_in[20];
    float* out = (float*)d_out;

    float *bufA, *bufB, *bufC, *bufD, *bufE, *bufF, *D1, *C2, *gate;
    cudaGetSymbolAddress((void**)&bufA, g_bufA);
    cudaGetSymbolAddress((void**)&bufB, g_bufB);
    cudaGetSymbolAddress((void**)&bufC, g_bufC);
    cudaGetSymbolAddress((void**)&bufD, g_bufD);
    cudaGetSymbolAddress((void**)&bufE, g_bufE);
    cudaGetSymbolAddress((void**)&bufF, g_bufF);
    cudaGetSymbolAddress((void**)&D1,   g_D1);
    cudaGetSymbolAddress((void**)&C2,   g_C2);
    cudaGetSymbolAddress((void**)&gate, g_gate);

    // precompute operator matrices
    k_tables<<<(L1*T1 + L2*T2 + 255)/256, 256>>>();
    k_buildM<<<dim3(T1, CC), T1>>>(Lc, Lt);
    k_buildK1<<<(CC*T1 + 255)/256, 256>>>(f1r, f1i);
    k_buildD1<<<dim3(T1, CC), T2>>>(Wfc);
    k_buildK2<<<(CC*T2 + 255)/256, 256>>>(f2r, f2i);
    k_expand2<<<(int)(((size_t)CC*T2*T2 + 255)/256), 256>>>();

    // freq_attn_in: u = Gc^T x, v = Gt^T x ; xc = x + u@Mc[c] + v@Mt[c]
    k_chmix<<<dim3(NN*T1/256, BB), 256>>>(x, Gc, Gt);
    k_mm2n<<<dim3((NN/128)*2, CC, BB), 256>>>(bufA, bufB, x, bufC);

    // input-side layers (gate fused into next consumer's loads)
    k_gmlp<T1, 2, false><<<dim3((NN/128)*2, CC, BB), 256>>>(bufC, mi1, mi2, nullptr, bufA);
    k_gate<T1><<<BB, T1>>>(aiq, aik);
    k_gmlp<T1, 2, true ><<<dim3((NN/128)*2, CC, BB), 256>>>(bufA, mi1 + (size_t)T1*T1, mi2 + (size_t)T1*T1, gate, bufC);
    k_gate<T1><<<BB, T1>>>(aiq + CC*EE, aik + CC*EE);

    // h_y = (x + xc*(1+g)) @ D1[c] + bfc     (fconv1 + fc_idp fused)
    k_gemm1<T1, true><<<dim3(NN/128, CC, BB), 256>>>(x, bufC, D1, bfc, gate, bufD);

    // output-side layers
    k_gmlp<T2, 1, false><<<dim3(NN/128, CC, BB), 256>>>(bufD, mo1, mo2, nullptr, bufE);
    k_gate<T2><<<BB, T2>>>(aoq, aok);
    k_gmlp<T2, 1, true ><<<dim3(NN/128, CC, BB), 256>>>(bufE, mo1 + (size_t)T2*T2, mo2 + (size_t)T2*T2, gate, bufF);
    k_gate<T2><<<BB, T2>>>(aoq, aok);   // placeholder overwritten below

    // NOTE: correct weights for output layer 1 gate:
    k_gate<T2><<<BB, T2>>>(aoq + CC*EE, aok + CC*EE);

    // out = (h_y + y_c*(1+g)) @ C2[c]
    k_gemm1<T2, false><<<dim3(NN/128, CC, BB), 256>>>(bufD, bufF, C2, nullptr, gate, out);
}

// round 7
// speedup vs baseline: 1.5102x; 1.0010x over previous
#include <cuda_runtime.h>
#include <math.h>
#include <stdint.h>

#define BB 16
#define CC 32
#define NN 512
#define T1 192
#define T2 96
#define L1 97
#define L2 49
#define EE 64

typedef unsigned long long ull;

static constexpr size_t SZ1 = (size_t)BB*CC*NN*T1;
static constexpr size_t SZ2 = (size_t)BB*CC*NN*T2;

// ---------------- scratch ----------------
__device__ float g_bufA[SZ1];
__device__ float g_bufB[SZ1];
__device__ float g_bufC[SZ1];
__device__ float g_bufD[SZ2];
__device__ float g_bufE[SZ2];
__device__ float g_bufF[SZ2];
__device__ float g_Mc[CC*T1*T1];
__device__ float g_Mt[CC*T1*T1];
__device__ float g_D1[CC*T1*T2];
__device__ float g_C2[CC*T2*T2];
__device__ float g_cos1[L1*T1];
__device__ float g_sin1[L1*T1];
__device__ float g_cos2[L2*T2];
__device__ float g_sin2[L2*T2];
__device__ float g_K1[CC*T1];
__device__ float g_K2[CC*T2];
__device__ float g_featP[BB*CC*4*T1];
__device__ float g_gate[BB*T1];

// ---------------- f32x2 helpers ----------------
__device__ __forceinline__ ull pk2(float lo, float hi) {
    ull r; asm("mov.b64 %0, {%1,%2};" : "=l"(r) : "f"(lo), "f"(hi)); return r;
}
__device__ __forceinline__ void fma2(ull& d, ull a, ull b) {
    asm("fma.rn.f32x2 %0, %1, %2, %0;" : "+l"(d) : "l"(a), "l"(b));
}
__device__ __forceinline__ float2 upk2(ull v) {
    float2 f; asm("mov.b64 {%0,%1}, %2;" : "=f"(f.x), "=f"(f.y) : "l"(v)); return f;
}

__device__ __forceinline__ float gelu_t(float x) {
    float x3 = x*x*x;
    return 0.5f*x*(1.0f + tanhf(0.7978845608028654f*(x + 0.044715f*x3)));
}

// ---------------- precompute ----------------
__global__ void k_tables() {
    int i = blockIdx.x*blockDim.x + threadIdx.x;
    if (i < L1*T1) {
        int h = i / T1, t = i % T1;
        int m = (h*t) % T1;
        float a = (float)m * (1.0f/96.0f);
        g_cos1[i] = cospif(a);
        g_sin1[i] = sinpif(a);
    }
    int j = i - L1*T1;
    if (j >= 0 && j < L2*T2) {
        int h = j / T2, t = j % T2;
        int m = (h*t) % T2;
        float a = (float)m * (1.0f/48.0f);
        g_cos2[j] = cospif(a);
        g_sin2[j] = sinpif(a);
    }
}

__global__ void k_buildM(const float* __restrict__ Lc, const float* __restrict__ Lt) {
    int t = blockIdx.x, l = blockIdx.y, tp = threadIdx.x;
    float ac = 0.f, as = 0.f;
    for (int h = 0; h < L1; h++) {
        float w = (h == 0 || h == L1-1) ? (1.0f/T1) : (2.0f/T1);
        float lc = Lc[l*L1+h]*w, lt = Lt[l*L1+h]*w;
        ac = fmaf(lc * g_cos1[h*T1+t], g_cos1[h*T1+tp], ac);
        as = fmaf(lt * g_sin1[h*T1+t], g_sin1[h*T1+tp], as);
    }
    size_t o = ((size_t)l*T1 + t)*T1 + tp;
    g_Mc[o] = ac;
    g_Mt[o] = as;
}

__global__ void k_buildK1(const float* __restrict__ Wr, const float* __restrict__ Wi) {
    int i = blockIdx.x*blockDim.x + threadIdx.x;
    if (i >= CC*T1) return;
    int c = i / T1, d = i % T1;
    float acc = 0.f;
    for (int h = 0; h < L1; h++) {
        float w = (h == 0 || h == L1-1) ? (1.0f/T1) : (2.0f/T1);
        acc += w * (Wr[c*L1+h]*g_cos1[h*T1+d] - Wi[c*L1+h]*g_sin1[h*T1+d]);
    }
    g_K1[i] = acc;
}

// D1[c][t][s2] = sum_s K1[c][(s-t) mod T1] * Wfc[s][s2]
__global__ void k_buildD1(const float* __restrict__ Wfc) {
    __shared__ float kr[T1];
    int t = blockIdx.x, c = blockIdx.y, s2 = threadIdx.x;
    for (int s = s2; s < T1; s += T2) kr[s] = g_K1[c*T1 + s];
    __syncthreads();
    float acc = 0.f;
    int ii = (T1 - t) % T1;
    for (int s = 0; s < T1; s++) {
        acc = fmaf(kr[ii], Wfc[s*T2 + s2], acc);
        ii++; if (ii == T1) ii = 0;
    }
    g_D1[((size_t)c*T1 + t)*T2 + s2] = acc;
}

__global__ void k_buildK2(const float* __restrict__ Wr, const float* __restrict__ Wi) {
    int i = blockIdx.x*blockDim.x + threadIdx.x;
    if (i >= CC*T2) return;
    int c = i / T2, d = i % T2;
    float acc = 0.f;
    for (int h = 0; h < L2; h++) {
        float w = (h == 0 || h == L2-1) ? (1.0f/T2) : (2.0f/T2);
        acc += w * (Wr[c*L2+h]*g_cos2[h*T2+d] - Wi[c*L2+h]*g_sin2[h*T2+d]);
    }
    g_K2[i] = acc;
}
__global__ void k_expand2() {
    size_t i = (size_t)blockIdx.x*blockDim.x + threadIdx.x;
    if (i >= (size_t)CC*T2*T2) return;
    int s = (int)(i % T2);
    int t = (int)((i / T2) % T2);
    int c = (int)(i / ((size_t)T2*T2));
    g_C2[i] = g_K2[c*T2 + ((s - t + T2) % T2)];
}

// ---------------- channel mix (f32x2: pack (u,v)) ----------------
__global__ void __launch_bounds__(256) k_chmix(const float* __restrict__ x,
                                               const float* __restrict__ Gc,
                                               const float* __restrict__ Gt) {
    __shared__ __align__(16) float2 sG[CC*CC];
    int tid = threadIdx.x;
    for (int i = tid; i < CC*CC; i += 256) sG[i] = make_float2(Gc[i], Gt[i]);
    __syncthreads();
    int b = blockIdx.y;
    size_t m = (size_t)blockIdx.x*256 + tid;
    ull a[CC];
#pragma unroll
    for (int l = 0; l < CC; l++) a[l] = 0ull;
    for (int c = 0; c < CC; c++) {
        float xv = x[((size_t)(b*CC + c)*NN)*T1 + m];
        ull xp = pk2(xv, xv);
#pragma unroll
        for (int l = 0; l < CC; l++) fma2(a[l], xp, *(const ull*)&sG[c*CC + l]);
    }
#pragma unroll
    for (int l = 0; l < CC; l++) {
        float2 p = upk2(a[l]);
        g_bufA[((size_t)(b*CC + l)*NN)*T1 + m] = p.x;
        g_bufB[((size_t)(b*CC + l)*NN)*T1 + m] = p.y;
    }
}

// ---------------- mm2: Y = resid + [u|v] @ [Mc[c];Mt[c]]  (K=384 concat, col-half split) ----------------
__global__ void __launch_bounds__(256, 2) k_mm2n(const float* __restrict__ U,
                                                 const float* __restrict__ V,
                                                 const float* __restrict__ resid,
                                                 float* __restrict__ Y) {
    constexpr int TM = 128, RI = 8, SN = 96, NP = 3, KT = 24;
    __shared__ __align__(16) ull xs[16][TM];
    __shared__ __align__(16) float ws[16][SN];
    int tid = threadIdx.x, tx = tid & 15, ty = tid >> 4;
    int c = blockIdx.y, b = blockIdx.z;
    int xt = blockIdx.x >> 1, half = blockIdx.x & 1;
    size_t row0 = (size_t)(b*CC + c)*NN + (size_t)xt*TM;
    int colbase = half*SN;
    const float* WaB = g_Mc + (size_t)c*T1*T1;
    const float* WbB = g_Mt + (size_t)c*T1*T1;

    int xr = tid & 127, xkq = tid >> 7;
    int wk0 = tid / 24, wc0 = (tid % 24)*4;
    int wk1 = (tid + 256) / 24, wc1 = ((tid + 256) % 24)*4;
    bool won = (tid < 128);

    ull acc[RI][NP];
#pragma unroll
    for (int i = 0; i < RI; i++)
#pragma unroll
        for (int j = 0; j < NP; j++) acc[i][j] = 0ull;

    float4 nx0, nx1, nw0, nw1;
    {   // tile 0 (kt=0 -> U / Mc)
        const float* xrow = U + (row0 + xr)*T1;
        nx0 = *(const float4*)&xrow[xkq*4];
        nx1 = *(const float4*)&xrow[(xkq+2)*4];
        nw0 = *(const float4*)&WaB[(size_t)wk0*T1 + colbase + wc0];
        if (won) nw1 = *(const float4*)&WaB[(size_t)wk1*T1 + colbase + wc1];
    }
    for (int kt = 0; kt < KT; kt++) {
        // store staged tile
        xs[xkq*4+0][xr] = pk2(nx0.x, nx0.x);
        xs[xkq*4+1][xr] = pk2(nx0.y, nx0.y);
        xs[xkq*4+2][xr] = pk2(nx0.z, nx0.z);
        xs[xkq*4+3][xr] = pk2(nx0.w, nx0.w);
        xs[(xkq+2)*4+0][xr] = pk2(nx1.x, nx1.x);
        xs[(xkq+2)*4+1][xr] = pk2(nx1.y, nx1.y);
        xs[(xkq+2)*4+2][xr] = pk2(nx1.z, nx1.z);
        xs[(xkq+2)*4+3][xr] = pk2(nx1.w, nx1.w);
        *(float4*)&ws[wk0][wc0] = nw0;
        if (won) *(float4*)&ws[wk1][wc1] = nw1;
        __syncthreads();
        // prefetch next tile
        if (kt + 1 < KT) {
            int ktn = kt + 1;
            const float* Xs = (ktn < 12) ? U : V;
            const float* Ws = (ktn < 12) ? WaB : WbB;
            int ktl = (ktn < 12) ? ktn : ktn - 12;
            const float* xrow = Xs + (row0 + xr)*T1 + ktl*16;
            nx0 = *(const float4*)&xrow[xkq*4];
            nx1 = *(const float4*)&xrow[(xkq+2)*4];
            nw0 = *(const float4*)&Ws[(size_t)(ktl*16 + wk0)*T1 + colbase + wc0];
            if (won) nw1 = *(const float4*)&Ws[(size_t)(ktl*16 + wk1)*T1 + colbase + wc1];
        }
        // compute
#pragma unroll
        for (int k = 0; k < 16; k++) {
            ulonglong2 xA = *(const ulonglong2*)&xs[k][ty*8];
            ulonglong2 xB = *(const ulonglong2*)&xs[k][ty*8+2];
            ulonglong2 xC = *(const ulonglong2*)&xs[k][ty*8+4];
            ulonglong2 xD = *(const ulonglong2*)&xs[k][ty*8+6];
            ull xp[RI] = { xA.x, xA.y, xB.x, xB.y, xC.x, xC.y, xD.x, xD.y };
            ull wp[NP];
#pragma unroll
            for (int j = 0; j < NP; j++) wp[j] = *(const ull*)&ws[k][32*j + 2*tx];
#pragma unroll
            for (int i = 0; i < RI; i++)
#pragma unroll
                for (int j = 0; j < NP; j++) fma2(acc[i][j], xp[i], wp[j]);
        }
        __syncthreads();
    }
#pragma unroll
    for (int i = 0; i < RI; i++)
#pragma unroll
        for (int j = 0; j < NP; j++) {
            size_t gi = (row0 + ty*8 + i)*T1 + colbase + 32*j + 2*tx;
            float2 o = upk2(acc[i][j]);
            float2 r = *(const float2*)&resid[gi];
            o.x += r.x; o.y += r.y;
            *(float2*)&Y[gi] = o;
        }
}

// ---------------- gmlp: Y = (X@W1)*gelu(X@W2), gate-in fused, featP partials ----------------
template<int TD, int NSPLIT, bool G1>
__global__ void __launch_bounds__(256, 1) k_gmlp(const float* __restrict__ X,
                                                 const float* __restrict__ W1,
                                                 const float* __restrict__ W2,
                                                 const float* __restrict__ gate,
                                                 float* __restrict__ Y) {
    constexpr int TM = 128, RI = 8, SN = 96, NP = 3, KT = TD/16;
    __shared__ __align__(16) ull xs[16][TM];
    __shared__ __align__(16) float ws1[16][SN];
    __shared__ __align__(16) float ws2[16][SN];
    __shared__ float sg[TD];
    int tid = threadIdx.x, tx = tid & 15, ty = tid >> 4;
    int c = blockIdx.y, b = blockIdx.z;
    int xt = blockIdx.x / NSPLIT, half = blockIdx.x % NSPLIT;
    size_t row0 = (size_t)(b*CC + c)*NN + (size_t)xt*TM;
    int colbase = half*SN;
    if (G1) {
        for (int t = tid; t < TD; t += 256) sg[t] = 1.0f + gate[b*TD + t];
        __syncthreads();
    }
    int xr = tid & 127, xkq = tid >> 7;
    const float* xrow = X + (row0 + xr)*TD;
    int wk0 = tid / 24, wc0 = (tid % 24)*4;
    int wk1 = (tid + 256) / 24, wc1 = ((tid + 256) % 24)*4;
    bool won = (tid < 128);

    ull a1[RI][NP], a2[RI][NP];
#pragma unroll
    for (int i = 0; i < RI; i++)
#pragma unroll
        for (int j = 0; j < NP; j++) { a1[i][j] = 0ull; a2[i][j] = 0ull; }

    float4 nx0, nx1, nw10, nw11, nw20, nw21;
    {
        nx0 = *(const float4*)&xrow[xkq*4];
        nx1 = *(const float4*)&xrow[(xkq+2)*4];
        nw10 = *(const float4*)&W1[(size_t)wk0*TD + colbase + wc0];
        nw20 = *(const float4*)&W2[(size_t)wk0*TD + colbase + wc0];
        if (won) {
            nw11 = *(const float4*)&W1[(size_t)wk1*TD + colbase + wc1];
            nw21 = *(const float4*)&W2[(size_t)wk1*TD + colbase + wc1];
        }
    }
    for (int kt = 0; kt < KT; kt++) {
        {
            int k0 = kt*16 + xkq*4;
            float4 v = nx0;
            if (G1) { v.x *= sg[k0]; v.y *= sg[k0+1]; v.z *= sg[k0+2]; v.w *= sg[k0+3]; }
            xs[xkq*4+0][xr] = pk2(v.x, v.x);
            xs[xkq*4+1][xr] = pk2(v.y, v.y);
            xs[xkq*4+2][xr] = pk2(v.z, v.z);
            xs[xkq*4+3][xr] = pk2(v.w, v.w);
            int k2 = k0 + 8;
            v = nx1;
            if (G1) { v.x *= sg[k2]; v.y *= sg[k2+1]; v.z *= sg[k2+2]; v.w *= sg[k2+3]; }
            xs[(xkq+2)*4+0][xr] = pk2(v.x, v.x);
            xs[(xkq+2)*4+1][xr] = pk2(v.y, v.y);
            xs[(xkq+2)*4+2][xr] = pk2(v.z, v.z);
            xs[(xkq+2)*4+3][xr] = pk2(v.w, v.w);
            *(float4*)&ws1[wk0][wc0] = nw10;
            *(float4*)&ws2[wk0][wc0] = nw20;
            if (won) { *(float4*)&ws1[wk1][wc1] = nw11; *(float4*)&ws2[wk1][wc1] = nw21; }
        }
        __syncthreads();
        if (kt + 1 < KT) {
            int kn = (kt + 1)*16;
            nx0 = *(const float4*)&xrow[kn + xkq*4];
            nx1 = *(const float4*)&xrow[kn + (xkq+2)*4];
            nw10 = *(const float4*)&W1[(size_t)(kn + wk0)*TD + colbase + wc0];
            nw20 = *(const float4*)&W2[(size_t)(kn + wk0)*TD + colbase + wc0];
            if (won) {
                nw11 = *(const float4*)&W1[(size_t)(kn + wk1)*TD + colbase + wc1];
                nw21 = *(const float4*)&W2[(size_t)(kn + wk1)*TD + colbase + wc1];
            }
        }
#pragma unroll
        for (int k = 0; k < 16; k++) {
            ulonglong2 xA = *(const ulonglong2*)&xs[k][ty*8];
            ulonglong2 xB = *(const ulonglong2*)&xs[k][ty*8+2];
            ulonglong2 xC = *(const ulonglong2*)&xs[k][ty*8+4];
            ulonglong2 xD = *(const ulonglong2*)&xs[k][ty*8+6];
            ull xp[RI] = { xA.x, xA.y, xB.x, xB.y, xC.x, xC.y, xD.x, xD.y };
            ull wp1[NP], wp2[NP];
#pragma unroll
            for (int j = 0; j < NP; j++) {
                wp1[j] = *(const ull*)&ws1[k][32*j + 2*tx];
                wp2[j] = *(const ull*)&ws2[k][32*j + 2*tx];
            }
#pragma unroll
            for (int i = 0; i < RI; i++)
#pragma unroll
                for (int j = 0; j < NP; j++) {
                    fma2(a1[i][j], xp[i], wp1[j]);
                    fma2(a2[i][j], xp[i], wp2[j]);
                }
        }
        __syncthreads();
    }
    float colx[NP], coly[NP];
#pragma unroll
    for (int j = 0; j < NP; j++) { colx[j] = 0.f; coly[j] = 0.f; }
#pragma unroll
    for (int i = 0; i < RI; i++)
#pragma unroll
        for (int j = 0; j < NP; j++) {
            int col = colbase + 32*j + 2*tx;
            float2 p1 = upk2(a1[i][j]);
            float2 p2 = upk2(a2[i][j]);
            float2 o = make_float2(p1.x*gelu_t(p2.x), p1.y*gelu_t(p2.y));
            *(float2*)&Y[(row0 + ty*8 + i)*TD + col] = o;
            colx[j] += o.x; coly[j] += o.y;
        }
    // per-block column partial sums (n-mean fusion), deterministic
#pragma unroll
    for (int j = 0; j < NP; j++) {
        ws1[ty][32*j + 2*tx]     = colx[j];
        ws1[ty][32*j + 2*tx + 1] = coly[j];
    }
    __syncthreads();
    if (tid < SN) {
        float tot = 0.f;
#pragma unroll
        for (int r = 0; r < 16; r++) tot += ws1[r][tid];
        g_featP[((size_t)(b*CC + c)*4 + xt)*TD + colbase + tid] = tot;
    }
}

// ---------------- gemm1: Y = (X1 + sg*X2) @ W[c] [+ bias], SD=96 ----------------
template<int TD, bool BIAS>
__global__ void __launch_bounds__(256, 2) k_gemm1(const float* __restrict__ X1,
                                                  const float* __restrict__ X2,
                                                  const float* __restrict__ W,
                                                  const float* __restrict__ bias,
                                                  const float* __restrict__ gate,
                                                  float* __restrict__ Y) {
    constexpr int TM = 128, RI = 8, SN = 96, NP = 3, KT = TD/16;
    __shared__ __align__(16) ull xs[16][TM];
    __shared__ __align__(16) float ws[16][SN];
    __shared__ float sg[TD];
    int tid = threadIdx.x, tx = tid & 15, ty = tid >> 4;
    int c = blockIdx.y, b = blockIdx.z;
    size_t row0 = (size_t)(b*CC + c)*NN + (size_t)blockIdx.x*TM;
    const float* Wb = W + (size_t)c*TD*SN;
    for (int t = tid; t < TD; t += 256) sg[t] = 1.0f + gate[b*TD + t];
    __syncthreads();

    int xr = tid & 127, xkq = tid >> 7;
    const float* x1row = X1 + (row0 + xr)*TD;
    const float* x2row = X2 + (row0 + xr)*TD;
    int wk0 = tid / 24, wc0 = (tid % 24)*4;
    int wk1 = (tid + 256) / 24, wc1 = ((tid + 256) % 24)*4;
    bool won = (tid < 128);

    ull acc[RI][NP];
#pragma unroll
    for (int i = 0; i < RI; i++)
#pragma unroll
        for (int j = 0; j < NP; j++) acc[i][j] = 0ull;

    float4 na0, na1, nb0, nb1, nw0, nw1;
    {
        na0 = *(const float4*)&x1row[xkq*4];
        na1 = *(const float4*)&x1row[(xkq+2)*4];
        nb0 = *(const float4*)&x2row[xkq*4];
        nb1 = *(const float4*)&x2row[(xkq+2)*4];
        nw0 = *(const float4*)&Wb[(size_t)wk0*SN + wc0];
        if (won) nw1 = *(const float4*)&Wb[(size_t)wk1*SN + wc1];
    }
    for (int kt = 0; kt < KT; kt++) {
        {
            int k0 = kt*16 + xkq*4;
            float4 v = na0, u = nb0;
            v.x = fmaf(u.x, sg[k0],   v.x);
            v.y = fmaf(u.y, sg[k0+1], v.y);
            v.z = fmaf(u.z, sg[k0+2], v.z);
            v.w = fmaf(u.w, sg[k0+3], v.w);
            xs[xkq*4+0][xr] = pk2(v.x, v.x);
            xs[xkq*4+1][xr] = pk2(v.y, v.y);
            xs[xkq*4+2][xr] = pk2(v.z, v.z);
            xs[xkq*4+3][xr] = pk2(v.w, v.w);
            int k2 = k0 + 8;
            v = na1; u = nb1;
            v.x = fmaf(u.x, sg[k2],   v.x);
            v.y = fmaf(u.y, sg[k2+1], v.y);
            v.z = fmaf(u.z, sg[k2+2], v.z);
            v.w = fmaf(u.w, sg[k2+3], v.w);
            xs[(xkq+2)*4+0][xr] = pk2(v.x, v.x);
            xs[(xkq+2)*4+1][xr] = pk2(v.y, v.y);
            xs[(xkq+2)*4+2][xr] = pk2(v.z, v.z);
            xs[(xkq+2)*4+3][xr] = pk2(v.w, v.w);
            *(float4*)&ws[wk0][wc0] = nw0;
            if (won) *(float4*)&ws[wk1][wc1] = nw1;
        }
        __syncthreads();
        if (kt + 1 < KT) {
            int kn = (kt + 1)*16;
            na0 = *(const float4*)&x1row[kn + xkq*4];
            na1 = *(const float4*)&x1row[kn + (xkq+2)*4];
            nb0 = *(const float4*)&x2row[kn + xkq*4];
            nb1 = *(const float4*)&x2row[kn + (xkq+2)*4];
            nw0 = *(const float4*)&Wb[(size_t)(kn + wk0)*SN + wc0];
            if (won) nw1 = *(const float4*)&Wb[(size_t)(kn + wk1)*SN + wc1];
        }
#pragma unroll
        for (int k = 0; k < 16; k++) {
            ulonglong2 xA = *(const ulonglong2*)&xs[k][ty*8];
            ulonglong2 xB = *(const ulonglong2*)&xs[k][ty*8+2];
            ulonglong2 xC = *(const ulonglong2*)&xs[k][ty*8+4];
            ulonglong2 xD = *(const ulonglong2*)&xs[k][ty*8+6];
            ull xp[RI] = { xA.x, xA.y, xB.x, xB.y, xC.x, xC.y, xD.x, xD.y };
            ull wp[NP];
#pragma unroll
            for (int j = 0; j < NP; j++) wp[j] = *(const ull*)&ws[k][32*j + 2*tx];
#pragma unroll
            for (int i = 0; i < RI; i++)
#pragma unroll
                for (int j = 0; j < NP; j++) fma2(acc[i][j], xp[i], wp[j]);
        }
        __syncthreads();
    }
#pragma unroll
    for (int i = 0; i < RI; i++)
#pragma unroll
        for (int j = 0; j < NP; j++) {
            int col = 32*j + 2*tx;
            float2 o = upk2(acc[i][j]);
            if (BIAS) { o.x += bias[col]; o.y += bias[col+1]; }
            *(float2*)&Y[(row0 + ty*8 + i)*SN + col] = o;
        }
}

// ---------------- attn gate ----------------
template<int T>
__global__ void __launch_bounds__(T) k_gate(const float* __restrict__ Wq,
                                            const float* __restrict__ Wk) {
    __shared__ float ks[T][EE];
    int b = blockIdx.x, t = threadIdx.x;
    float q[EE], kk[EE];
#pragma unroll
    for (int e = 0; e < EE; e++) { q[e] = 0.f; kk[e] = 0.f; }
    for (int c = 0; c < CC; c++) {
        float f = 0.f;
#pragma unroll
        for (int p = 0; p < 4; p++) f += g_featP[((size_t)(b*CC + c)*4 + p)*T + t];
        f *= (1.0f/NN);
#pragma unroll
        for (int e = 0; e < EE; e++) {
            q[e]  = fmaf(f, Wq[c*EE + e], q[e]);
            kk[e] = fmaf(f, Wk[c*EE + e], kk[e]);
        }
    }
#pragma unroll
    for (int e = 0; e < EE; e++) ks[t][e] = kk[e];
    __syncthreads();
    float smax = -1e30f, stt = 0.f;
    for (int j = 0; j < T; j++) {
        float d = 0.f;
#pragma unroll
        for (int e = 0; e < EE; e++) d = fmaf(q[e], ks[j][e], d);
        d *= 0.125f;
        if (j == t) stt = d;
        smax = fmaxf(smax, d);
    }
    float ssum = 0.f;
    for (int j = 0; j < T; j++) {
        float d = 0.f;
#pragma unroll
        for (int e = 0; e < EE; e++) d = fmaf(q[e], ks[j][e], d);
        ssum += expf(d*0.125f - smax);
    }
    float p = expf(stt - smax) / ssum;
    g_gate[b*T + t] = gelu_t(p);
}

// ---------------- driver ----------------
extern "C" void kernel_launch(void* const* d_in, const int* in_sizes, int n_in,
                              void* d_out, int out_size) {
    const float* x   = (const float*)d_in[0];
    const float* Gc  = (const float*)d_in[3];
    const float* Lc  = (const float*)d_in[4];
    const float* Gt  = (const float*)d_in[5];
    const float* Lt  = (const float*)d_in[6];
    const float* f1r = (const float*)d_in[7];
    const float* f1i = (const float*)d_in[8];
    const float* f2r = (const float*)d_in[9];
    const float* f2i = (const float*)d_in[10];
    const float* Wfc = (const float*)d_in[11];
    const float* bfc = (const float*)d_in[12];
    const float* mi1 = (const float*)d_in[13];
    const float* mi2 = (const float*)d_in[14];
    const float* mo1 = (const float*)d_in[15];
    const float* mo2 = (const float*)d_in[16];
    const float* aiq = (const float*)d_in[17];
    const float* aik = (const float*)d_in[18];
    const float* aoq = (const float*)d_in[19];
    const float* aok = (const float*)d_in[20];
    float* out = (float*)d_out;

    float *bufA, *bufB, *bufC, *bufD, *bufE, *bufF, *D1, *C2, *gate;
    cudaGetSymbolAddress((void**)&bufA, g_bufA);
    cudaGetSymbolAddress((void**)&bufB, g_bufB);
    cudaGetSymbolAddress((void**)&bufC, g_bufC);
    cudaGetSymbolAddress((void**)&bufD, g_bufD);
    cudaGetSymbolAddress((void**)&bufE, g_bufE);
    cudaGetSymbolAddress((void**)&bufF, g_bufF);
    cudaGetSymbolAddress((void**)&D1,   g_D1);
    cudaGetSymbolAddress((void**)&C2,   g_C2);
    cudaGetSymbolAddress((void**)&gate, g_gate);

    // precompute operator matrices
    k_tables<<<(L1*T1 + L2*T2 + 255)/256, 256>>>();
    k_buildM<<<dim3(T1, CC), T1>>>(Lc, Lt);
    k_buildK1<<<(CC*T1 + 255)/256, 256>>>(f1r, f1i);
    k_buildD1<<<dim3(T1, CC), T2>>>(Wfc);
    k_buildK2<<<(CC*T2 + 255)/256, 256>>>(f2r, f2i);
    k_expand2<<<(int)(((size_t)CC*T2*T2 + 255)/256), 256>>>();

    // freq_attn_in: u = Gc^T x, v = Gt^T x ; xc = x + u@Mc[c] + v@Mt[c]
    k_chmix<<<dim3(NN*T1/256, BB), 256>>>(x, Gc, Gt);
    k_mm2n<<<dim3((NN/128)*2, CC, BB), 256>>>(bufA, bufB, x, bufC);

    // input-side layers (gate fused into next consumer's loads)
    k_gmlp<T1, 2, false><<<dim3((NN/128)*2, CC, BB), 256>>>(bufC, mi1, mi2, nullptr, bufA);
    k_gate<T1><<<BB, T1>>>(aiq, aik);
    k_gmlp<T1, 2, true ><<<dim3((NN/128)*2, CC, BB), 256>>>(bufA, mi1 + (size_t)T1*T1, mi2 + (size_t)T1*T1, gate, bufC);
    k_gate<T1><<<BB, T1>>>(aiq + CC*EE, aik + CC*EE);

    // h_y = (x + xc*(1+g)) @ D1[c] + bfc     (fconv1 + fc_idp fused)
    k_gemm1<T1, true><<<dim3(NN/128, CC, BB), 256>>>(x, bufC, D1, bfc, gate, bufD);

    // output-side layers
    k_gmlp<T2, 1, false><<<dim3(NN/128, CC, BB), 256>>>(bufD, mo1, mo2, nullptr, bufE);
    k_gate<T2><<<BB, T2>>>(aoq, aok);
    k_gmlp<T2, 1, true ><<<dim3(NN/128, CC, BB), 256>>>(bufE, mo1 + (size_t)T2*T2, mo2 + (size_t)T2*T2, gate, bufF);
    k_gate<T2><<<BB, T2>>>(aoq, aok);   // placeholder overwritten below

    // NOTE: correct weights for output layer 1 gate:
    k_gate<T2><<<BB, T2>>>(aoq + CC*EE, aok + CC*EE);

    // out = (h_y + y_c*(1+g)) @ C2[c]
    k_gemm1<T2, false><<<dim3(NN/128, CC, BB), 256>>>(bufD, bufF, C2, nullptr, gate, out);
}

// round 9
// speedup vs baseline: 2.0093x; 1.3305x over previous
#include <cuda_runtime.h>
#include <cuda_bf16.h>
#include <math.h>
#include <stdint.h>

#define BB 16
#define CC 32
#define NN 512
#define T1 192
#define T2 96
#define L1 97
#define L2 49
#define EE 64

typedef unsigned long long ull;

static constexpr size_t SZ1 = (size_t)BB*CC*NN*T1;
static constexpr size_t SZ2 = (size_t)BB*CC*NN*T2;

// ---------------- scratch ----------------
__device__ float g_bufA[SZ1];
__device__ float g_bufB[SZ1];
__device__ float g_bufC[SZ1];
__device__ float g_bufD[SZ2];
__device__ float g_bufE[SZ2];
__device__ float g_bufF[SZ2];
__device__ float g_Mc[CC*T1*T1];
__device__ float g_Mt[CC*T1*T1];
__device__ float g_D1[CC*T1*T2];
__device__ float g_C2[CC*T2*T2];
__device__ float g_cos1[L1*T1];
__device__ float g_sin1[L1*T1];
__device__ float g_cos2[L2*T2];
__device__ float g_sin2[L2*T2];
__device__ float g_K1[CC*T1];
__device__ float g_K2[CC*T2];
__device__ float g_feat[BB*CC*T1];
__device__ float g_gate[BB*T1];
// pre-split bf16 weights, layout [layer][half][mat: W1h,W1l,W2h,W2l][n=96][KTOT]
__device__ __nv_bfloat16 g_Bin[2*2*4*96*T1];   // 294912
__device__ __nv_bfloat16 g_Bout[2*1*4*96*T2];  // 73728

// ---------------- f32x2 helpers (fp32 kernels) ----------------
__device__ __forceinline__ ull pk2(float lo, float hi) {
    ull r; asm("mov.b64 %0, {%1,%2};" : "=l"(r) : "f"(lo), "f"(hi)); return r;
}
__device__ __forceinline__ void fma2(ull& d, ull a, ull b) {
    asm("fma.rn.f32x2 %0, %1, %2, %0;" : "+l"(d) : "l"(a), "l"(b));
}
__device__ __forceinline__ float2 upk2(ull v) {
    float2 f; asm("mov.b64 {%0,%1}, %2;" : "=f"(f.x), "=f"(f.y) : "l"(v)); return f;
}

__device__ __forceinline__ float gelu_t(float x) {
    float x3 = x*x*x;
    return 0.5f*x*(1.0f + tanhf(0.7978845608028654f*(x + 0.044715f*x3)));
}

__device__ __forceinline__ uint32_t smem_u32(const void* p) {
    uint32_t a;
    asm("{ .reg .u64 t; cvta.to.shared.u64 t, %1; cvt.u32.u64 %0, t; }" : "=r"(a) : "l"(p));
    return a;
}

// ---------------- mma.sync helpers (base-arch tensor path) ----------------
#define LDM4(r, addr) \
    asm volatile("ldmatrix.sync.aligned.m8n8.x4.shared.b16 {%0,%1,%2,%3}, [%4];" \
        : "=r"((r)[0]), "=r"((r)[1]), "=r"((r)[2]), "=r"((r)[3]) : "r"(addr))

#define MMA_BF16(c, a, b0, b1) \
    asm volatile("mma.sync.aligned.m16n8k16.row.col.f32.bf16.bf16.f32 " \
        "{%0,%1,%2,%3},{%4,%5,%6,%7},{%8,%9},{%0,%1,%2,%3};" \
        : "+f"((c)[0]), "+f"((c)[1]), "+f"((c)[2]), "+f"((c)[3]) \
        : "r"((a)[0]), "r"((a)[1]), "r"((a)[2]), "r"((a)[3]), "r"(b0), "r"(b1))

// ---------------- precompute ----------------
__global__ void k_tables() {
    int i = blockIdx.x*blockDim.x + threadIdx.x;
    if (i < L1*T1) {
        int h = i / T1, t = i % T1;
        int m = (h*t) % T1;
        float a = (float)m * (1.0f/96.0f);
        g_cos1[i] = cospif(a);
        g_sin1[i] = sinpif(a);
    }
    int j = i - L1*T1;
    if (j >= 0 && j < L2*T2) {
        int h = j / T2, t = j % T2;
        int m = (h*t) % T2;
        float a = (float)m * (1.0f/48.0f);
        g_cos2[j] = cospif(a);
        g_sin2[j] = sinpif(a);
    }
}

__global__ void k_buildM(const float* __restrict__ Lc, const float* __restrict__ Lt) {
    int t = blockIdx.x, l = blockIdx.y, tp = threadIdx.x;
    float ac = 0.f, as = 0.f;
    for (int h = 0; h < L1; h++) {
        float w = (h == 0 || h == L1-1) ? (1.0f/T1) : (2.0f/T1);
        float lc = Lc[l*L1+h]*w, lt = Lt[l*L1+h]*w;
        ac = fmaf(lc * g_cos1[h*T1+t], g_cos1[h*T1+tp], ac);
        as = fmaf(lt * g_sin1[h*T1+t], g_sin1[h*T1+tp], as);
    }
    size_t o = ((size_t)l*T1 + t)*T1 + tp;
    g_Mc[o] = ac;
    g_Mt[o] = as;
}

__global__ void k_buildK1(const float* __restrict__ Wr, const float* __restrict__ Wi) {
    int i = blockIdx.x*blockDim.x + threadIdx.x;
    if (i >= CC*T1) return;
    int c = i / T1, d = i % T1;
    float acc = 0.f;
    for (int h = 0; h < L1; h++) {
        float w = (h == 0 || h == L1-1) ? (1.0f/T1) : (2.0f/T1);
        acc += w * (Wr[c*L1+h]*g_cos1[h*T1+d] - Wi[c*L1+h]*g_sin1[h*T1+d]);
    }
    g_K1[i] = acc;
}

__global__ void k_buildD1(const float* __restrict__ Wfc) {
    __shared__ float kr[T1];
    int t = blockIdx.x, c = blockIdx.y, s2 = threadIdx.x;
    for (int s = s2; s < T1; s += T2) kr[s] = g_K1[c*T1 + s];
    __syncthreads();
    float acc = 0.f;
    int ii = (T1 - t) % T1;
    for (int s = 0; s < T1; s++) {
        acc = fmaf(kr[ii], Wfc[s*T2 + s2], acc);
        ii++; if (ii == T1) ii = 0;
    }
    g_D1[((size_t)c*T1 + t)*T2 + s2] = acc;
}

__global__ void k_buildK2(const float* __restrict__ Wr, const float* __restrict__ Wi) {
    int i = blockIdx.x*blockDim.x + threadIdx.x;
    if (i >= CC*T2) return;
    int c = i / T2, d = i % T2;
    float acc = 0.f;
    for (int h = 0; h < L2; h++) {
        float w = (h == 0 || h == L2-1) ? (1.0f/T2) : (2.0f/T2);
        acc += w * (Wr[c*L2+h]*g_cos2[h*T2+d] - Wi[c*L2+h]*g_sin2[h*T2+d]);
    }
    g_K2[i] = acc;
}
__global__ void k_expand2() {
    size_t i = (size_t)blockIdx.x*blockDim.x + threadIdx.x;
    if (i >= (size_t)CC*T2*T2) return;
    int s = (int)(i % T2);
    int t = (int)((i / T2) % T2);
    int c = (int)(i / ((size_t)T2*T2));
    g_C2[i] = g_K2[c*T2 + ((s - t + T2) % T2)];
}

// split gmlp weights into hi/lo bf16, transposed to [n][k]
// dst layout: [layer][half][mat: W1h,W1l,W2h,W2l][n=96][KTOT]
template<int KTOT, int HALVES>
__global__ void k_splitW(const float* __restrict__ W1, const float* __restrict__ W2,
                         __nv_bfloat16* __restrict__ dst) {
    int total = 2*HALVES*4*96*KTOT;
    int idx = blockIdx.x*blockDim.x + threadIdx.x;
    if (idx >= total) return;
    int k     = idx % KTOT;
    int n     = (idx / KTOT) % 96;
    int mat   = (idx / (KTOT*96)) % 4;
    int half  = (idx / (KTOT*96*4)) % HALVES;
    int layer = idx / (KTOT*96*4*HALVES);
    const float* src = (mat < 2) ? W1 : W2;
    int s = half*96 + n;
    float w = src[(size_t)layer*KTOT*KTOT + (size_t)k*KTOT + s];
    __nv_bfloat16 hi = __float2bfloat16(w);
    __nv_bfloat16 v = (mat & 1) ? __float2bfloat16(w - __bfloat162float(hi)) : hi;
    dst[idx] = v;
}

// ---------------- channel mix ----------------
__global__ void __launch_bounds__(256) k_chmix(const float* __restrict__ x,
                                               const float* __restrict__ Gc,
                                               const float* __restrict__ Gt) {
    __shared__ __align__(16) float2 sG[CC*CC];
    int tid = threadIdx.x;
    for (int i = tid; i < CC*CC; i += 256) sG[i] = make_float2(Gc[i], Gt[i]);
    __syncthreads();
    int b = blockIdx.y;
    size_t m = (size_t)blockIdx.x*256 + tid;
    ull a[CC];
#pragma unroll
    for (int l = 0; l < CC; l++) a[l] = 0ull;
    for (int c = 0; c < CC; c++) {
        float xv = x[((size_t)(b*CC + c)*NN)*T1 + m];
        ull xp = pk2(xv, xv);
#pragma unroll
        for (int l = 0; l < CC; l++) fma2(a[l], xp, *(const ull*)&sG[c*CC + l]);
    }
#pragma unroll
    for (int l = 0; l < CC; l++) {
        float2 p = upk2(a[l]);
        g_bufA[((size_t)(b*CC + l)*NN)*T1 + m] = p.x;
        g_bufB[((size_t)(b*CC + l)*NN)*T1 + m] = p.y;
    }
}

// ---------------- mm2: Y = resid + [u|v] @ [Mc[c];Mt[c]] ----------------
__global__ void __launch_bounds__(256, 2) k_mm2n(const float* __restrict__ U,
                                                 const float* __restrict__ V,
                                                 const float* __restrict__ resid,
                                                 float* __restrict__ Y) {
    constexpr int TM = 128, RI = 8, SN = 96, NP = 3, KT = 24;
    __shared__ __align__(16) ull xs[16][TM];
    __shared__ __align__(16) float ws[16][SN];
    int tid = threadIdx.x, tx = tid & 15, ty = tid >> 4;
    int c = blockIdx.y, b = blockIdx.z;
    int xt = blockIdx.x >> 1, half = blockIdx.x & 1;
    size_t row0 = (size_t)(b*CC + c)*NN + (size_t)xt*TM;
    int colbase = half*SN;
    const float* WaB = g_Mc + (size_t)c*T1*T1;
    const float* WbB = g_Mt + (size_t)c*T1*T1;

    int xr = tid & 127, xkq = tid >> 7;
    int wk0 = tid / 24, wc0 = (tid % 24)*4;
    int wk1 = (tid + 256) / 24, wc1 = ((tid + 256) % 24)*4;
    bool won = (tid < 128);

    ull acc[RI][NP];
#pragma unroll
    for (int i = 0; i < RI; i++)
#pragma unroll
        for (int j = 0; j < NP; j++) acc[i][j] = 0ull;

    float4 nx0, nx1, nw0, nw1;
    {
        const float* xrow = U + (row0 + xr)*T1;
        nx0 = *(const float4*)&xrow[xkq*4];
        nx1 = *(const float4*)&xrow[(xkq+2)*4];
        nw0 = *(const float4*)&WaB[(size_t)wk0*T1 + colbase + wc0];
        if (won) nw1 = *(const float4*)&WaB[(size_t)wk1*T1 + colbase + wc1];
    }
    for (int kt = 0; kt < KT; kt++) {
        xs[xkq*4+0][xr] = pk2(nx0.x, nx0.x);
        xs[xkq*4+1][xr] = pk2(nx0.y, nx0.y);
        xs[xkq*4+2][xr] = pk2(nx0.z, nx0.z);
        xs[xkq*4+3][xr] = pk2(nx0.w, nx0.w);
        xs[(xkq+2)*4+0][xr] = pk2(nx1.x, nx1.x);
        xs[(xkq+2)*4+1][xr] = pk2(nx1.y, nx1.y);
        xs[(xkq+2)*4+2][xr] = pk2(nx1.z, nx1.z);
        xs[(xkq+2)*4+3][xr] = pk2(nx1.w, nx1.w);
        *(float4*)&ws[wk0][wc0] = nw0;
        if (won) *(float4*)&ws[wk1][wc1] = nw1;
        __syncthreads();
        if (kt + 1 < KT) {
            int ktn = kt + 1;
            const float* Xs = (ktn < 12) ? U : V;
            const float* Ws = (ktn < 12) ? WaB : WbB;
            int ktl = (ktn < 12) ? ktn : ktn - 12;
            const float* xrow = Xs + (row0 + xr)*T1 + ktl*16;
            nx0 = *(const float4*)&xrow[xkq*4];
            nx1 = *(const float4*)&xrow[(xkq+2)*4];
            nw0 = *(const float4*)&Ws[(size_t)(ktl*16 + wk0)*T1 + colbase + wc0];
            if (won) nw1 = *(const float4*)&Ws[(size_t)(ktl*16 + wk1)*T1 + colbase + wc1];
        }
#pragma unroll
        for (int k = 0; k < 16; k++) {
            ulonglong2 xA = *(const ulonglong2*)&xs[k][ty*8];
            ulonglong2 xB = *(const ulonglong2*)&xs[k][ty*8+2];
            ulonglong2 xC = *(const ulonglong2*)&xs[k][ty*8+4];
            ulonglong2 xD = *(const ulonglong2*)&xs[k][ty*8+6];
            ull xp[RI] = { xA.x, xA.y, xB.x, xB.y, xC.x, xC.y, xD.x, xD.y };
            ull wp[NP];
#pragma unroll
            for (int j = 0; j < NP; j++) wp[j] = *(const ull*)&ws[k][32*j + 2*tx];
#pragma unroll
            for (int i = 0; i < RI; i++)
#pragma unroll
                for (int j = 0; j < NP; j++) fma2(acc[i][j], xp[i], wp[j]);
        }
        __syncthreads();
    }
#pragma unroll
    for (int i = 0; i < RI; i++)
#pragma unroll
        for (int j = 0; j < NP; j++) {
            size_t gi = (row0 + ty*8 + i)*T1 + colbase + 32*j + 2*tx;
            float2 o = upk2(acc[i][j]);
            float2 r = *(const float2*)&resid[gi];
            o.x += r.x; o.y += r.y;
            *(float2*)&Y[gi] = o;
        }
}

// ---------------- tensor-core gmlp: Y = (X@W1)*gelu(X@W2), 3-pass bf16 mma.sync ----------------
// CTA: 256 thr (8 warps as 4M x 2N), tile M=64, N=96 per matrix (x2 matrices).
template<int KTOT, bool G1>
__global__ void __launch_bounds__(256) k_gmlpMMA(const float* __restrict__ X,
                                                 const __nv_bfloat16* __restrict__ Bw,
                                                 const float* __restrict__ gate,
                                                 float* __restrict__ Y) {
    constexpr int KC = KTOT/32;
    constexpr int AST = 40;   // padded row stride (bf16 elems) = 80B: 16B-aligned, ldmatrix conflict-free
    __shared__ __align__(16) __nv_bfloat16 sAh[64*AST];
    __shared__ __align__(16) __nv_bfloat16 sAl[64*AST];
    __shared__ __align__(16) __nv_bfloat16 sB[4*96*AST];
    __shared__ float sg[KTOT];
    int tid = threadIdx.x, lane = tid & 31, wid = tid >> 5;
    int wm = wid & 3, wn = wid >> 2;
    int half = blockIdx.y;
    size_t row0 = (size_t)blockIdx.x * 64;
    int b = blockIdx.x >> 8;   // 256 tiles per batch
    const __nv_bfloat16* BwH = Bw + (size_t)half * 4*96*KTOT;

    if (G1) {
        for (int t = tid; t < KTOT; t += 256) sg[t] = 1.0f + gate[b*KTOT + t];
        __syncthreads();
    }

    float c1[6][4], c2[6][4];
#pragma unroll
    for (int i = 0; i < 6; i++)
#pragma unroll
        for (int j = 0; j < 4; j++) { c1[i][j] = 0.f; c2[i][j] = 0.f; }

    // ldmatrix source addresses (bytes)
    uint32_t aOff = (uint32_t)((wm*16 + (lane & 15))*AST + ((lane >> 4) << 3)) * 2;
    uint32_t aAddrH = smem_u32(sAh) + aOff;
    uint32_t aAddrL = smem_u32(sAl) + aOff;
    uint32_t bRow = (uint32_t)(wn*48 + (lane & 7) + ((lane >> 4) << 3));
    uint32_t bOff = (bRow*AST + (((lane >> 3) & 1) << 3)) * 2;
    uint32_t sBbase = smem_u32(sB);

    int arow = tid >> 2, akg = (tid & 3) * 8;
    const float* xrow = X + (row0 + arow)*KTOT;
    __nv_bfloat16* aDstH = &sAh[arow*AST + akg];
    __nv_bfloat16* aDstL = &sAl[arow*AST + akg];

    for (int kc = 0; kc < KC; kc++) {
        // ---- stage A (fp32 -> bf16 hi/lo, gate fused) ----
        {
            int k0 = kc*32 + akg;
            float4 v0 = *(const float4*)&xrow[k0];
            float4 v1 = *(const float4*)&xrow[k0 + 4];
            if (G1) {
                v0.x *= sg[k0];   v0.y *= sg[k0+1]; v0.z *= sg[k0+2]; v0.w *= sg[k0+3];
                v1.x *= sg[k0+4]; v1.y *= sg[k0+5]; v1.z *= sg[k0+6]; v1.w *= sg[k0+7];
            }
            __nv_bfloat162 h0 = __floats2bfloat162_rn(v0.x, v0.y);
            __nv_bfloat162 h1 = __floats2bfloat162_rn(v0.z, v0.w);
            __nv_bfloat162 h2 = __floats2bfloat162_rn(v1.x, v1.y);
            __nv_bfloat162 h3 = __floats2bfloat162_rn(v1.z, v1.w);
            __nv_bfloat162 l0 = __floats2bfloat162_rn(v0.x - __bfloat162float(h0.x), v0.y - __bfloat162float(h0.y));
            __nv_bfloat162 l1 = __floats2bfloat162_rn(v0.z - __bfloat162float(h1.x), v0.w - __bfloat162float(h1.y));
            __nv_bfloat162 l2 = __floats2bfloat162_rn(v1.x - __bfloat162float(h2.x), v1.y - __bfloat162float(h2.y));
            __nv_bfloat162 l3 = __floats2bfloat162_rn(v1.z - __bfloat162float(h3.x), v1.w - __bfloat162float(h3.y));
            *(uint4*)aDstH = make_uint4(*(uint32_t*)&h0, *(uint32_t*)&h1, *(uint32_t*)&h2, *(uint32_t*)&h3);
            *(uint4*)aDstL = make_uint4(*(uint32_t*)&l0, *(uint32_t*)&l1, *(uint32_t*)&l2, *(uint32_t*)&l3);
        }
        // ---- stage B (pre-split global [mat][n][KTOT] -> padded smem [mat][n][32]) ----
#pragma unroll
        for (int it = 0; it < 6; it++) {
            int i = tid + it*256;
            int mat = i / 384, rem = i % 384;
            int n = rem >> 2, kg = (rem & 3) * 8;
            uint4 v = *(const uint4*)&BwH[((size_t)mat*96 + n)*KTOT + kc*32 + kg];
            *(uint4*)&sB[(mat*96 + n)*AST + kg] = v;
        }
        __syncthreads();
        // ---- compute ----
#pragma unroll
        for (int k16 = 0; k16 < 2; k16++) {
            uint32_t kof = (uint32_t)(k16 * 32);   // 16 elems * 2B
            uint32_t ah[4], al[4];
            LDM4(ah, aAddrH + kof);
            LDM4(al, aAddrL + kof);
#pragma unroll
            for (int mat = 0; mat < 2; mat++) {
                float (*cf)[4] = mat ? c2 : c1;
                uint32_t baseH = sBbase + (uint32_t)((mat*2 + 0)*96*AST)*2 + bOff + kof;
                uint32_t baseL = sBbase + (uint32_t)((mat*2 + 1)*96*AST)*2 + bOff + kof;
#pragma unroll
                for (int pr = 0; pr < 3; pr++) {
                    uint32_t po = (uint32_t)(pr*16*AST)*2;
                    uint32_t bh[4], bl[4];
                    LDM4(bh, baseH + po);
                    LDM4(bl, baseL + po);
                    MMA_BF16(cf[2*pr],   ah, bh[0], bh[1]);
                    MMA_BF16(cf[2*pr+1], ah, bh[2], bh[3]);
                    MMA_BF16(cf[2*pr],   al, bh[0], bh[1]);
                    MMA_BF16(cf[2*pr+1], al, bh[2], bh[3]);
                    MMA_BF16(cf[2*pr],   ah, bl[0], bl[1]);
                    MMA_BF16(cf[2*pr+1], ah, bl[2], bl[3]);
                }
            }
        }
        __syncthreads();
    }

    // ---- epilogue: o = (X@W1) * gelu(X@W2) ----
    int g = lane >> 2, tg = lane & 3;
    size_t mrow = row0 + (size_t)wm*16 + g;
    int colb = half*96 + wn*48 + tg*2;
#pragma unroll
    for (int nf = 0; nf < 6; nf++) {
        int col = colb + nf*8;
        float2 o0 = make_float2(c1[nf][0]*gelu_t(c2[nf][0]), c1[nf][1]*gelu_t(c2[nf][1]));
        float2 o1 = make_float2(c1[nf][2]*gelu_t(c2[nf][2]), c1[nf][3]*gelu_t(c2[nf][3]));
        *(float2*)&Y[mrow*KTOT + col] = o0;
        *(float2*)&Y[(mrow + 8)*KTOT + col] = o1;
    }
}

// ---------------- gemm1: Y = (X1 + sg*X2) @ W[c] [+ bias], SD=96 ----------------
template<int TD, bool BIAS>
__global__ void __launch_bounds__(256, 2) k_gemm1(const float* __restrict__ X1,
                                                  const float* __restrict__ X2,
                                                  const float* __restrict__ W,
                                                  const float* __restrict__ bias,
                                                  const float* __restrict__ gate,
                                                  float* __restrict__ Y) {
    constexpr int TM = 128, RI = 8, SN = 96, NP = 3, KT = TD/16;
    __shared__ __align__(16) ull xs[16][TM];
    __shared__ __align__(16) float ws[16][SN];
    __shared__ float sg[TD];
    int tid = threadIdx.x, tx = tid & 15, ty = tid >> 4;
    int c = blockIdx.y, b = blockIdx.z;
    size_t row0 = (size_t)(b*CC + c)*NN + (size_t)blockIdx.x*TM;
    const float* Wb = W + (size_t)c*TD*SN;
    for (int t = tid; t < TD; t += 256) sg[t] = 1.0f + gate[b*TD + t];
    __syncthreads();

    int xr = tid & 127, xkq = tid >> 7;
    const float* x1row = X1 + (row0 + xr)*TD;
    const float* x2row = X2 + (row0 + xr)*TD;
    int wk0 = tid / 24, wc0 = (tid % 24)*4;
    int wk1 = (tid + 256) / 24, wc1 = ((tid + 256) % 24)*4;
    bool won = (tid < 128);

    ull acc[RI][NP];
#pragma unroll
    for (int i = 0; i < RI; i++)
#pragma unroll
        for (int j = 0; j < NP; j++) acc[i][j] = 0ull;

    float4 na0, na1, nb0, nb1, nw0, nw1;
    {
        na0 = *(const float4*)&x1row[xkq*4];
        na1 = *(const float4*)&x1row[(xkq+2)*4];
        nb0 = *(const float4*)&x2row[xkq*4];
        nb1 = *(const float4*)&x2row[(xkq+2)*4];
        nw0 = *(const float4*)&Wb[(size_t)wk0*SN + wc0];
        if (won) nw1 = *(const float4*)&Wb[(size_t)wk1*SN + wc1];
    }
    for (int kt = 0; kt < KT; kt++) {
        {
            int k0 = kt*16 + xkq*4;
            float4 v = na0, u = nb0;
            v.x = fmaf(u.x, sg[k0],   v.x);
            v.y = fmaf(u.y, sg[k0+1], v.y);
            v.z = fmaf(u.z, sg[k0+2], v.z);
            v.w = fmaf(u.w, sg[k0+3], v.w);
            xs[xkq*4+0][xr] = pk2(v.x, v.x);
            xs[xkq*4+1][xr] = pk2(v.y, v.y);
            xs[xkq*4+2][xr] = pk2(v.z, v.z);
            xs[xkq*4+3][xr] = pk2(v.w, v.w);
            int k2 = k0 + 8;
            v = na1; u = nb1;
            v.x = fmaf(u.x, sg[k2],   v.x);
            v.y = fmaf(u.y, sg[k2+1], v.y);
            v.z = fmaf(u.z, sg[k2+2], v.z);
            v.w = fmaf(u.w, sg[k2+3], v.w);
            xs[(xkq+2)*4+0][xr] = pk2(v.x, v.x);
            xs[(xkq+2)*4+1][xr] = pk2(v.y, v.y);
            xs[(xkq+2)*4+2][xr] = pk2(v.z, v.z);
            xs[(xkq+2)*4+3][xr] = pk2(v.w, v.w);
            *(float4*)&ws[wk0][wc0] = nw0;
            if (won) *(float4*)&ws[wk1][wc1] = nw1;
        }
        __syncthreads();
        if (kt + 1 < KT) {
            int kn = (kt + 1)*16;
            na0 = *(const float4*)&x1row[kn + xkq*4];
            na1 = *(const float4*)&x1row[kn + (xkq+2)*4];
            nb0 = *(const float4*)&x2row[kn + xkq*4];
            nb1 = *(const float4*)&x2row[kn + (xkq+2)*4];
            nw0 = *(const float4*)&Wb[(size_t)(kn + wk0)*SN + wc0];
            if (won) nw1 = *(const float4*)&Wb[(size_t)(kn + wk1)*SN + wc1];
        }
#pragma unroll
        for (int k = 0; k < 16; k++) {
            ulonglong2 xA = *(const ulonglong2*)&xs[k][ty*8];
            ulonglong2 xB = *(const ulonglong2*)&xs[k][ty*8+2];
            ulonglong2 xC = *(const ulonglong2*)&xs[k][ty*8+4];
            ulonglong2 xD = *(const ulonglong2*)&xs[k][ty*8+6];
            ull xp[RI] = { xA.x, xA.y, xB.x, xB.y, xC.x, xC.y, xD.x, xD.y };
            ull wp[NP];
#pragma unroll
            for (int j = 0; j < NP; j++) wp[j] = *(const ull*)&ws[k][32*j + 2*tx];
#pragma unroll
            for (int i = 0; i < RI; i++)
#pragma unroll
                for (int j = 0; j < NP; j++) fma2(acc[i][j], xp[i], wp[j]);
        }
        __syncthreads();
    }
#pragma unroll
    for (int i = 0; i < RI; i++)
#pragma unroll
        for (int j = 0; j < NP; j++) {
            int col = 32*j + 2*tx;
            float2 o = upk2(acc[i][j]);
            if (BIAS) { o.x += bias[col]; o.y += bias[col+1]; }
            *(float2*)&Y[(row0 + ty*8 + i)*SN + col] = o;
        }
}

// ---------------- mean over n ----------------
template<int T>
__global__ void __launch_bounds__(T) k_meanN(const float* __restrict__ X) {
    int c = blockIdx.x, b = blockIdx.y, t = threadIdx.x;
    const float* p = X + ((size_t)(b*CC + c)*NN)*T + t;
    float s0 = 0.f, s1 = 0.f, s2 = 0.f, s3 = 0.f;
    for (int n = 0; n < NN; n += 4) {
        s0 += p[(size_t)n*T];
        s1 += p[(size_t)(n+1)*T];
        s2 += p[(size_t)(n+2)*T];
        s3 += p[(size_t)(n+3)*T];
    }
    g_feat[(b*CC + c)*T + t] = (s0+s1+s2+s3) * (1.0f/NN);
}

// ---------------- attn gate ----------------
template<int T>
__global__ void __launch_bounds__(T) k_gate(const float* __restrict__ Wq,
                                            const float* __restrict__ Wk) {
    __shared__ float ks[T][EE];
    int b = blockIdx.x, t = threadIdx.x;
    float q[EE], kk[EE];
#pragma unroll
    for (int e = 0; e < EE; e++) { q[e] = 0.f; kk[e] = 0.f; }
    for (int c = 0; c < CC; c++) {
        float f = g_feat[(b*CC + c)*T + t];
#pragma unroll
        for (int e = 0; e < EE; e++) {
            q[e]  = fmaf(f, Wq[c*EE + e], q[e]);
            kk[e] = fmaf(f, Wk[c*EE + e], kk[e]);
        }
    }
#pragma unroll
    for (int e = 0; e < EE; e++) ks[t][e] = kk[e];
    __syncthreads();
    float smax = -1e30f, stt = 0.f;
    for (int j = 0; j < T; j++) {
        float d = 0.f;
#pragma unroll
        for (int e = 0; e < EE; e++) d = fmaf(q[e], ks[j][e], d);
        d *= 0.125f;
        if (j == t) stt = d;
        smax = fmaxf(smax, d);
    }
    float ssum = 0.f;
    for (int j = 0; j < T; j++) {
        float d = 0.f;
#pragma unroll
        for (int e = 0; e < EE; e++) d = fmaf(q[e], ks[j][e], d);
        ssum += expf(d*0.125f - smax);
    }
    float p = expf(stt - smax) / ssum;
    g_gate[b*T + t] = gelu_t(p);
}

// ---------------- driver ----------------
extern "C" void kernel_launch(void* const* d_in, const int* in_sizes, int n_in,
                              void* d_out, int out_size) {
    const float* x   = (const float*)d_in[0];
    const float* Gc  = (const float*)d_in[3];
    const float* Lc  = (const float*)d_in[4];
    const float* Gt  = (const float*)d_in[5];
    const float* Lt  = (const float*)d_in[6];
    const float* f1r = (const float*)d_in[7];
    const float* f1i = (const float*)d_in[8];
    const float* f2r = (const float*)d_in[9];
    const float* f2i = (const float*)d_in[10];
    const float* Wfc = (const float*)d_in[11];
    const float* bfc = (const float*)d_in[12];
    const float* mi1 = (const float*)d_in[13];
    const float* mi2 = (const float*)d_in[14];
    const float* mo1 = (const float*)d_in[15];
    const float* mo2 = (const float*)d_in[16];
    const float* aiq = (const float*)d_in[17];
    const float* aik = (const float*)d_in[18];
    const float* aoq = (const float*)d_in[19];
    const float* aok = (const float*)d_in[20];
    float* out = (float*)d_out;

    float *bufA, *bufB, *bufC, *bufD, *bufE, *bufF, *D1, *C2, *gate;
    __nv_bfloat16 *Bin, *Bout;
    cudaGetSymbolAddress((void**)&bufA, g_bufA);
    cudaGetSymbolAddress((void**)&bufB, g_bufB);
    cudaGetSymbolAddress((void**)&bufC, g_bufC);
    cudaGetSymbolAddress((void**)&bufD, g_bufD);
    cudaGetSymbolAddress((void**)&bufE, g_bufE);
    cudaGetSymbolAddress((void**)&bufF, g_bufF);
    cudaGetSymbolAddress((void**)&D1,   g_D1);
    cudaGetSymbolAddress((void**)&C2,   g_C2);
    cudaGetSymbolAddress((void**)&gate, g_gate);
    cudaGetSymbolAddress((void**)&Bin,  g_Bin);
    cudaGetSymbolAddress((void**)&Bout, g_Bout);

    // precompute operator matrices + split weights
    k_tables<<<(L1*T1 + L2*T2 + 255)/256, 256>>>();
    k_buildM<<<dim3(T1, CC), T1>>>(Lc, Lt);
    k_buildK1<<<(CC*T1 + 255)/256, 256>>>(f1r, f1i);
    k_buildD1<<<dim3(T1, CC), T2>>>(Wfc);
    k_buildK2<<<(CC*T2 + 255)/256, 256>>>(f2r, f2i);
    k_expand2<<<(int)(((size_t)CC*T2*T2 + 255)/256), 256>>>();
    k_splitW<T1,2><<<(2*2*4*96*T1 + 255)/256, 256>>>(mi1, mi2, Bin);
    k_splitW<T2,1><<<(2*1*4*96*T2 + 255)/256, 256>>>(mo1, mo2, Bout);

    // freq_attn_in
    k_chmix<<<dim3(NN*T1/256, BB), 256>>>(x, Gc, Gt);
    k_mm2n<<<dim3((NN/128)*2, CC, BB), 256>>>(bufA, bufB, x, bufC);

    const int NT = BB*CC*NN/64;          // 4096 M-tiles of 64 rows
    const size_t L1OFF = (size_t)2*4*96*T1;   // per-layer stride in g_Bin
    const size_t L2OFF = (size_t)1*4*96*T2;   // per-layer stride in g_Bout

    // input-side layers (tensor core)
    k_gmlpMMA<T1,false><<<dim3(NT, 2), 256>>>(bufC, Bin, nullptr, bufA);
    k_meanN<T1><<<dim3(CC, BB), T1>>>(bufA);
    k_gate<T1><<<BB, T1>>>(aiq, aik);
    k_gmlpMMA<T1,true ><<<dim3(NT, 2), 256>>>(bufA, Bin + L1OFF, gate, bufC);
    k_meanN<T1><<<dim3(CC, BB), T1>>>(bufC);
    k_gate<T1><<<BB, T1>>>(aiq + CC*EE, aik + CC*EE);

    // h_y = (x + xc*(1+g)) @ D1[c] + bfc
    k_gemm1<T1, true><<<dim3(NN/128, CC, BB), 256>>>(x, bufC, D1, bfc, gate, bufD);

    // output-side layers (tensor core)
    k_gmlpMMA<T2,false><<<dim3(NT, 1), 256>>>(bufD, Bout, nullptr, bufE);
    k_meanN<T2><<<dim3(CC, BB), T2>>>(bufE);
    k_gate<T2><<<BB, T2>>>(aoq, aok);
    k_gmlpMMA<T2,true ><<<dim3(NT, 1), 256>>>(bufE, Bout + L2OFF, gate, bufF);
    k_meanN<T2><<<dim3(CC, BB), T2>>>(bufF);
    k_gate<T2><<<BB, T2>>>(aoq + CC*EE, aok + CC*EE);

    // out = (h_y + y_c*(1+g)) @ C2[c]
    k_gemm1<T2, false><<<dim3(NN/128, CC, BB), 256>>>(bufD, bufF, C2, nullptr, gate, out);
}

// round 10
// speedup vs baseline: 2.4941x; 1.2413x over previous
#include <cuda_runtime.h>
#include <cuda_bf16.h>
#include <math.h>
#include <stdint.h>

#define BB 16
#define CC 32
#define NN 512
#define T1 192
#define T2 96
#define L1 97
#define L2 49
#define EE 64

typedef unsigned long long ull;
typedef __nv_bfloat16 bf16;

static constexpr size_t SZ1 = (size_t)BB*CC*NN*T1;
static constexpr size_t SZ2 = (size_t)BB*CC*NN*T2;

// ---------------- scratch ----------------
__device__ float g_bufA[SZ1];
__device__ float g_bufB[SZ1];
__device__ float g_bufC[SZ1];
__device__ float g_bufD[SZ2];
__device__ float g_bufF[SZ2];
__device__ float g_Mc[CC*T1*T1];
__device__ float g_Mt[CC*T1*T1];
__device__ float g_D1[CC*T1*T2];
__device__ float g_C2[CC*T2*T2];
__device__ float g_cos1[L1*T1];
__device__ float g_sin1[L1*T1];
__device__ float g_cos2[L2*T2];
__device__ float g_sin2[L2*T2];
__device__ float g_K1[CC*T1];
__device__ float g_K2[CC*T2];
__device__ float g_feat[BB*CC*T1];
__device__ float g_gate[BB*T1];
// pre-split bf16 weights
__device__ bf16 g_Bin[2*2*4*96*T1];          // gmlp input layers [layer][half][mat][n][k]
__device__ bf16 g_Bout[2*1*4*96*T2];         // gmlp output layers
__device__ bf16 g_McB[CC*2*192*384];         // mm2 combined [c][plane][n=192][k=384]
__device__ bf16 g_D1B[CC*2*96*T1];           // fconv1+fc [c][plane][n=96][k=192]
__device__ bf16 g_C2B[CC*2*96*T2];           // fconv2 [c][plane][n=96][k=96]

// ---------------- f32x2 helpers ----------------
__device__ __forceinline__ ull pk2(float lo, float hi) {
    ull r; asm("mov.b64 %0, {%1,%2};" : "=l"(r) : "f"(lo), "f"(hi)); return r;
}
__device__ __forceinline__ void fma2(ull& d, ull a, ull b) {
    asm("fma.rn.f32x2 %0, %1, %2, %0;" : "+l"(d) : "l"(a), "l"(b));
}
__device__ __forceinline__ float2 upk2(ull v) {
    float2 f; asm("mov.b64 {%0,%1}, %2;" : "=f"(f.x), "=f"(f.y) : "l"(v)); return f;
}

__device__ __forceinline__ float gelu_t(float x) {
    float x3 = x*x*x;
    return 0.5f*x*(1.0f + tanhf(0.7978845608028654f*(x + 0.044715f*x3)));
}

__device__ __forceinline__ uint32_t smem_u32(const void* p) {
    uint32_t a;
    asm("{ .reg .u64 t; cvta.to.shared.u64 t, %1; cvt.u32.u64 %0, t; }" : "=r"(a) : "l"(p));
    return a;
}

// ---------------- mma.sync helpers ----------------
#define LDM4(r, addr) \
    asm volatile("ldmatrix.sync.aligned.m8n8.x4.shared.b16 {%0,%1,%2,%3}, [%4];" \
        : "=r"((r)[0]), "=r"((r)[1]), "=r"((r)[2]), "=r"((r)[3]) : "r"(addr))

#define MMA_BF16(c, a, b0, b1) \
    asm volatile("mma.sync.aligned.m16n8k16.row.col.f32.bf16.bf16.f32 " \
        "{%0,%1,%2,%3},{%4,%5,%6,%7},{%8,%9},{%0,%1,%2,%3};" \
        : "+f"((c)[0]), "+f"((c)[1]), "+f"((c)[2]), "+f"((c)[3]) \
        : "r"((a)[0]), "r"((a)[1]), "r"((a)[2]), "r"((a)[3]), "r"(b0), "r"(b1))

// A-tile hi/lo convert+store helper (8 k-elems per thread)
__device__ __forceinline__ void cvt_hilo_store(float4 v0, float4 v1, bf16* dH, bf16* dL) {
    __nv_bfloat162 h0 = __floats2bfloat162_rn(v0.x, v0.y);
    __nv_bfloat162 h1 = __floats2bfloat162_rn(v0.z, v0.w);
    __nv_bfloat162 h2 = __floats2bfloat162_rn(v1.x, v1.y);
    __nv_bfloat162 h3 = __floats2bfloat162_rn(v1.z, v1.w);
    __nv_bfloat162 l0 = __floats2bfloat162_rn(v0.x - __bfloat162float(h0.x), v0.y - __bfloat162float(h0.y));
    __nv_bfloat162 l1 = __floats2bfloat162_rn(v0.z - __bfloat162float(h1.x), v0.w - __bfloat162float(h1.y));
    __nv_bfloat162 l2 = __floats2bfloat162_rn(v1.x - __bfloat162float(h2.x), v1.y - __bfloat162float(h2.y));
    __nv_bfloat162 l3 = __floats2bfloat162_rn(v1.z - __bfloat162float(h3.x), v1.w - __bfloat162float(h3.y));
    *(uint4*)dH = make_uint4(*(uint32_t*)&h0, *(uint32_t*)&h1, *(uint32_t*)&h2, *(uint32_t*)&h3);
    *(uint4*)dL = make_uint4(*(uint32_t*)&l0, *(uint32_t*)&l1, *(uint32_t*)&l2, *(uint32_t*)&l3);
}

// ---------------- precompute ----------------
__global__ void k_tables() {
    int i = blockIdx.x*blockDim.x + threadIdx.x;
    if (i < L1*T1) {
        int h = i / T1, t = i % T1;
        int m = (h*t) % T1;
        float a = (float)m * (1.0f/96.0f);
        g_cos1[i] = cospif(a);
        g_sin1[i] = sinpif(a);
    }
    int j = i - L1*T1;
    if (j >= 0 && j < L2*T2) {
        int h = j / T2, t = j % T2;
        int m = (h*t) % T2;
        float a = (float)m * (1.0f/48.0f);
        g_cos2[j] = cospif(a);
        g_sin2[j] = sinpif(a);
    }
}

__global__ void k_buildM(const float* __restrict__ Lc, const float* __restrict__ Lt) {
    int t = blockIdx.x, l = blockIdx.y, tp = threadIdx.x;
    float ac = 0.f, as = 0.f;
    for (int h = 0; h < L1; h++) {
        float w = (h == 0 || h == L1-1) ? (1.0f/T1) : (2.0f/T1);
        float lc = Lc[l*L1+h]*w, lt = Lt[l*L1+h]*w;
        ac = fmaf(lc * g_cos1[h*T1+t], g_cos1[h*T1+tp], ac);
        as = fmaf(lt * g_sin1[h*T1+t], g_sin1[h*T1+tp], as);
    }
    size_t o = ((size_t)l*T1 + t)*T1 + tp;
    g_Mc[o] = ac;
    g_Mt[o] = as;
}

__global__ void k_buildK1(const float* __restrict__ Wr, const float* __restrict__ Wi) {
    int i = blockIdx.x*blockDim.x + threadIdx.x;
    if (i >= CC*T1) return;
    int c = i / T1, d = i % T1;
    float acc = 0.f;
    for (int h = 0; h < L1; h++) {
        float w = (h == 0 || h == L1-1) ? (1.0f/T1) : (2.0f/T1);
        acc += w * (Wr[c*L1+h]*g_cos1[h*T1+d] - Wi[c*L1+h]*g_sin1[h*T1+d]);
    }
    g_K1[i] = acc;
}

__global__ void k_buildD1(const float* __restrict__ Wfc) {
    __shared__ float kr[T1];
    int t = blockIdx.x, c = blockIdx.y, s2 = threadIdx.x;
    for (int s = s2; s < T1; s += T2) kr[s] = g_K1[c*T1 + s];
    __syncthreads();
    float acc = 0.f;
    int ii = (T1 - t) % T1;
    for (int s = 0; s < T1; s++) {
        acc = fmaf(kr[ii], Wfc[s*T2 + s2], acc);
        ii++; if (ii == T1) ii = 0;
    }
    g_D1[((size_t)c*T1 + t)*T2 + s2] = acc;
}

__global__ void k_buildK2(const float* __restrict__ Wr, const float* __restrict__ Wi) {
    int i = blockIdx.x*blockDim.x + threadIdx.x;
    if (i >= CC*T2) return;
    int c = i / T2, d = i % T2;
    float acc = 0.f;
    for (int h = 0; h < L2; h++) {
        float w = (h == 0 || h == L2-1) ? (1.0f/T2) : (2.0f/T2);
        acc += w * (Wr[c*L2+h]*g_cos2[h*T2+d] - Wi[c*L2+h]*g_sin2[h*T2+d]);
    }
    g_K2[i] = acc;
}
__global__ void k_expand2() {
    size_t i = (size_t)blockIdx.x*blockDim.x + threadIdx.x;
    if (i >= (size_t)CC*T2*T2) return;
    int s = (int)(i % T2);
    int t = (int)((i / T2) % T2);
    int c = (int)(i / ((size_t)T2*T2));
    g_C2[i] = g_K2[c*T2 + ((s - t + T2) % T2)];
}

// split gmlp weights (global inputs) into hi/lo bf16, transposed to [n][k]
template<int KTOT, int HALVES>
__global__ void k_splitW(const float* __restrict__ W1, const float* __restrict__ W2,
                         bf16* __restrict__ dst) {
    int total = 2*HALVES*4*96*KTOT;
    int idx = blockIdx.x*blockDim.x + threadIdx.x;
    if (idx >= total) return;
    int k     = idx % KTOT;
    int n     = (idx / KTOT) % 96;
    int mat   = (idx / (KTOT*96)) % 4;
    int half  = (idx / (KTOT*96*4)) % HALVES;
    int layer = idx / (KTOT*96*4*HALVES);
    const float* src = (mat < 2) ? W1 : W2;
    int s = half*96 + n;
    float w = src[(size_t)layer*KTOT*KTOT + (size_t)k*KTOT + s];
    bf16 hi = __float2bfloat16(w);
    bf16 v = (mat & 1) ? __float2bfloat16(w - __bfloat162float(hi)) : hi;
    dst[idx] = v;
}

// split device-built Mc/Mt into combined [c][plane][n=192][k=384] hi/lo
__global__ void k_splitMM() {
    size_t total = (size_t)CC*2*192*384;
    size_t idx = (size_t)blockIdx.x*blockDim.x + threadIdx.x;
    if (idx >= total) return;
    int k     = (int)(idx % 384);
    int n     = (int)((idx / 384) % 192);
    int plane = (int)((idx / (384*192)) % 2);
    int c     = (int)(idx / (384*192*2));
    float w = (k < 192) ? g_Mc[((size_t)c*T1 + k)*T1 + n]
                        : g_Mt[((size_t)c*T1 + (k-192))*T1 + n];
    bf16 hi = __float2bfloat16(w);
    g_McB[idx] = plane ? __float2bfloat16(w - __bfloat162float(hi)) : hi;
}

// split D1 [c][k=192][n=96] -> [c][plane][n][k]
__global__ void k_splitD1() {
    int total = CC*2*96*T1;
    int idx = blockIdx.x*blockDim.x + threadIdx.x;
    if (idx >= total) return;
    int k     = idx % T1;
    int n     = (idx / T1) % 96;
    int plane = (idx / (T1*96)) % 2;
    int c     = idx / (T1*96*2);
    float w = g_D1[((size_t)c*T1 + k)*T2 + n];
    bf16 hi = __float2bfloat16(w);
    g_D1B[idx] = plane ? __float2bfloat16(w - __bfloat162float(hi)) : hi;
}

// split C2 [c][k=96][n=96] -> [c][plane][n][k]
__global__ void k_splitC2() {
    int total = CC*2*96*T2;
    int idx = blockIdx.x*blockDim.x + threadIdx.x;
    if (idx >= total) return;
    int k     = idx % T2;
    int n     = (idx / T2) % 96;
    int plane = (idx / (T2*96)) % 2;
    int c     = idx / (T2*96*2);
    float w = g_C2[((size_t)c*T2 + k)*T2 + n];
    bf16 hi = __float2bfloat16(w);
    g_C2B[idx] = plane ? __float2bfloat16(w - __bfloat162float(hi)) : hi;
}

// ---------------- channel mix ----------------
__global__ void __launch_bounds__(256) k_chmix(const float* __restrict__ x,
                                               const float* __restrict__ Gc,
                                               const float* __restrict__ Gt) {
    __shared__ __align__(16) float2 sG[CC*CC];
    int tid = threadIdx.x;
    for (int i = tid; i < CC*CC; i += 256) sG[i] = make_float2(Gc[i], Gt[i]);
    __syncthreads();
    int b = blockIdx.y;
    size_t m = (size_t)blockIdx.x*256 + tid;
    ull a[CC];
#pragma unroll
    for (int l = 0; l < CC; l++) a[l] = 0ull;
    for (int c = 0; c < CC; c++) {
        float xv = x[((size_t)(b*CC + c)*NN)*T1 + m];
        ull xp = pk2(xv, xv);
#pragma unroll
        for (int l = 0; l < CC; l++) fma2(a[l], xp, *(const ull*)&sG[c*CC + l]);
    }
#pragma unroll
    for (int l = 0; l < CC; l++) {
        float2 p = upk2(a[l]);
        g_bufA[((size_t)(b*CC + l)*NN)*T1 + m] = p.x;
        g_bufB[((size_t)(b*CC + l)*NN)*T1 + m] = p.y;
    }
}

// ---------------- mm2 (tensor): Y = resid + [u|v] @ [Mc;Mt][c], 3-pass bf16 ----------------
__global__ void __launch_bounds__(256) k_mm2MMA(const float* __restrict__ U,
                                                const float* __restrict__ V,
                                                const float* __restrict__ resid,
                                                float* __restrict__ Y) {
    constexpr int AST = 40;
    __shared__ __align__(16) bf16 sAh[64*AST];
    __shared__ __align__(16) bf16 sAl[64*AST];
    __shared__ __align__(16) bf16 sB[2*96*AST];
    int tid = threadIdx.x, lane = tid & 31, wid = tid >> 5;
    int wm = wid & 3, wn = wid >> 2;
    int xt = blockIdx.x >> 1, half = blockIdx.x & 1;
    int c = blockIdx.y, b = blockIdx.z;
    size_t row0 = (size_t)(b*CC + c)*NN + (size_t)xt*64;
    const bf16* Wc = g_McB + (size_t)c*2*192*384;

    float cc[6][4];
#pragma unroll
    for (int i = 0; i < 6; i++)
#pragma unroll
        for (int j = 0; j < 4; j++) cc[i][j] = 0.f;

    uint32_t aOff = (uint32_t)((wm*16 + (lane & 15))*AST + ((lane >> 4) << 3)) * 2;
    uint32_t aAddrH = smem_u32(sAh) + aOff;
    uint32_t aAddrL = smem_u32(sAl) + aOff;
    uint32_t bRow = (uint32_t)(wn*48 + (lane & 7) + ((lane >> 4) << 3));
    uint32_t bOff = (bRow*AST + (((lane >> 3) & 1) << 3)) * 2;
    uint32_t sBbase = smem_u32(sB);

    int arow = tid >> 2, akg = (tid & 3) * 8;
    bf16* aDstH = &sAh[arow*AST + akg];
    bf16* aDstL = &sAl[arow*AST + akg];

    for (int kc = 0; kc < 12; kc++) {
        {
            const float* Xs = (kc < 6) ? U : V;
            int kl = (kc < 6) ? kc : kc - 6;
            const float* xr = Xs + (row0 + arow)*T1 + kl*32 + akg;
            cvt_hilo_store(*(const float4*)xr, *(const float4*)(xr + 4), aDstH, aDstL);
        }
#pragma unroll
        for (int it = 0; it < 3; it++) {
            int i = tid + it*256;
            int plane = i / 384, rem = i % 384;
            int n = rem >> 2, kg = (rem & 3) * 8;
            uint4 v = *(const uint4*)&Wc[((size_t)plane*192 + half*96 + n)*384 + kc*32 + kg];
            *(uint4*)&sB[(plane*96 + n)*AST + kg] = v;
        }
        __syncthreads();
#pragma unroll
        for (int k16 = 0; k16 < 2; k16++) {
            uint32_t kof = (uint32_t)(k16 * 32);
            uint32_t ah[4], al[4];
            LDM4(ah, aAddrH + kof);
            LDM4(al, aAddrL + kof);
            uint32_t baseH = sBbase + bOff + kof;
            uint32_t baseL = baseH + (uint32_t)(96*AST)*2;
#pragma unroll
            for (int pr = 0; pr < 3; pr++) {
                uint32_t po = (uint32_t)(pr*16*AST)*2;
                uint32_t bh[4], bl[4];
                LDM4(bh, baseH + po);
                LDM4(bl, baseL + po);
                MMA_BF16(cc[2*pr],   ah, bh[0], bh[1]);
                MMA_BF16(cc[2*pr+1], ah, bh[2], bh[3]);
                MMA_BF16(cc[2*pr],   al, bh[0], bh[1]);
                MMA_BF16(cc[2*pr+1], al, bh[2], bh[3]);
                MMA_BF16(cc[2*pr],   ah, bl[0], bl[1]);
                MMA_BF16(cc[2*pr+1], ah, bl[2], bl[3]);
            }
        }
        __syncthreads();
    }

    int g = lane >> 2, tg = lane & 3;
    size_t mrow = row0 + (size_t)wm*16 + g;
    int colb = half*96 + wn*48 + tg*2;
#pragma unroll
    for (int nf = 0; nf < 6; nf++) {
        int col = colb + nf*8;
        float2 r0 = *(const float2*)&resid[mrow*T1 + col];
        float2 r1 = *(const float2*)&resid[(mrow + 8)*T1 + col];
        *(float2*)&Y[mrow*T1 + col]       = make_float2(cc[nf][0] + r0.x, cc[nf][1] + r0.y);
        *(float2*)&Y[(mrow + 8)*T1 + col] = make_float2(cc[nf][2] + r1.x, cc[nf][3] + r1.y);
    }
}

// ---------------- channel GEMM (tensor): Y = (X1 + sg*X2) @ W[c] [+bias], N=96 ----------------
template<int KTOT, bool BIAS>
__global__ void __launch_bounds__(256) k_cgemmMMA(const float* __restrict__ X1,
                                                  const float* __restrict__ X2,
                                                  const bf16* __restrict__ WB,
                                                  const float* __restrict__ bias,
                                                  const float* __restrict__ gate,
                                                  float* __restrict__ Y) {
    constexpr int AST = 40, KC = KTOT/32;
    __shared__ __align__(16) bf16 sAh[64*AST];
    __shared__ __align__(16) bf16 sAl[64*AST];
    __shared__ __align__(16) bf16 sB[2*96*AST];
    __shared__ float sg[KTOT];
    int tid = threadIdx.x, lane = tid & 31, wid = tid >> 5;
    int wm = wid & 3, wn = wid >> 2;
    int c = blockIdx.y, b = blockIdx.z;
    size_t row0 = (size_t)(b*CC + c)*NN + (size_t)blockIdx.x*64;
    const bf16* Wc = WB + (size_t)c*2*96*KTOT;

    for (int t = tid; t < KTOT; t += 256) sg[t] = 1.0f + gate[b*KTOT + t];
    __syncthreads();

    float cc[6][4];
#pragma unroll
    for (int i = 0; i < 6; i++)
#pragma unroll
        for (int j = 0; j < 4; j++) cc[i][j] = 0.f;

    uint32_t aOff = (uint32_t)((wm*16 + (lane & 15))*AST + ((lane >> 4) << 3)) * 2;
    uint32_t aAddrH = smem_u32(sAh) + aOff;
    uint32_t aAddrL = smem_u32(sAl) + aOff;
    uint32_t bRow = (uint32_t)(wn*48 + (lane & 7) + ((lane >> 4) << 3));
    uint32_t bOff = (bRow*AST + (((lane >> 3) & 1) << 3)) * 2;
    uint32_t sBbase = smem_u32(sB);

    int arow = tid >> 2, akg = (tid & 3) * 8;
    const float* x1r = X1 + (row0 + arow)*KTOT;
    const float* x2r = X2 + (row0 + arow)*KTOT;
    bf16* aDstH = &sAh[arow*AST + akg];
    bf16* aDstL = &sAl[arow*AST + akg];

    for (int kc = 0; kc < KC; kc++) {
        {
            int k0 = kc*32 + akg;
            float4 v0 = *(const float4*)&x1r[k0];
            float4 v1 = *(const float4*)&x1r[k0 + 4];
            float4 u0 = *(const float4*)&x2r[k0];
            float4 u1 = *(const float4*)&x2r[k0 + 4];
            v0.x = fmaf(u0.x, sg[k0],   v0.x);
            v0.y = fmaf(u0.y, sg[k0+1], v0.y);
            v0.z = fmaf(u0.z, sg[k0+2], v0.z);
            v0.w = fmaf(u0.w, sg[k0+3], v0.w);
            v1.x = fmaf(u1.x, sg[k0+4], v1.x);
            v1.y = fmaf(u1.y, sg[k0+5], v1.y);
            v1.z = fmaf(u1.z, sg[k0+6], v1.z);
            v1.w = fmaf(u1.w, sg[k0+7], v1.w);
            cvt_hilo_store(v0, v1, aDstH, aDstL);
        }
#pragma unroll
        for (int it = 0; it < 3; it++) {
            int i = tid + it*256;
            int plane = i / 384, rem = i % 384;
            int n = rem >> 2, kg = (rem & 3) * 8;
            uint4 v = *(const uint4*)&Wc[((size_t)plane*96 + n)*KTOT + kc*32 + kg];
            *(uint4*)&sB[(plane*96 + n)*AST + kg] = v;
        }
        __syncthreads();
#pragma unroll
        for (int k16 = 0; k16 < 2; k16++) {
            uint32_t kof = (uint32_t)(k16 * 32);
            uint32_t ah[4], al[4];
            LDM4(ah, aAddrH + kof);
            LDM4(al, aAddrL + kof);
            uint32_t baseH = sBbase + bOff + kof;
            uint32_t baseL = baseH + (uint32_t)(96*AST)*2;
#pragma unroll
            for (int pr = 0; pr < 3; pr++) {
                uint32_t po = (uint32_t)(pr*16*AST)*2;
                uint32_t bh[4], bl[4];
                LDM4(bh, baseH + po);
                LDM4(bl, baseL + po);
                MMA_BF16(cc[2*pr],   ah, bh[0], bh[1]);
                MMA_BF16(cc[2*pr+1], ah, bh[2], bh[3]);
                MMA_BF16(cc[2*pr],   al, bh[0], bh[1]);
                MMA_BF16(cc[2*pr+1], al, bh[2], bh[3]);
                MMA_BF16(cc[2*pr],   ah, bl[0], bl[1]);
                MMA_BF16(cc[2*pr+1], ah, bl[2], bl[3]);
            }
        }
        __syncthreads();
    }

    int g = lane >> 2, tg = lane & 3;
    size_t mrow = row0 + (size_t)wm*16 + g;
    int colb = wn*48 + tg*2;
#pragma unroll
    for (int nf = 0; nf < 6; nf++) {
        int col = colb + nf*8;
        float2 o0 = make_float2(cc[nf][0], cc[nf][1]);
        float2 o1 = make_float2(cc[nf][2], cc[nf][3]);
        if (BIAS) {
            float2 bv = *(const float2*)&bias[col];
            o0.x += bv.x; o0.y += bv.y; o1.x += bv.x; o1.y += bv.y;
        }
        *(float2*)&Y[mrow*96 + col]       = o0;
        *(float2*)&Y[(mrow + 8)*96 + col] = o1;
    }
}

// ---------------- tensor-core gmlp (from R9, unchanged) ----------------
template<int KTOT, bool G1>
__global__ void __launch_bounds__(256) k_gmlpMMA(const float* __restrict__ X,
                                                 const bf16* __restrict__ Bw,
                                                 const float* __restrict__ gate,
                                                 float* __restrict__ Y) {
    constexpr int KC = KTOT/32;
    constexpr int AST = 40;
    __shared__ __align__(16) bf16 sAh[64*AST];
    __shared__ __align__(16) bf16 sAl[64*AST];
    __shared__ __align__(16) bf16 sB[4*96*AST];
    __shared__ float sg[KTOT];
    int tid = threadIdx.x, lane = tid & 31, wid = tid >> 5;
    int wm = wid & 3, wn = wid >> 2;
    int half = blockIdx.y;
    size_t row0 = (size_t)blockIdx.x * 64;
    int b = blockIdx.x >> 8;
    const bf16* BwH = Bw + (size_t)half * 4*96*KTOT;

    if (G1) {
        for (int t = tid; t < KTOT; t += 256) sg[t] = 1.0f + gate[b*KTOT + t];
        __syncthreads();
    }

    float c1[6][4], c2[6][4];
#pragma unroll
    for (int i = 0; i < 6; i++)
#pragma unroll
        for (int j = 0; j < 4; j++) { c1[i][j] = 0.f; c2[i][j] = 0.f; }

    uint32_t aOff = (uint32_t)((wm*16 + (lane & 15))*AST + ((lane >> 4) << 3)) * 2;
    uint32_t aAddrH = smem_u32(sAh) + aOff;
    uint32_t aAddrL = smem_u32(sAl) + aOff;
    uint32_t bRow = (uint32_t)(wn*48 + (lane & 7) + ((lane >> 4) << 3));
    uint32_t bOff = (bRow*AST + (((lane >> 3) & 1) << 3)) * 2;
    uint32_t sBbase = smem_u32(sB);

    int arow = tid >> 2, akg = (tid & 3) * 8;
    const float* xrow = X + (row0 + arow)*KTOT;
    bf16* aDstH = &sAh[arow*AST + akg];
    bf16* aDstL = &sAl[arow*AST + akg];

    for (int kc = 0; kc < KC; kc++) {
        {
            int k0 = kc*32 + akg;
            float4 v0 = *(const float4*)&xrow[k0];
            float4 v1 = *(const float4*)&xrow[k0 + 4];
            if (G1) {
                v0.x *= sg[k0];   v0.y *= sg[k0+1]; v0.z *= sg[k0+2]; v0.w *= sg[k0+3];
                v1.x *= sg[k0+4]; v1.y *= sg[k0+5]; v1.z *= sg[k0+6]; v1.w *= sg[k0+7];
            }
            cvt_hilo_store(v0, v1, aDstH, aDstL);
        }
#pragma unroll
        for (int it = 0; it < 6; it++) {
            int i = tid + it*256;
            int mat = i / 384, rem = i % 384;
            int n = rem >> 2, kg = (rem & 3) * 8;
            uint4 v = *(const uint4*)&BwH[((size_t)mat*96 + n)*KTOT + kc*32 + kg];
            *(uint4*)&sB[(mat*96 + n)*AST + kg] = v;
        }
        __syncthreads();
#pragma unroll
        for (int k16 = 0; k16 < 2; k16++) {
            uint32_t kof = (uint32_t)(k16 * 32);
            uint32_t ah[4], al[4];
            LDM4(ah, aAddrH + kof);
            LDM4(al, aAddrL + kof);
#pragma unroll
            for (int mat = 0; mat < 2; mat++) {
                float (*cf)[4] = mat ? c2 : c1;
                uint32_t baseH = sBbase + (uint32_t)((mat*2 + 0)*96*AST)*2 + bOff + kof;
                uint32_t baseL = sBbase + (uint32_t)((mat*2 + 1)*96*AST)*2 + bOff + kof;
#pragma unroll
                for (int pr = 0; pr < 3; pr++) {
                    uint32_t po = (uint32_t)(pr*16*AST)*2;
                    uint32_t bh[4], bl[4];
                    LDM4(bh, baseH + po);
                    LDM4(bl, baseL + po);
                    MMA_BF16(cf[2*pr],   ah, bh[0], bh[1]);
                    MMA_BF16(cf[2*pr+1], ah, bh[2], bh[3]);
                    MMA_BF16(cf[2*pr],   al, bh[0], bh[1]);
                    MMA_BF16(cf[2*pr+1], al, bh[2], bh[3]);
                    MMA_BF16(cf[2*pr],   ah, bl[0], bl[1]);
                    MMA_BF16(cf[2*pr+1], ah, bl[2], bl[3]);
                }
            }
        }
        __syncthreads();
    }

    int g = lane >> 2, tg = lane & 3;
    size_t mrow = row0 + (size_t)wm*16 + g;
    int colb = half*96 + wn*48 + tg*2;
#pragma unroll
    for (int nf = 0; nf < 6; nf++) {
        int col = colb + nf*8;
        float2 o0 = make_float2(c1[nf][0]*gelu_t(c2[nf][0]), c1[nf][1]*gelu_t(c2[nf][1]));
        float2 o1 = make_float2(c1[nf][2]*gelu_t(c2[nf][2]), c1[nf][3]*gelu_t(c2[nf][3]));
        *(float2*)&Y[mrow*KTOT + col] = o0;
        *(float2*)&Y[(mrow + 8)*KTOT + col] = o1;
    }
}

// ---------------- mean over n ----------------
template<int T>
__global__ void __launch_bounds__(T) k_meanN(const float* __restrict__ X) {
    int c = blockIdx.x, b = blockIdx.y, t = threadIdx.x;
    const float* p = X + ((size_t)(b*CC + c)*NN)*T + t;
    float s0 = 0.f, s1 = 0.f, s2 = 0.f, s3 = 0.f;
    for (int n = 0; n < NN; n += 4) {
        s0 += p[(size_t)n*T];
        s1 += p[(size_t)(n+1)*T];
        s2 += p[(size_t)(n+2)*T];
        s3 += p[(size_t)(n+3)*T];
    }
    g_feat[(b*CC + c)*T + t] = (s0+s1+s2+s3) * (1.0f/NN);
}

// ---------------- attn gate ----------------
template<int T>
__global__ void __launch_bounds__(T) k_gate(const float* __restrict__ Wq,
                                            const float* __restrict__ Wk) {
    __shared__ float ks[T][EE];
    int b = blockIdx.x, t = threadIdx.x;
    float q[EE], kk[EE];
#pragma unroll
    for (int e = 0; e < EE; e++) { q[e] = 0.f; kk[e] = 0.f; }
    for (int c = 0; c < CC; c++) {
        float f = g_feat[(b*CC + c)*T + t];
#pragma unroll
        for (int e = 0; e < EE; e++) {
            q[e]  = fmaf(f, Wq[c*EE + e], q[e]);
            kk[e] = fmaf(f, Wk[c*EE + e], kk[e]);
        }
    }
#pragma unroll
    for (int e = 0; e < EE; e++) ks[t][e] = kk[e];
    __syncthreads();
    float smax = -1e30f, stt = 0.f;
    for (int j = 0; j < T; j++) {
        float d = 0.f;
#pragma unroll
        for (int e = 0; e < EE; e++) d = fmaf(q[e], ks[j][e], d);
        d *= 0.125f;
        if (j == t) stt = d;
        smax = fmaxf(smax, d);
    }
    float ssum = 0.f;
    for (int j = 0; j < T; j++) {
        float d = 0.f;
#pragma unroll
        for (int e = 0; e < EE; e++) d = fmaf(q[e], ks[j][e], d);
        ssum += expf(d*0.125f - smax);
    }
    float p = expf(stt - smax) / ssum;
    g_gate[b*T + t] = gelu_t(p);
}

// ---------------- driver ----------------
extern "C" void kernel_launch(void* const* d_in, const int* in_sizes, int n_in,
                              void* d_out, int out_size) {
    const float* x   = (const float*)d_in[0];
    const float* Gc  = (const float*)d_in[3];
    const float* Lc  = (const float*)d_in[4];
    const float* Gt  = (const float*)d_in[5];
    const float* Lt  = (const float*)d_in[6];
    const float* f1r = (const float*)d_in[7];
    const float* f1i = (const float*)d_in[8];
    const float* f2r = (const float*)d_in[9];
    const float* f2i = (const float*)d_in[10];
    const float* Wfc = (const float*)d_in[11];
    const float* bfc = (const float*)d_in[12];
    const float* mi1 = (const float*)d_in[13];
    const float* mi2 = (const float*)d_in[14];
    const float* mo1 = (const float*)d_in[15];
    const float* mo2 = (const float*)d_in[16];
    const float* aiq = (const float*)d_in[17];
    const float* aik = (const float*)d_in[18];
    const float* aoq = (const float*)d_in[19];
    const float* aok = (const float*)d_in[20];
    float* out = (float*)d_out;

    float *bufA, *bufB, *bufC, *bufD, *bufF, *gate;
    bf16 *Bin, *Bout, *D1B, *C2B;
    cudaGetSymbolAddress((void**)&bufA, g_bufA);
    cudaGetSymbolAddress((void**)&bufB, g_bufB);
    cudaGetSymbolAddress((void**)&bufC, g_bufC);
    cudaGetSymbolAddress((void**)&bufD, g_bufD);
    cudaGetSymbolAddress((void**)&bufF, g_bufF);
    cudaGetSymbolAddress((void**)&gate, g_gate);
    cudaGetSymbolAddress((void**)&Bin,  g_Bin);
    cudaGetSymbolAddress((void**)&Bout, g_Bout);
    cudaGetSymbolAddress((void**)&D1B,  g_D1B);
    cudaGetSymbolAddress((void**)&C2B,  g_C2B);

    // precompute operator matrices + weight splits
    k_tables<<<(L1*T1 + L2*T2 + 255)/256, 256>>>();
    k_buildM<<<dim3(T1, CC), T1>>>(Lc, Lt);
    k_buildK1<<<(CC*T1 + 255)/256, 256>>>(f1r, f1i);
    k_buildD1<<<dim3(T1, CC), T2>>>(Wfc);
    k_buildK2<<<(CC*T2 + 255)/256, 256>>>(f2r, f2i);
    k_expand2<<<(int)(((size_t)CC*T2*T2 + 255)/256), 256>>>();
    k_splitW<T1,2><<<(2*2*4*96*T1 + 255)/256, 256>>>(mi1, mi2, Bin);
    k_splitW<T2,1><<<(2*1*4*96*T2 + 255)/256, 256>>>(mo1, mo2, Bout);
    k_splitMM<<<(int)(((size_t)CC*2*192*384 + 255)/256), 256>>>();
    k_splitD1<<<(CC*2*96*T1 + 255)/256, 256>>>();
    k_splitC2<<<(CC*2*96*T2 + 255)/256, 256>>>();

    // freq_attn_in: u = Gc^T x, v = Gt^T x ; xc = x + u@Mc[c] + v@Mt[c]
    k_chmix<<<dim3(NN*T1/256, BB), 256>>>(x, Gc, Gt);
    k_mm2MMA<<<dim3((NN/64)*2, CC, BB), 256>>>(bufA, bufB, x, bufC);

    const int NT = BB*CC*NN/64;               // 4096 M-tiles of 64 rows
    const size_t L1OFF = (size_t)2*4*96*T1;
    const size_t L2OFF = (size_t)1*4*96*T2;

    // input-side layers (tensor core)
    k_gmlpMMA<T1,false><<<dim3(NT, 2), 256>>>(bufC, Bin, nullptr, bufA);
    k_meanN<T1><<<dim3(CC, BB), T1>>>(bufA);
    k_gate<T1><<<BB, T1>>>(aiq, aik);
    k_gmlpMMA<T1,true ><<<dim3(NT, 2), 256>>>(bufA, Bin + L1OFF, gate, bufC);
    k_meanN<T1><<<dim3(CC, BB), T1>>>(bufC);
    k_gate<T1><<<BB, T1>>>(aiq + CC*EE, aik + CC*EE);

    // h_y = (x + xc*(1+g)) @ D1[c] + bfc   (fconv1 + fc_idp fused, tensor)
    k_cgemmMMA<T1, true><<<dim3(NN/64, CC, BB), 256>>>(x, bufC, D1B, bfc, gate, bufD);

    // output-side layers (tensor core)
    k_gmlpMMA<T2,false><<<dim3(NT, 1), 256>>>(bufD, Bout, nullptr, bufA);
    k_meanN<T2><<<dim3(CC, BB), T2>>>(bufA);
    k_gate<T2><<<BB, T2>>>(aoq, aok);
    k_gmlpMMA<T2,true ><<<dim3(NT, 1), 256>>>(bufA, Bout + L2OFF, gate, bufF);
    k_meanN<T2><<<dim3(CC, BB), T2>>>(bufF);
    k_gate<T2><<<BB, T2>>>(aoq + CC*EE, aok + CC*EE);

    // out = (h_y + y_c*(1+g)) @ C2[c]   (tensor)
    k_cgemmMMA<T2, false><<<dim3(NN/64, CC, BB), 256>>>(bufD, bufF, C2B, nullptr, gate, out);
}

// round 11
// speedup vs baseline: 2.7158x; 1.0889x over previous
#include <cuda_runtime.h>
#include <cuda_bf16.h>
#include <math.h>
#include <stdint.h>

#define BB 16
#define CC 32
#define NN 512
#define T1 192
#define T2 96
#define L1 97
#define L2 49
#define EE 64

typedef unsigned long long ull;
typedef __nv_bfloat16 bf16;

static constexpr size_t SZ1 = (size_t)BB*CC*NN*T1;
static constexpr size_t SZ2 = (size_t)BB*CC*NN*T2;

// ---------------- scratch ----------------
__device__ float g_bufA[SZ1];
__device__ float g_bufB[SZ1];
__device__ float g_bufC[SZ1];
__device__ float g_bufD[SZ2];
__device__ float g_bufF[SZ2];
__device__ float g_Mc[CC*T1*T1];
__device__ float g_Mt[CC*T1*T1];
__device__ float g_D1[CC*T1*T2];
__device__ float g_C2[CC*T2*T2];
__device__ float g_cos1[L1*T1];
__device__ float g_sin1[L1*T1];
__device__ float g_cos2[L2*T2];
__device__ float g_sin2[L2*T2];
__device__ float g_K1[CC*T1];
__device__ float g_K2[CC*T2];
__device__ float g_featP[BB*CC*8*T1];
__device__ float g_gate[BB*T1];
// pre-split bf16 weights
__device__ bf16 g_Bin[2*2*4*96*T1];
__device__ bf16 g_Bout[2*1*4*96*T2];
__device__ bf16 g_McB[CC*2*192*384];
__device__ bf16 g_D1B[CC*2*96*T1];
__device__ bf16 g_C2B[CC*2*96*T2];

// ---------------- f32x2 helpers ----------------
__device__ __forceinline__ ull pk2(float lo, float hi) {
    ull r; asm("mov.b64 %0, {%1,%2};" : "=l"(r) : "f"(lo), "f"(hi)); return r;
}
__device__ __forceinline__ void fma2(ull& d, ull a, ull b) {
    asm("fma.rn.f32x2 %0, %1, %2, %0;" : "+l"(d) : "l"(a), "l"(b));
}
__device__ __forceinline__ float2 upk2(ull v) {
    float2 f; asm("mov.b64 {%0,%1}, %2;" : "=f"(f.x), "=f"(f.y) : "l"(v)); return f;
}

__device__ __forceinline__ float gelu_t(float x) {
    float x3 = x*x*x;
    return 0.5f*x*(1.0f + tanhf(0.7978845608028654f*(x + 0.044715f*x3)));
}

__device__ __forceinline__ uint32_t smem_u32(const void* p) {
    uint32_t a;
    asm("{ .reg .u64 t; cvta.to.shared.u64 t, %1; cvt.u32.u64 %0, t; }" : "=r"(a) : "l"(p));
    return a;
}

// ---------------- mma.sync helpers ----------------
#define LDM4(r, addr) \
    asm volatile("ldmatrix.sync.aligned.m8n8.x4.shared.b16 {%0,%1,%2,%3}, [%4];" \
        : "=r"((r)[0]), "=r"((r)[1]), "=r"((r)[2]), "=r"((r)[3]) : "r"(addr))

#define MMA_BF16(c, a, b0, b1) \
    asm volatile("mma.sync.aligned.m16n8k16.row.col.f32.bf16.bf16.f32 " \
        "{%0,%1,%2,%3},{%4,%5,%6,%7},{%8,%9},{%0,%1,%2,%3};" \
        : "+f"((c)[0]), "+f"((c)[1]), "+f"((c)[2]), "+f"((c)[3]) \
        : "r"((a)[0]), "r"((a)[1]), "r"((a)[2]), "r"((a)[3]), "r"(b0), "r"(b1))

__device__ __forceinline__ void cvt_hilo_store(float4 v0, float4 v1, bf16* dH, bf16* dL) {
    __nv_bfloat162 h0 = __floats2bfloat162_rn(v0.x, v0.y);
    __nv_bfloat162 h1 = __floats2bfloat162_rn(v0.z, v0.w);
    __nv_bfloat162 h2 = __floats2bfloat162_rn(v1.x, v1.y);
    __nv_bfloat162 h3 = __floats2bfloat162_rn(v1.z, v1.w);
    __nv_bfloat162 l0 = __floats2bfloat162_rn(v0.x - __bfloat162float(h0.x), v0.y - __bfloat162float(h0.y));
    __nv_bfloat162 l1 = __floats2bfloat162_rn(v0.z - __bfloat162float(h1.x), v0.w - __bfloat162float(h1.y));
    __nv_bfloat162 l2 = __floats2bfloat162_rn(v1.x - __bfloat162float(h2.x), v1.y - __bfloat162float(h2.y));
    __nv_bfloat162 l3 = __floats2bfloat162_rn(v1.z - __bfloat162float(h3.x), v1.w - __bfloat162float(h3.y));
    *(uint4*)dH = make_uint4(*(uint32_t*)&h0, *(uint32_t*)&h1, *(uint32_t*)&h2, *(uint32_t*)&h3);
    *(uint4*)dL = make_uint4(*(uint32_t*)&l0, *(uint32_t*)&l1, *(uint32_t*)&l2, *(uint32_t*)&l3);
}

// ---------------- precompute ----------------
__global__ void k_tables() {
    int i = blockIdx.x*blockDim.x + threadIdx.x;
    if (i < L1*T1) {
        int h = i / T1, t = i % T1;
        int m = (h*t) % T1;
        float a = (float)m * (1.0f/96.0f);
        g_cos1[i] = cospif(a);
        g_sin1[i] = sinpif(a);
    }
    int j = i - L1*T1;
    if (j >= 0 && j < L2*T2) {
        int h = j / T2, t = j % T2;
        int m = (h*t) % T2;
        float a = (float)m * (1.0f/48.0f);
        g_cos2[j] = cospif(a);
        g_sin2[j] = sinpif(a);
    }
}

__global__ void k_buildM(const float* __restrict__ Lc, const float* __restrict__ Lt) {
    int t = blockIdx.x, l = blockIdx.y, tp = threadIdx.x;
    float ac = 0.f, as = 0.f;
    for (int h = 0; h < L1; h++) {
        float w = (h == 0 || h == L1-1) ? (1.0f/T1) : (2.0f/T1);
        float lc = Lc[l*L1+h]*w, lt = Lt[l*L1+h]*w;
        ac = fmaf(lc * g_cos1[h*T1+t], g_cos1[h*T1+tp], ac);
        as = fmaf(lt * g_sin1[h*T1+t], g_sin1[h*T1+tp], as);
    }
    size_t o = ((size_t)l*T1 + t)*T1 + tp;
    g_Mc[o] = ac;
    g_Mt[o] = as;
}

__global__ void k_buildK1(const float* __restrict__ Wr, const float* __restrict__ Wi) {
    int i = blockIdx.x*blockDim.x + threadIdx.x;
    if (i >= CC*T1) return;
    int c = i / T1, d = i % T1;
    float acc = 0.f;
    for (int h = 0; h < L1; h++) {
        float w = (h == 0 || h == L1-1) ? (1.0f/T1) : (2.0f/T1);
        acc += w * (Wr[c*L1+h]*g_cos1[h*T1+d] - Wi[c*L1+h]*g_sin1[h*T1+d]);
    }
    g_K1[i] = acc;
}

__global__ void k_buildD1(const float* __restrict__ Wfc) {
    __shared__ float kr[T1];
    int t = blockIdx.x, c = blockIdx.y, s2 = threadIdx.x;
    for (int s = s2; s < T1; s += T2) kr[s] = g_K1[c*T1 + s];
    __syncthreads();
    float acc = 0.f;
    int ii = (T1 - t) % T1;
    for (int s = 0; s < T1; s++) {
        acc = fmaf(kr[ii], Wfc[s*T2 + s2], acc);
        ii++; if (ii == T1) ii = 0;
    }
    g_D1[((size_t)c*T1 + t)*T2 + s2] = acc;
}

__global__ void k_buildK2(const float* __restrict__ Wr, const float* __restrict__ Wi) {
    int i = blockIdx.x*blockDim.x + threadIdx.x;
    if (i >= CC*T2) return;
    int c = i / T2, d = i % T2;
    float acc = 0.f;
    for (int h = 0; h < L2; h++) {
        float w = (h == 0 || h == L2-1) ? (1.0f/T2) : (2.0f/T2);
        acc += w * (Wr[c*L2+h]*g_cos2[h*T2+d] - Wi[c*L2+h]*g_sin2[h*T2+d]);
    }
    g_K2[i] = acc;
}
__global__ void k_expand2() {
    size_t i = (size_t)blockIdx.x*blockDim.x + threadIdx.x;
    if (i >= (size_t)CC*T2*T2) return;
    int s = (int)(i % T2);
    int t = (int)((i / T2) % T2);
    int c = (int)(i / ((size_t)T2*T2));
    g_C2[i] = g_K2[c*T2 + ((s - t + T2) % T2)];
}

template<int KTOT, int HALVES>
__global__ void k_splitW(const float* __restrict__ W1, const float* __restrict__ W2,
                         bf16* __restrict__ dst) {
    int total = 2*HALVES*4*96*KTOT;
    int idx = blockIdx.x*blockDim.x + threadIdx.x;
    if (idx >= total) return;
    int k     = idx % KTOT;
    int n     = (idx / KTOT) % 96;
    int mat   = (idx / (KTOT*96)) % 4;
    int half  = (idx / (KTOT*96*4)) % HALVES;
    int layer = idx / (KTOT*96*4*HALVES);
    const float* src = (mat < 2) ? W1 : W2;
    int s = half*96 + n;
    float w = src[(size_t)layer*KTOT*KTOT + (size_t)k*KTOT + s];
    bf16 hi = __float2bfloat16(w);
    bf16 v = (mat & 1) ? __float2bfloat16(w - __bfloat162float(hi)) : hi;
    dst[idx] = v;
}

__global__ void k_splitMM() {
    size_t total = (size_t)CC*2*192*384;
    size_t idx = (size_t)blockIdx.x*blockDim.x + threadIdx.x;
    if (idx >= total) return;
    int k     = (int)(idx % 384);
    int n     = (int)((idx / 384) % 192);
    int plane = (int)((idx / (384*192)) % 2);
    int c     = (int)(idx / (384*192*2));
    float w = (k < 192) ? g_Mc[((size_t)c*T1 + k)*T1 + n]
                        : g_Mt[((size_t)c*T1 + (k-192))*T1 + n];
    bf16 hi = __float2bfloat16(w);
    g_McB[idx] = plane ? __float2bfloat16(w - __bfloat162float(hi)) : hi;
}

__global__ void k_splitD1() {
    int total = CC*2*96*T1;
    int idx = blockIdx.x*blockDim.x + threadIdx.x;
    if (idx >= total) return;
    int k     = idx % T1;
    int n     = (idx / T1) % 96;
    int plane = (idx / (T1*96)) % 2;
    int c     = idx / (T1*96*2);
    float w = g_D1[((size_t)c*T1 + k)*T2 + n];
    bf16 hi = __float2bfloat16(w);
    g_D1B[idx] = plane ? __float2bfloat16(w - __bfloat162float(hi)) : hi;
}

__global__ void k_splitC2() {
    int total = CC*2*96*T2;
    int idx = blockIdx.x*blockDim.x + threadIdx.x;
    if (idx >= total) return;
    int k     = idx % T2;
    int n     = (idx / T2) % 96;
    int plane = (idx / (T2*96)) % 2;
    int c     = idx / (T2*96*2);
    float w = g_C2[((size_t)c*T2 + k)*T2 + n];
    bf16 hi = __float2bfloat16(w);
    g_C2B[idx] = plane ? __float2bfloat16(w - __bfloat162float(hi)) : hi;
}

// ---------------- channel mix ----------------
__global__ void __launch_bounds__(256) k_chmix(const float* __restrict__ x,
                                               const float* __restrict__ Gc,
                                               const float* __restrict__ Gt) {
    __shared__ __align__(16) float2 sG[CC*CC];
    int tid = threadIdx.x;
    for (int i = tid; i < CC*CC; i += 256) sG[i] = make_float2(Gc[i], Gt[i]);
    __syncthreads();
    int b = blockIdx.y;
    size_t m = (size_t)blockIdx.x*256 + tid;
    ull a[CC];
#pragma unroll
    for (int l = 0; l < CC; l++) a[l] = 0ull;
    for (int c = 0; c < CC; c++) {
        float xv = x[((size_t)(b*CC + c)*NN)*T1 + m];
        ull xp = pk2(xv, xv);
#pragma unroll
        for (int l = 0; l < CC; l++) fma2(a[l], xp, *(const ull*)&sG[c*CC + l]);
    }
#pragma unroll
    for (int l = 0; l < CC; l++) {
        float2 p = upk2(a[l]);
        g_bufA[((size_t)(b*CC + l)*NN)*T1 + m] = p.x;
        g_bufB[((size_t)(b*CC + l)*NN)*T1 + m] = p.y;
    }
}

// ---------------- mm2 (tensor, merged N=192): Y = resid + [u|v] @ [Mc;Mt][c] ----------------
__global__ void __launch_bounds__(256) k_mm2MMA(const float* __restrict__ U,
                                                const float* __restrict__ V,
                                                const float* __restrict__ resid,
                                                float* __restrict__ Y) {
    constexpr int AST = 40;
    __shared__ __align__(16) bf16 sAh[64*AST];
    __shared__ __align__(16) bf16 sAl[64*AST];
    __shared__ __align__(16) bf16 sB[2*192*AST];
    int tid = threadIdx.x, lane = tid & 31, wid = tid >> 5;
    int wm = wid & 3, wn = wid >> 2;
    int c = blockIdx.y, b = blockIdx.z;
    size_t row0 = (size_t)(b*CC + c)*NN + (size_t)blockIdx.x*64;
    const bf16* Wc = g_McB + (size_t)c*2*192*384;

    float cc[12][4];
#pragma unroll
    for (int i = 0; i < 12; i++)
#pragma unroll
        for (int j = 0; j < 4; j++) cc[i][j] = 0.f;

    uint32_t aOff = (uint32_t)((wm*16 + (lane & 15))*AST + ((lane >> 4) << 3)) * 2;
    uint32_t aAddrH = smem_u32(sAh) + aOff;
    uint32_t aAddrL = smem_u32(sAl) + aOff;
    uint32_t bRow = (uint32_t)((lane & 7) + ((lane >> 4) << 3));
    uint32_t bOff = (bRow*AST + (((lane >> 3) & 1) << 3)) * 2;
    uint32_t sBbase = smem_u32(sB);

    int arow = tid >> 2, akg = (tid & 3) * 8;
    bf16* aDstH = &sAh[arow*AST + akg];
    bf16* aDstL = &sAl[arow*AST + akg];
    int bpl = tid / 768, brem = tid % 768;
    int bn = brem >> 2, bkg = (brem & 3) * 8;

    float4 nx0, nx1;
    uint4 nB[6];
    {
        const float* xr = U + (row0 + arow)*T1 + akg;
        nx0 = *(const float4*)xr; nx1 = *(const float4*)(xr + 4);
#pragma unroll
        for (int it = 0; it < 6; it++) {
            int pl = bpl + (it & 1), nn2 = bn + (it >> 1)*64;   // tid covers plane0 n0-63 / plane pattern
            // simpler exact mapping: linear index
            int i = tid + it*256;
            int plane = i / 768, rem = i % 768;
            int n = rem >> 2, kg = (rem & 3) * 8;
            nB[it] = *(const uint4*)&Wc[((size_t)plane*192 + n)*384 + kg];
            (void)pl; (void)nn2;
        }
    }
    for (int kc = 0; kc < 12; kc++) {
        cvt_hilo_store(nx0, nx1, aDstH, aDstL);
#pragma unroll
        for (int it = 0; it < 6; it++) {
            int i = tid + it*256;
            int plane = i / 768, rem = i % 768;
            int n = rem >> 2, kg = (rem & 3) * 8;
            *(uint4*)&sB[(plane*192 + n)*AST + kg] = nB[it];
        }
        __syncthreads();
        if (kc + 1 < 12) {
            int kn = kc + 1;
            const float* Xs = (kn < 6) ? U : V;
            int kl = (kn < 6) ? kn : kn - 6;
            const float* xr = Xs + (row0 + arow)*T1 + kl*32 + akg;
            nx0 = *(const float4*)xr; nx1 = *(const float4*)(xr + 4);
#pragma unroll
            for (int it = 0; it < 6; it++) {
                int i = tid + it*256;
                int plane = i / 768, rem = i % 768;
                int n = rem >> 2, kg = (rem & 3) * 8;
                nB[it] = *(const uint4*)&Wc[((size_t)plane*192 + n)*384 + kn*32 + kg];
            }
        }
#pragma unroll
        for (int k16 = 0; k16 < 2; k16++) {
            uint32_t kof = (uint32_t)(k16 * 32);
            uint32_t ah[4], al[4];
            LDM4(ah, aAddrH + kof);
            LDM4(al, aAddrL + kof);
            uint32_t baseH = sBbase + bOff + kof;
            uint32_t baseL = baseH + (uint32_t)(192*AST)*2;
#pragma unroll
            for (int pr = 0; pr < 6; pr++) {
                uint32_t po = (uint32_t)((wn*96 + pr*16)*AST)*2;
                uint32_t bh[4], bl[4];
                LDM4(bh, baseH + po);
                LDM4(bl, baseL + po);
                MMA_BF16(cc[2*pr],   ah, bh[0], bh[1]);
                MMA_BF16(cc[2*pr+1], ah, bh[2], bh[3]);
                MMA_BF16(cc[2*pr],   al, bh[0], bh[1]);
                MMA_BF16(cc[2*pr+1], al, bh[2], bh[3]);
                MMA_BF16(cc[2*pr],   ah, bl[0], bl[1]);
                MMA_BF16(cc[2*pr+1], ah, bl[2], bl[3]);
            }
        }
        __syncthreads();
    }

    int g = lane >> 2, tg = lane & 3;
    size_t mrow = row0 + (size_t)wm*16 + g;
    int colb = wn*96 + tg*2;
#pragma unroll
    for (int nf = 0; nf < 12; nf++) {
        int col = colb + nf*8;
        float2 r0 = *(const float2*)&resid[mrow*T1 + col];
        float2 r1 = *(const float2*)&resid[(mrow + 8)*T1 + col];
        *(float2*)&Y[mrow*T1 + col]       = make_float2(cc[nf][0] + r0.x, cc[nf][1] + r0.y);
        *(float2*)&Y[(mrow + 8)*T1 + col] = make_float2(cc[nf][2] + r1.x, cc[nf][3] + r1.y);
    }
}

// ---------------- channel GEMM (tensor): Y = (X1 + sg*X2) @ W[c] [+bias] ----------------
template<int KTOT, bool BIAS>
__global__ void __launch_bounds__(256) k_cgemmMMA(const float* __restrict__ X1,
                                                  const float* __restrict__ X2,
                                                  const bf16* __restrict__ WB,
                                                  const float* __restrict__ bias,
                                                  const float* __restrict__ gate,
                                                  float* __restrict__ Y) {
    constexpr int AST = 40, KC = KTOT/32;
    __shared__ __align__(16) bf16 sAh[64*AST];
    __shared__ __align__(16) bf16 sAl[64*AST];
    __shared__ __align__(16) bf16 sB[2*96*AST];
    __shared__ float sg[KTOT];
    int tid = threadIdx.x, lane = tid & 31, wid = tid >> 5;
    int wm = wid & 3, wn = wid >> 2;
    int c = blockIdx.y, b = blockIdx.z;
    size_t row0 = (size_t)(b*CC + c)*NN + (size_t)blockIdx.x*64;
    const bf16* Wc = WB + (size_t)c*2*96*KTOT;

    for (int t = tid; t < KTOT; t += 256) sg[t] = 1.0f + gate[b*KTOT + t];
    __syncthreads();

    float cc[6][4];
#pragma unroll
    for (int i = 0; i < 6; i++)
#pragma unroll
        for (int j = 0; j < 4; j++) cc[i][j] = 0.f;

    uint32_t aOff = (uint32_t)((wm*16 + (lane & 15))*AST + ((lane >> 4) << 3)) * 2;
    uint32_t aAddrH = smem_u32(sAh) + aOff;
    uint32_t aAddrL = smem_u32(sAl) + aOff;
    uint32_t bRow = (uint32_t)(wn*48 + (lane & 7) + ((lane >> 4) << 3));
    uint32_t bOff = (bRow*AST + (((lane >> 3) & 1) << 3)) * 2;
    uint32_t sBbase = smem_u32(sB);

    int arow = tid >> 2, akg = (tid & 3) * 8;
    const float* x1r = X1 + (row0 + arow)*KTOT;
    const float* x2r = X2 + (row0 + arow)*KTOT;
    bf16* aDstH = &sAh[arow*AST + akg];
    bf16* aDstL = &sAl[arow*AST + akg];

    float4 na0, na1, nb0, nb1;
    uint4 nB[3];
    {
        na0 = *(const float4*)&x1r[akg];
        na1 = *(const float4*)&x1r[akg + 4];
        nb0 = *(const float4*)&x2r[akg];
        nb1 = *(const float4*)&x2r[akg + 4];
#pragma unroll
        for (int it = 0; it < 3; it++) {
            int i = tid + it*256;
            int plane = i / 384, rem = i % 384;
            int n = rem >> 2, kg = (rem & 3) * 8;
            nB[it] = *(const uint4*)&Wc[((size_t)plane*96 + n)*KTOT + kg];
        }
    }
    for (int kc = 0; kc < KC; kc++) {
        {
            int k0 = kc*32 + akg;
            float4 v0 = na0, v1 = na1;
            v0.x = fmaf(nb0.x, sg[k0],   v0.x);
            v0.y = fmaf(nb0.y, sg[k0+1], v0.y);
            v0.z = fmaf(nb0.z, sg[k0+2], v0.z);
            v0.w = fmaf(nb0.w, sg[k0+3], v0.w);
            v1.x = fmaf(nb1.x, sg[k0+4], v1.x);
            v1.y = fmaf(nb1.y, sg[k0+5], v1.y);
            v1.z = fmaf(nb1.z, sg[k0+6], v1.z);
            v1.w = fmaf(nb1.w, sg[k0+7], v1.w);
            cvt_hilo_store(v0, v1, aDstH, aDstL);
#pragma unroll
            for (int it = 0; it < 3; it++) {
                int i = tid + it*256;
                int plane = i / 384, rem = i % 384;
                int n = rem >> 2, kg = (rem & 3) * 8;
                *(uint4*)&sB[(plane*96 + n)*AST + kg] = nB[it];
            }
        }
        __syncthreads();
        if (kc + 1 < KC) {
            int kn = (kc + 1)*32 + akg;
            na0 = *(const float4*)&x1r[kn];
            na1 = *(const float4*)&x1r[kn + 4];
            nb0 = *(const float4*)&x2r[kn];
            nb1 = *(const float4*)&x2r[kn + 4];
#pragma unroll
            for (int it = 0; it < 3; it++) {
                int i = tid + it*256;
                int plane = i / 384, rem = i % 384;
                int n = rem >> 2, kg = (rem & 3) * 8;
                nB[it] = *(const uint4*)&Wc[((size_t)plane*96 + n)*KTOT + (kc+1)*32 + kg];
            }
        }
#pragma unroll
        for (int k16 = 0; k16 < 2; k16++) {
            uint32_t kof = (uint32_t)(k16 * 32);
            uint32_t ah[4], al[4];
            LDM4(ah, aAddrH + kof);
            LDM4(al, aAddrL + kof);
            uint32_t baseH = sBbase + bOff + kof;
            uint32_t baseL = baseH + (uint32_t)(96*AST)*2;
#pragma unroll
            for (int pr = 0; pr < 3; pr++) {
                uint32_t po = (uint32_t)(pr*16*AST)*2;
                uint32_t bh[4], bl[4];
                LDM4(bh, baseH + po);
                LDM4(bl, baseL + po);
                MMA_BF16(cc[2*pr],   ah, bh[0], bh[1]);
                MMA_BF16(cc[2*pr+1], ah, bh[2], bh[3]);
                MMA_BF16(cc[2*pr],   al, bh[0], bh[1]);
                MMA_BF16(cc[2*pr+1], al, bh[2], bh[3]);
                MMA_BF16(cc[2*pr],   ah, bl[0], bl[1]);
                MMA_BF16(cc[2*pr+1], ah, bl[2], bl[3]);
            }
        }
        __syncthreads();
    }

    int g = lane >> 2, tg = lane & 3;
    size_t mrow = row0 + (size_t)wm*16 + g;
    int colb = wn*48 + tg*2;
#pragma unroll
    for (int nf = 0; nf < 6; nf++) {
        int col = colb + nf*8;
        float2 o0 = make_float2(cc[nf][0], cc[nf][1]);
        float2 o1 = make_float2(cc[nf][2], cc[nf][3]);
        if (BIAS) {
            float2 bv = *(const float2*)&bias[col];
            o0.x += bv.x; o0.y += bv.y; o1.x += bv.x; o1.y += bv.y;
        }
        *(float2*)&Y[mrow*96 + col]       = o0;
        *(float2*)&Y[(mrow + 8)*96 + col] = o1;
    }
}

// ---------------- tensor gmlp + fused n-mean partials ----------------
template<int KTOT, bool G1>
__global__ void __launch_bounds__(256) k_gmlpMMA(const float* __restrict__ X,
                                                 const bf16* __restrict__ Bw,
                                                 const float* __restrict__ gate,
                                                 float* __restrict__ Y) {
    constexpr int KC = KTOT/32;
    constexpr int AST = 40;
    __shared__ __align__(16) bf16 sAh[64*AST];
    __shared__ __align__(16) bf16 sAl[64*AST];
    __shared__ __align__(16) bf16 sB[4*96*AST];
    __shared__ float sg[KTOT];
    __shared__ float sFP[8][48];
    int tid = threadIdx.x, lane = tid & 31, wid = tid >> 5;
    int wm = wid & 3, wn = wid >> 2;
    int half = blockIdx.y;
    size_t row0 = (size_t)blockIdx.x * 64;
    int b = blockIdx.x >> 8;
    int ch = (blockIdx.x >> 3) & 31;
    int tile = blockIdx.x & 7;
    const bf16* BwH = Bw + (size_t)half * 4*96*KTOT;

    if (G1) {
        for (int t = tid; t < KTOT; t += 256) sg[t] = 1.0f + gate[b*KTOT + t];
        __syncthreads();
    }

    float c1[6][4], c2[6][4];
#pragma unroll
    for (int i = 0; i < 6; i++)
#pragma unroll
        for (int j = 0; j < 4; j++) { c1[i][j] = 0.f; c2[i][j] = 0.f; }

    uint32_t aOff = (uint32_t)((wm*16 + (lane & 15))*AST + ((lane >> 4) << 3)) * 2;
    uint32_t aAddrH = smem_u32(sAh) + aOff;
    uint32_t aAddrL = smem_u32(sAl) + aOff;
    uint32_t bRow = (uint32_t)(wn*48 + (lane & 7) + ((lane >> 4) << 3));
    uint32_t bOff = (bRow*AST + (((lane >> 3) & 1) << 3)) * 2;
    uint32_t sBbase = smem_u32(sB);

    int arow = tid >> 2, akg = (tid & 3) * 8;
    const float* xrow = X + (row0 + arow)*KTOT;
    bf16* aDstH = &sAh[arow*AST + akg];
    bf16* aDstL = &sAl[arow*AST + akg];

    float4 nx0, nx1;
    uint4 nB[6];
    {
        nx0 = *(const float4*)&xrow[akg];
        nx1 = *(const float4*)&xrow[akg + 4];
#pragma unroll
        for (int it = 0; it < 6; it++) {
            int i = tid + it*256;
            int mat = i / 384, rem = i % 384;
            int n = rem >> 2, kg = (rem & 3) * 8;
            nB[it] = *(const uint4*)&BwH[((size_t)mat*96 + n)*KTOT + kg];
        }
    }
    for (int kc = 0; kc < KC; kc++) {
        {
            int k0 = kc*32 + akg;
            float4 v0 = nx0, v1 = nx1;
            if (G1) {
                v0.x *= sg[k0];   v0.y *= sg[k0+1]; v0.z *= sg[k0+2]; v0.w *= sg[k0+3];
                v1.x *= sg[k0+4]; v1.y *= sg[k0+5]; v1.z *= sg[k0+6]; v1.w *= sg[k0+7];
            }
            cvt_hilo_store(v0, v1, aDstH, aDstL);
#pragma unroll
            for (int it = 0; it < 6; it++) {
                int i = tid + it*256;
                int mat = i / 384, rem = i % 384;
                int n = rem >> 2, kg = (rem & 3) * 8;
                *(uint4*)&sB[(mat*96 + n)*AST + kg] = nB[it];
            }
        }
        __syncthreads();
        if (kc + 1 < KC) {
            int kn = (kc + 1)*32;
            nx0 = *(const float4*)&xrow[kn + akg];
            nx1 = *(const float4*)&xrow[kn + akg + 4];
#pragma unroll
            for (int it = 0; it < 6; it++) {
                int i = tid + it*256;
                int mat = i / 384, rem = i % 384;
                int n = rem >> 2, kg = (rem & 3) * 8;
                nB[it] = *(const uint4*)&BwH[((size_t)mat*96 + n)*KTOT + kn + kg];
            }
        }
#pragma unroll
        for (int k16 = 0; k16 < 2; k16++) {
            uint32_t kof = (uint32_t)(k16 * 32);
            uint32_t ah[4], al[4];
            LDM4(ah, aAddrH + kof);
            LDM4(al, aAddrL + kof);
#pragma unroll
            for (int mat = 0; mat < 2; mat++) {
                float (*cf)[4] = mat ? c2 : c1;
                uint32_t baseH = sBbase + (uint32_t)((mat*2 + 0)*96*AST)*2 + bOff + kof;
                uint32_t baseL = sBbase + (uint32_t)((mat*2 + 1)*96*AST)*2 + bOff + kof;
#pragma unroll
                for (int pr = 0; pr < 3; pr++) {
                    uint32_t po = (uint32_t)(pr*16*AST)*2;
                    uint32_t bh[4], bl[4];
                    LDM4(bh, baseH + po);
                    LDM4(bl, baseL + po);
                    MMA_BF16(cf[2*pr],   ah, bh[0], bh[1]);
                    MMA_BF16(cf[2*pr+1], ah, bh[2], bh[3]);
                    MMA_BF16(cf[2*pr],   al, bh[0], bh[1]);
                    MMA_BF16(cf[2*pr+1], al, bh[2], bh[3]);
                    MMA_BF16(cf[2*pr],   ah, bl[0], bl[1]);
                    MMA_BF16(cf[2*pr+1], ah, bl[2], bl[3]);
                }
            }
        }
        __syncthreads();
    }

    // epilogue: o = (X@W1)*gelu(X@W2), store + column partial sums
    int g = lane >> 2, tg = lane & 3;
    size_t mrow = row0 + (size_t)wm*16 + g;
    int colb = half*96 + wn*48 + tg*2;
    float colsum[12];
#pragma unroll
    for (int nf = 0; nf < 6; nf++) {
        int col = colb + nf*8;
        float2 o0 = make_float2(c1[nf][0]*gelu_t(c2[nf][0]), c1[nf][1]*gelu_t(c2[nf][1]));
        float2 o1 = make_float2(c1[nf][2]*gelu_t(c2[nf][2]), c1[nf][3]*gelu_t(c2[nf][3]));
        *(float2*)&Y[mrow*KTOT + col] = o0;
        *(float2*)&Y[(mrow + 8)*KTOT + col] = o1;
        colsum[2*nf]   = o0.x + o1.x;
        colsum[2*nf+1] = o0.y + o1.y;
    }
    // reduce over g (8 row-groups per warp)
#pragma unroll
    for (int i = 0; i < 12; i++) {
        float v = colsum[i];
        v += __shfl_xor_sync(0xFFFFFFFF, v, 16);
        v += __shfl_xor_sync(0xFFFFFFFF, v, 8);
        v += __shfl_xor_sync(0xFFFFFFFF, v, 4);
        colsum[i] = v;
    }
    if (lane < 4) {
#pragma unroll
        for (int nf = 0; nf < 6; nf++) {
            sFP[wid][lane*2 + nf*8]     = colsum[2*nf];
            sFP[wid][lane*2 + nf*8 + 1] = colsum[2*nf+1];
        }
    }
    __syncthreads();
    if (tid < 96) {
        int wn2 = tid / 48, idx = tid % 48;
        float tot = sFP[wn2*4+0][idx] + sFP[wn2*4+1][idx] + sFP[wn2*4+2][idx] + sFP[wn2*4+3][idx];
        g_featP[((size_t)(b*CC + ch)*8 + tile)*KTOT + half*96 + wn2*48 + idx] = tot;
    }
}

// ---------------- attn gate (reads featP partials) ----------------
template<int T>
__global__ void __launch_bounds__(T) k_gate(const float* __restrict__ Wq,
                                            const float* __restrict__ Wk) {
    __shared__ float ks[T][EE];
    int b = blockIdx.x, t = threadIdx.x;
    float q[EE], kk[EE];
#pragma unroll
    for (int e = 0; e < EE; e++) { q[e] = 0.f; kk[e] = 0.f; }
    for (int c = 0; c < CC; c++) {
        float f = 0.f;
#pragma unroll
        for (int p = 0; p < 8; p++) f += g_featP[((size_t)(b*CC + c)*8 + p)*T + t];
        f *= (1.0f/NN);
#pragma unroll
        for (int e = 0; e < EE; e++) {
            q[e]  = fmaf(f, Wq[c*EE + e], q[e]);
            kk[e] = fmaf(f, Wk[c*EE + e], kk[e]);
        }
    }
#pragma unroll
    for (int e = 0; e < EE; e++) ks[t][e] = kk[e];
    __syncthreads();
    float smax = -1e30f, stt = 0.f;
    for (int j = 0; j < T; j++) {
        float d = 0.f;
#pragma unroll
        for (int e = 0; e < EE; e++) d = fmaf(q[e], ks[j][e], d);
        d *= 0.125f;
        if (j == t) stt = d;
        smax = fmaxf(smax, d);
    }
    float ssum = 0.f;
    for (int j = 0; j < T; j++) {
        float d = 0.f;
#pragma unroll
        for (int e = 0; e < EE; e++) d = fmaf(q[e], ks[j][e], d);
        ssum += expf(d*0.125f - smax);
    }
    float p = expf(stt - smax) / ssum;
    g_gate[b*T + t] = gelu_t(p);
}

// ---------------- driver ----------------
extern "C" void kernel_launch(void* const* d_in, const int* in_sizes, int n_in,
                              void* d_out, int out_size) {
    const float* x   = (const float*)d_in[0];
    const float* Gc  = (const float*)d_in[3];
    const float* Lc  = (const float*)d_in[4];
    const float* Gt  = (const float*)d_in[5];
    const float* Lt  = (const float*)d_in[6];
    const float* f1r = (const float*)d_in[7];
    const float* f1i = (const float*)d_in[8];
    const float* f2r = (const float*)d_in[9];
    const float* f2i = (const float*)d_in[10];
    const float* Wfc = (const float*)d_in[11];
    const float* bfc = (const float*)d_in[12];
    const float* mi1 = (const float*)d_in[13];
    const float* mi2 = (const float*)d_in[14];
    const float* mo1 = (const float*)d_in[15];
    const float* mo2 = (const float*)d_in[16];
    const float* aiq = (const float*)d_in[17];
    const float* aik = (const float*)d_in[18];
    const float* aoq = (const float*)d_in[19];
    const float* aok = (const float*)d_in[20];
    float* out = (float*)d_out;

    float *bufA, *bufB, *bufC, *bufD, *bufF, *gate;
    bf16 *Bin, *Bout, *D1B, *C2B;
    cudaGetSymbolAddress((void**)&bufA, g_bufA);
    cudaGetSymbolAddress((void**)&bufB, g_bufB);
    cudaGetSymbolAddress((void**)&bufC, g_bufC);
    cudaGetSymbolAddress((void**)&bufD, g_bufD);
    cudaGetSymbolAddress((void**)&bufF, g_bufF);
    cudaGetSymbolAddress((void**)&gate, g_gate);
    cudaGetSymbolAddress((void**)&Bin,  g_Bin);
    cudaGetSymbolAddress((void**)&Bout, g_Bout);
    cudaGetSymbolAddress((void**)&D1B,  g_D1B);
    cudaGetSymbolAddress((void**)&C2B,  g_C2B);

    // precompute operator matrices + weight splits
    k_tables<<<(L1*T1 + L2*T2 + 255)/256, 256>>>();
    k_buildM<<<dim3(T1, CC), T1>>>(Lc, Lt);
    k_buildK1<<<(CC*T1 + 255)/256, 256>>>(f1r, f1i);
    k_buildD1<<<dim3(T1, CC), T2>>>(Wfc);
    k_buildK2<<<(CC*T2 + 255)/256, 256>>>(f2r, f2i);
    k_expand2<<<(int)(((size_t)CC*T2*T2 + 255)/256), 256>>>();
    k_splitW<T1,2><<<(2*2*4*96*T1 + 255)/256, 256>>>(mi1, mi2, Bin);
    k_splitW<T2,1><<<(2*1*4*96*T2 + 255)/256, 256>>>(mo1, mo2, Bout);
    k_splitMM<<<(int)(((size_t)CC*2*192*384 + 255)/256), 256>>>();
    k_splitD1<<<(CC*2*96*T1 + 255)/256, 256>>>();
    k_splitC2<<<(CC*2*96*T2 + 255)/256, 256>>>();

    // freq_attn_in: u = Gc^T x, v = Gt^T x ; xc = x + u@Mc[c] + v@Mt[c]
    k_chmix<<<dim3(NN*T1/256, BB), 256>>>(x, Gc, Gt);
    k_mm2MMA<<<dim3(NN/64, CC, BB), 256>>>(bufA, bufB, x, bufC);

    const int NT = BB*CC*NN/64;               // 4096 M-tiles of 64 rows
    const size_t L1OFF = (size_t)2*4*96*T1;
    const size_t L2OFF = (size_t)1*4*96*T2;

    // input-side layers (tensor core, n-mean fused)
    k_gmlpMMA<T1,false><<<dim3(NT, 2), 256>>>(bufC, Bin, nullptr, bufA);
    k_gate<T1><<<BB, T1>>>(aiq, aik);
    k_gmlpMMA<T1,true ><<<dim3(NT, 2), 256>>>(bufA, Bin + L1OFF, gate, bufC);
    k_gate<T1><<<BB, T1>>>(aiq + CC*EE, aik + CC*EE);

    // h_y = (x + xc*(1+g)) @ D1[c] + bfc   (fconv1 + fc_idp fused, tensor)
    k_cgemmMMA<T1, true><<<dim3(NN/64, CC, BB), 256>>>(x, bufC, D1B, bfc, gate, bufD);

    // output-side layers (tensor core, n-mean fused)
    k_gmlpMMA<T2,false><<<dim3(NT, 1), 256>>>(bufD, Bout, nullptr, bufA);
    k_gate<T2><<<BB, T2>>>(aoq, aok);
    k_gmlpMMA<T2,true ><<<dim3(NT, 1), 256>>>(bufA, Bout + L2OFF, gate, bufF);
    k_gate<T2><<<BB, T2>>>(aoq + CC*EE, aok + CC*EE);

    // out = (h_y + y_c*(1+g)) @ C2[c]   (tensor)
    k_cgemmMMA<T2, false><<<dim3(NN/64, CC, BB), 256>>>(bufD, bufF, C2B, nullptr, gate, out);
}